// round 6
// baseline (speedup 1.0000x reference)
#include <cuda_runtime.h>
#include <cuda_bf16.h>
#include <math.h>
#include <stdint.h>

#define B_  2
#define T_  2048
#define C_  1024
#define H_  16
#define HD  64
#define BT  (B_*T_)      // 4096
#define C5  (5*C_)       // 5120
#define NC  (T_/HD)      // 32 chunks
#define BH  (B_*H_)      // 32

// ---------------- scratch (device globals) ----------------
__device__ float g_qkvff[BT*(size_t)C5];          // q,k,v fp32 (cols < 3C used)
__device__ float g_W [BH*(size_t)NC*HD*HD];
__device__ float g_S [BH*(size_t)NC*HD*HD];
__device__ float g_y [BT*(size_t)C_];             // GN'd attention out
__device__ float g_yp[BT*(size_t)C_];             // proj out
// split-bf16 operands, layout [hi | lo] along K' = 2K
__device__ __nv_bfloat16 g_a_qkv [BT*(size_t)2*C_];
__device__ __nv_bfloat16 g_b_qkv [C5*(size_t)2*C_];
__device__ __nv_bfloat16 g_a_x   [BT*(size_t)2*C_];
__device__ __nv_bfloat16 g_b_gat [C_*(size_t)2*C_];
__device__ __nv_bfloat16 g_a_prj [BT*(size_t)2*C_];
__device__ __nv_bfloat16 g_b_prj [C_*(size_t)2*C_];
__device__ __nv_bfloat16 g_a_ff  [BT*(size_t)4*C_];   // gelu(ff) split, K=2048
__device__ __nv_bfloat16 g_b_ff  [C_*(size_t)4*C_];

// ---------------- PTX helpers ----------------
__device__ __forceinline__ uint32_t smem_u32(const void* p) {
    uint32_t a;
    asm("{ .reg .u64 t; cvta.to.shared.u64 t, %1; cvt.u32.u64 %0, t; }" : "=r"(a) : "l"(p));
    return a;
}
#define CPA(dst, src)  asm volatile("cp.async.cg.shared.global [%0], [%1], 16;" :: "r"(dst), "l"(src) : "memory")
#define CPC()          asm volatile("cp.async.commit_group;" ::: "memory")
#define CPW(n)         asm volatile("cp.async.wait_group %0;" :: "n"(n) : "memory")
#define SWZ64(o) ((o) ^ (((o) >> 3) & 0x30))

#define LDM_X4(r0, r1, r2, r3, a) \
    asm volatile("ldmatrix.sync.aligned.m8n8.x4.shared.b16 {%0,%1,%2,%3}, [%4];" \
        : "=r"(r0), "=r"(r1), "=r"(r2), "=r"(r3) : "r"(a))

#define MMA_BF16(d, a0, a1, a2, a3, b0, b1) \
    asm volatile("mma.sync.aligned.m16n8k16.row.col.f32.bf16.bf16.f32 " \
        "{%0,%1,%2,%3}, {%4,%5,%6,%7}, {%8,%9}, {%0,%1,%2,%3};" \
        : "+f"((d)[0]), "+f"((d)[1]), "+f"((d)[2]), "+f"((d)[3]) \
        : "r"(a0), "r"(a1), "r"(a2), "r"(a3), "r"(b0), "r"(b1))

// ---------------- warp-MMA split-bf16 NT GEMM, fragment-reuse 3-term scheme ----------------
// acc = Ah.Bh + Al.Bh + Ah.Bl   (A, B stored [hi|lo], row stride 2K)
// block tile 128x256, BK=32, S=3 cp.async stages, 8 warps (2m x 4n), warp 64x64
// MMA issue is term-major across mt so one accumulator's reuse distance is 8.
template<int EPI>
__global__ void __launch_bounds__(256, 1) mma_gemm(
    const __nv_bfloat16* __restrict__ A, const __nv_bfloat16* __restrict__ Bm,
    int K, int N, float* __restrict__ Cout,
    const float* __restrict__ bias, const float* __restrict__ aux0,
    const float* __restrict__ aux1, __nv_bfloat16* __restrict__ osplit)
{
    extern __shared__ __align__(1024) char smem_raw[];
    const int S = 3;
    const uint32_t STAGE = 49152;   // A_hi 8K | A_lo 8K | B_hi 16K | B_lo 16K
    uint32_t sbase = (smem_u32(smem_raw) + 1023) & ~1023u;

    int tid = threadIdx.x;
    int wid = tid >> 5, lane = tid & 31;
    int warp_m = wid & 1, warp_n = wid >> 1;
    int bm = blockIdx.y << 7, bn = blockIdx.x << 8;
    int K2 = 2 * K;
    const int nk = K >> 5;

    auto load_stage = [&](int s, int k) {
        uint32_t st = sbase + (uint32_t)s * STAGE;
        const __nv_bfloat16* Ag = A + (size_t)bm * K2 + (size_t)k * 32;
        const __nv_bfloat16* Bg = Bm + (size_t)bn * K2 + (size_t)k * 32;
        #pragma unroll
        for (int q = 0; q < 2; q++) {
            int i = tid + (q << 8);
            int r = i >> 2, c = i & 3;
            uint32_t off = SWZ64(r * 64 + c * 16);
            const __nv_bfloat16* src = Ag + (size_t)r * K2 + c * 8;
            CPA(st + off,        (const char*)src);
            CPA(st + 8192 + off, (const char*)(src + K));
        }
        #pragma unroll
        for (int q = 0; q < 4; q++) {
            int i = tid + (q << 8);
            int r = i >> 2, c = i & 3;
            uint32_t off = SWZ64(r * 64 + c * 16);
            const __nv_bfloat16* src = Bg + (size_t)r * K2 + c * 8;
            CPA(st + 16384 + off, (const char*)src);
            CPA(st + 32768 + off, (const char*)(src + K));
        }
    };

    float acc[4][8][4];
    #pragma unroll
    for (int mt = 0; mt < 4; mt++)
        #pragma unroll
        for (int nt = 0; nt < 8; nt++)
            #pragma unroll
            for (int u = 0; u < 4; u++) acc[mt][nt][u] = 0.f;

    int j = lane >> 3;
    int lrow = lane & 7;
    int a_row_off = ((j & 1) << 3) + lrow;
    int a_byte_off = (j >> 1) << 4;
    int b_row_off = ((j >> 1) << 3) + lrow;
    int b_byte_off = (j & 1) << 4;

    #pragma unroll
    for (int p = 0; p < S - 1; p++) { load_stage(p, p); CPC(); }

    for (int k = 0; k < nk; k++) {
        CPW(S - 2);
        __syncthreads();
        if (k + S - 1 < nk) load_stage((k + S - 1) % S, k + S - 1);
        CPC();

        uint32_t st = sbase + (uint32_t)(k % S) * STAGE;
        #pragma unroll
        for (int ks = 0; ks < 2; ks++) {
            uint32_t ah[4][4], al[4][4];
            #pragma unroll
            for (int mt = 0; mt < 4; mt++) {
                int row = warp_m * 64 + mt * 16 + a_row_off;
                uint32_t off = SWZ64(row * 64 + ks * 32 + a_byte_off);
                LDM_X4(ah[mt][0], ah[mt][1], ah[mt][2], ah[mt][3], st + off);
                LDM_X4(al[mt][0], al[mt][1], al[mt][2], al[mt][3], st + 8192 + off);
            }
            #pragma unroll
            for (int ng = 0; ng < 4; ng++) {
                int row = warp_n * 64 + ng * 16 + b_row_off;
                uint32_t off = SWZ64(row * 64 + ks * 32 + b_byte_off);
                uint32_t bh[4], bl[4];
                LDM_X4(bh[0], bh[1], bh[2], bh[3], st + 16384 + off);
                LDM_X4(bl[0], bl[1], bl[2], bl[3], st + 32768 + off);
                int nt0 = 2 * ng;
                // term hh: all 8 accumulators once (reuse distance 8)
                #pragma unroll
                for (int mt = 0; mt < 4; mt++) {
                    MMA_BF16(acc[mt][nt0],     ah[mt][0], ah[mt][1], ah[mt][2], ah[mt][3], bh[0], bh[1]);
                    MMA_BF16(acc[mt][nt0 + 1], ah[mt][0], ah[mt][1], ah[mt][2], ah[mt][3], bh[2], bh[3]);
                }
                // term lh
                #pragma unroll
                for (int mt = 0; mt < 4; mt++) {
                    MMA_BF16(acc[mt][nt0],     al[mt][0], al[mt][1], al[mt][2], al[mt][3], bh[0], bh[1]);
                    MMA_BF16(acc[mt][nt0 + 1], al[mt][0], al[mt][1], al[mt][2], al[mt][3], bh[2], bh[3]);
                }
                // term hl
                #pragma unroll
                for (int mt = 0; mt < 4; mt++) {
                    MMA_BF16(acc[mt][nt0],     ah[mt][0], ah[mt][1], ah[mt][2], ah[mt][3], bl[0], bl[1]);
                    MMA_BF16(acc[mt][nt0 + 1], ah[mt][0], ah[mt][1], ah[mt][2], ah[mt][3], bl[2], bl[3]);
                }
            }
        }
    }

    // ---------------- epilogue ----------------
    int gid = lane >> 2;
    int tig = lane & 3;
    #pragma unroll
    for (int mt = 0; mt < 4; mt++) {
        int m0 = bm + warp_m * 64 + mt * 16 + gid;
        #pragma unroll
        for (int nt = 0; nt < 8; nt++) {
            int n0 = bn + warp_n * 64 + nt * 8 + tig * 2;
            float* ac = acc[mt][nt];
            #pragma unroll
            for (int half = 0; half < 2; half++) {
                int m = m0 + half * 8;
                float v0 = ac[half * 2], v1 = ac[half * 2 + 1];
                if (EPI == 0) {
                    if (n0 < 3 * C_) {
                        float2 w; w.x = v0; w.y = v1;
                        *(float2*)&Cout[(size_t)m * N + n0] = w;
                    } else {
                        int e = n0 - 3 * C_;
                        float g0 = 0.5f * v0 * (1.0f + erff(v0 * 0.70710678118654752f));
                        float g1 = 0.5f * v1 * (1.0f + erff(v1 * 0.70710678118654752f));
                        __nv_bfloat16 h0 = __float2bfloat16(g0);
                        __nv_bfloat16 h1 = __float2bfloat16(g1);
                        __nv_bfloat16 l0 = __float2bfloat16(g0 - __bfloat162float(h0));
                        __nv_bfloat16 l1 = __float2bfloat16(g1 - __bfloat162float(h1));
                        size_t ob = (size_t)m * 4096 + e;
                        *(__nv_bfloat162*)(osplit + ob)        = __nv_bfloat162(h0, h1);
                        *(__nv_bfloat162*)(osplit + ob + 2048) = __nv_bfloat162(l0, l1);
                    }
                } else if (EPI == 1) {
                    float z0 = v0 + bias[n0], z1 = v1 + bias[n0 + 1];
                    float w0 = (z0 / (1.f + expf(-z0))) * aux0[(size_t)m * 1024 + n0];
                    float w1 = (z1 / (1.f + expf(-z1))) * aux0[(size_t)m * 1024 + n0 + 1];
                    __nv_bfloat16 h0 = __float2bfloat16(w0);
                    __nv_bfloat16 h1 = __float2bfloat16(w1);
                    __nv_bfloat16 l0 = __float2bfloat16(w0 - __bfloat162float(h0));
                    __nv_bfloat16 l1 = __float2bfloat16(w1 - __bfloat162float(h1));
                    size_t ob = (size_t)m * 2048 + n0;
                    *(__nv_bfloat162*)(osplit + ob)        = __nv_bfloat162(h0, h1);
                    *(__nv_bfloat162*)(osplit + ob + 1024) = __nv_bfloat162(l0, l1);
                } else {
                    size_t o = (size_t)m * N + n0;
                    if (EPI == 2) { v0 += bias[n0]; v1 += bias[n0 + 1]; }
                    else {
                        v0 += aux0[o] + aux1[o];
                        v1 += aux0[o + 1] + aux1[o + 1];
                    }
                    float2 w; w.x = v0; w.y = v1;
                    *(float2*)&Cout[o] = w;
                }
            }
        }
    }
}

// ---------------- split helper: fp32 -> [hi | lo] ----------------
__global__ void k_split(const float* __restrict__ in, __nv_bfloat16* __restrict__ out, int K) {
    int idx = blockIdx.x * 256 + threadIdx.x;
    int r = idx / K, k = idx - r * K;
    float v = in[idx];
    __nv_bfloat16 hi = __float2bfloat16(v);
    __nv_bfloat16 lo = __float2bfloat16(v - __bfloat162float(hi));
    size_t b = (size_t)r * 2 * K + k;
    out[b] = hi;
    out[b + K] = lo;
}

// ---------------- K1: RMSNorm -> split A ----------------
__global__ void k_rmsnorm(const float* __restrict__ x, const float* __restrict__ rms_w) {
    int n = blockIdx.x;
    const float* xr = x + (size_t)n * C_;
    __shared__ float red[256];
    float s = 0.f;
    for (int c = threadIdx.x; c < C_; c += 256) { float v = xr[c]; s += v * v; }
    red[threadIdx.x] = s; __syncthreads();
    for (int o = 128; o > 0; o >>= 1) {
        if (threadIdx.x < o) red[threadIdx.x] += red[threadIdx.x + o];
        __syncthreads();
    }
    float nrm = sqrtf(red[0]) * 0.03125f;
    float inv = 1.0f / fmaxf(nrm, 1e-8f);
    size_t ob = (size_t)n * 2048;
    for (int c = threadIdx.x; c < C_; c += 256) {
        float v = xr[c] * inv * rms_w[c];
        __nv_bfloat16 hi = __float2bfloat16(v);
        __nv_bfloat16 lo = __float2bfloat16(v - __bfloat162float(hi));
        g_a_qkv[ob + c] = hi;
        g_a_qkv[ob + 1024 + c] = lo;
    }
}

// ---------------- K3: xPos rotary (one thread serves both batches) ----------------
__global__ void k_xpos() {
    int idx = blockIdx.x * 256 + threadIdx.x;        // over T_*512
    int t = idx >> 9;
    int j = idx & 511;
    float invf  = powf(10000.0f, -(float)j / 512.0f);
    float theta = (float)t * invf;
    float sn, cs;
    sincosf(theta, &sn, &cs);
    float svec  = (2.0f * (float)j + 0.4f * 1024.0f) / (1.4f * 1024.0f);
    float pw    = ((float)t - 1024.0f) * (1.0f / 512.0f);
    float scale = powf(svec, pw);
    float cq = cs * scale, sq = sn * scale;
    float ck = cs / scale, sk = sn / scale;
    #pragma unroll
    for (int b = 0; b < 2; b++) {
        float* q = g_qkvff + (size_t)(b * T_ + t) * C5 + 2 * j;
        float* k = q + C_;
        float q0 = q[0], q1 = q[1];
        q[0] = q0 * cq - q1 * sq;  q[1] = q1 * cq + q0 * sq;
        float k0 = k[0], k1 = k[1];
        k[0] = k0 * ck - k1 * sk;  k[1] = k1 * ck + k0 * sk;
    }
}

// ---------------- K4: chunk KV summaries ----------------
__global__ void k_chunk_kv() {
    int blk = blockIdx.x;
    int bh = blk / NC, c = blk % NC;
    int b = bh / H_, h = bh % H_;
    float gamma = 1.0f - exp2f(-5.0f - (float)h);
    __shared__ float Ks[64 * 65], Vs[64 * 64], dec[64];
    if (threadIdx.x < 64) dec[threadIdx.x] = powf(gamma, (float)(HD - threadIdx.x));
    __syncthreads();
    for (int i = threadIdx.x; i < HD * HD; i += 256) {
        int j = i >> 6, d = i & 63;
        size_t base = (size_t)(b * T_ + c * HD + j) * C5 + h * HD + d;
        Ks[j * 65 + d] = g_qkvff[base + C_] * dec[j];
        Vs[j * 64 + d] = g_qkvff[base + 2 * C_];
    }
    __syncthreads();
    float* Wout = g_W + ((size_t)bh * NC + c) * HD * HD;
    for (int p = threadIdx.x; p < 1024; p += 256) {
        int d = p >> 4, e0 = (p & 15) << 2;
        float s0 = 0, s1 = 0, s2 = 0, s3 = 0;
        #pragma unroll 8
        for (int j = 0; j < 64; j++) {
            float kd = Ks[j * 65 + d];
            float4 v4 = *(const float4*)&Vs[j * 64 + e0];
            s0 += kd * v4.x; s1 += kd * v4.y; s2 += kd * v4.z; s3 += kd * v4.w;
        }
        float4 r; r.x = s0; r.y = s1; r.z = s2; r.w = s3;
        *(float4*)&Wout[d * 64 + e0] = r;
    }
}

// ---------------- K5: state scan ----------------
__global__ void k_scan() {
    int bh = blockIdx.x;
    int h = bh % H_;
    float gamma = 1.0f - exp2f(-5.0f - (float)h);
    float g64 = powf(gamma, 64.0f);
    float st[16];
    #pragma unroll
    for (int r = 0; r < 16; r++) st[r] = 0.f;
    size_t base0 = (size_t)bh * NC * 4096;
    for (int c = 0; c < NC; c++) {
        size_t base = base0 + (size_t)c * 4096;
        #pragma unroll
        for (int r = 0; r < 16; r++) {
            int i = threadIdx.x + r * 256;
            g_S[base + i] = st[r];
            st[r] = st[r] * g64 + g_W[base + i];
        }
    }
}

// ---------------- K6: per-chunk attention + fused GroupNorm ----------------
__global__ void k_chunk_attn(const float* __restrict__ gn_w, const float* __restrict__ gn_b) {
    extern __shared__ float sm[];
    float* Qs   = sm;              // 64*65
    float* Kt   = Qs + 64 * 65;    // 64*68 (d-major)
    float* Vs   = Kt + 64 * 68;    // 64*64
    float* Ss   = Vs + 64 * 64;    // 64*64
    float* As   = Ss + 64 * 64;    // 64*68
    float* gpow = As + 64 * 68;    // 64
    int blk = blockIdx.x;
    int bh = blk / NC, c = blk % NC;
    int b = bh / H_, h = bh % H_;
    float gamma = 1.0f - exp2f(-5.0f - (float)h);
    if (threadIdx.x < 64) gpow[threadIdx.x] = powf(gamma, (float)threadIdx.x);
    for (int i = threadIdx.x; i < 4096; i += 256) {
        int j = i >> 6, d = i & 63;
        size_t base = (size_t)(b * T_ + c * HD + j) * C5 + h * HD + d;
        Qs[j * 65 + d] = g_qkvff[base];
        Kt[d * 68 + j] = g_qkvff[base + C_];
        Vs[j * 64 + d] = g_qkvff[base + 2 * C_];
        Ss[i] = g_S[((size_t)bh * NC + c) * 4096 + i];
    }
    __syncthreads();
    for (int p = threadIdx.x; p < 1024; p += 256) {
        int i = p >> 4, j0 = (p & 15) << 2;
        float s0 = 0, s1 = 0, s2 = 0, s3 = 0;
        #pragma unroll 8
        for (int d = 0; d < 64; d++) {
            float q = Qs[i * 65 + d];
            float4 k4 = *(const float4*)&Kt[d * 68 + j0];
            s0 += q * k4.x; s1 += q * k4.y; s2 += q * k4.z; s3 += q * k4.w;
        }
        float4 r;
        r.x = (j0     <= i) ? s0 * gpow[i - j0]     : 0.f;
        r.y = (j0 + 1 <= i) ? s1 * gpow[i - j0 - 1] : 0.f;
        r.z = (j0 + 2 <= i) ? s2 * gpow[i - j0 - 2] : 0.f;
        r.w = (j0 + 3 <= i) ? s3 * gpow[i - j0 - 3] : 0.f;
        *(float4*)&As[i * 68 + j0] = r;
    }
    __syncthreads();
    for (int p = threadIdx.x; p < 1024; p += 256) {
        int i = p >> 4, e0 = (p & 15) << 2;
        float a0 = 0, a1 = 0, a2 = 0, a3 = 0;
        float c0 = 0, c1 = 0, c2 = 0, c3 = 0;
        #pragma unroll 8
        for (int jj = 0; jj < 64; jj++) {
            float av = As[i * 68 + jj];
            float qv = Qs[i * 65 + jj];
            float4 v4 = *(const float4*)&Vs[jj * 64 + e0];
            float4 s4 = *(const float4*)&Ss[jj * 64 + e0];
            a0 += av * v4.x; a1 += av * v4.y; a2 += av * v4.z; a3 += av * v4.w;
            c0 += qv * s4.x; c1 += qv * s4.y; c2 += qv * s4.z; c3 += qv * s4.w;
        }
        float gi = gpow[i];
        float y0 = (a0 + gi * c0) * 0.125f;
        float y1 = (a1 + gi * c1) * 0.125f;
        float y2 = (a2 + gi * c2) * 0.125f;
        float y3 = (a3 + gi * c3) * 0.125f;
        float sum = y0 + y1 + y2 + y3;
        float sq  = y0 * y0 + y1 * y1 + y2 * y2 + y3 * y3;
        #pragma unroll
        for (int o = 8; o >= 1; o >>= 1) {
            sum += __shfl_xor_sync(~0u, sum, o);
            sq  += __shfl_xor_sync(~0u, sq, o);
        }
        float mu  = sum * (1.0f / 64.0f);
        float var = sq * (1.0f / 64.0f) - mu * mu;
        float inv = rsqrtf(var + 1e-5f);
        int cb = h * 64 + e0;
        float4 o4;
        o4.x = (y0 - mu) * inv * gn_w[cb]     + gn_b[cb];
        o4.y = (y1 - mu) * inv * gn_w[cb + 1] + gn_b[cb + 1];
        o4.z = (y2 - mu) * inv * gn_w[cb + 2] + gn_b[cb + 2];
        o4.w = (y3 - mu) * inv * gn_w[cb + 3] + gn_b[cb + 3];
        *(float4*)&g_y[(size_t)(b * T_ + c * HD + i) * C_ + cb] = o4;
    }
}

// ---------------- launch ----------------
extern "C" void kernel_launch(void* const* d_in, const int* in_sizes, int n_in,
                              void* d_out, int out_size) {
    const float* x       = (const float*)d_in[0];
    const float* w_qkvff = (const float*)d_in[1];
    const float* w_gated = (const float*)d_in[2];
    const float* b_gated = (const float*)d_in[3];
    const float* w_proj  = (const float*)d_in[4];
    const float* b_proj  = (const float*)d_in[5];
    const float* gn_w    = (const float*)d_in[6];
    const float* gn_b    = (const float*)d_in[7];
    const float* w_ff    = (const float*)d_in[8];
    const float* rms_w   = (const float*)d_in[9];
    float* out = (float*)d_out;

    float *p_qkvff, *p_y, *p_yp;
    __nv_bfloat16 *p_a_qkv, *p_b_qkv, *p_a_x, *p_b_gat, *p_a_prj, *p_b_prj, *p_a_ff, *p_b_ff;
    cudaGetSymbolAddress((void**)&p_qkvff, g_qkvff);
    cudaGetSymbolAddress((void**)&p_y,     g_y);
    cudaGetSymbolAddress((void**)&p_yp,    g_yp);
    cudaGetSymbolAddress((void**)&p_a_qkv, g_a_qkv);
    cudaGetSymbolAddress((void**)&p_b_qkv, g_b_qkv);
    cudaGetSymbolAddress((void**)&p_a_x,   g_a_x);
    cudaGetSymbolAddress((void**)&p_b_gat, g_b_gat);
    cudaGetSymbolAddress((void**)&p_a_prj, g_a_prj);
    cudaGetSymbolAddress((void**)&p_b_prj, g_b_prj);
    cudaGetSymbolAddress((void**)&p_a_ff,  g_a_ff);
    cudaGetSymbolAddress((void**)&p_b_ff,  g_b_ff);

    const int SMEM = 1024 + 3 * 49152;               // 148480
    const int ATTN_SMEM = (64*65 + 64*68 + 64*64 + 64*64 + 64*68 + 64) * 4;
    cudaFuncSetAttribute(mma_gemm<0>, cudaFuncAttributeMaxDynamicSharedMemorySize, SMEM);
    cudaFuncSetAttribute(mma_gemm<1>, cudaFuncAttributeMaxDynamicSharedMemorySize, SMEM);
    cudaFuncSetAttribute(mma_gemm<2>, cudaFuncAttributeMaxDynamicSharedMemorySize, SMEM);
    cudaFuncSetAttribute(mma_gemm<3>, cudaFuncAttributeMaxDynamicSharedMemorySize, SMEM);
    cudaFuncSetAttribute(k_chunk_attn, cudaFuncAttributeMaxDynamicSharedMemorySize, ATTN_SMEM);

    // weight + x splits
    k_split<<<(C5 * C_) / 256, 256>>>(w_qkvff, p_b_qkv, C_);
    k_split<<<(C_ * C_) / 256, 256>>>(w_gated, p_b_gat, C_);
    k_split<<<(C_ * C_) / 256, 256>>>(w_proj,  p_b_prj, C_);
    k_split<<<(C_ * 2 * C_) / 256, 256>>>(w_ff, p_b_ff, 2 * C_);
    k_split<<<(BT * C_) / 256, 256>>>(x, p_a_x, C_);

    // 1. RMSNorm (-> split A)
    k_rmsnorm<<<BT, 256>>>(x, rms_w);
    // 2. qkvff GEMM (q,k,v fp32; ff -> fused gelu+split)
    mma_gemm<0><<<dim3(C5 / 256, BT / 128), 256, SMEM>>>(
        p_a_qkv, p_b_qkv, C_, C5, p_qkvff, nullptr, nullptr, nullptr, p_a_ff);
    // 3. xPos
    k_xpos<<<(T_ * 512) / 256, 256>>>();
    // 4-6. chunked retention (+ fused GN)
    k_chunk_kv<<<BH * NC, 256>>>();
    k_scan<<<BH, 256>>>();
    k_chunk_attn<<<BH * NC, 256, ATTN_SMEM>>>(gn_w, gn_b);
    // 7. gate GEMM: silu(x @ w_gated^T + b) * y -> split for proj
    mma_gemm<1><<<dim3(C_ / 256, BT / 128), 256, SMEM>>>(
        p_a_x, p_b_gat, C_, C_, nullptr, b_gated, p_y, nullptr, p_a_prj);
    // 8. proj GEMM
    mma_gemm<2><<<dim3(C_ / 256, BT / 128), 256, SMEM>>>(
        p_a_prj, p_b_prj, C_, C_, p_yp, b_proj, nullptr, nullptr, nullptr);
    // 9. ff GEMM + residuals: out = gelu(ff) @ w_ff^T + x + yp
    mma_gemm<3><<<dim3(C_ / 256, BT / 128), 256, SMEM>>>(
        p_a_ff, p_b_ff, 2 * C_, C_, out, nullptr, x, p_yp, nullptr);
}

// round 7
// speedup vs baseline: 1.0688x; 1.0688x over previous
#include <cuda_runtime.h>
#include <cuda_bf16.h>
#include <math.h>
#include <stdint.h>

#define B_  2
#define T_  2048
#define C_  1024
#define H_  16
#define HD  64
#define BT  (B_*T_)      // 4096
#define C5  (5*C_)       // 5120
#define NC  (T_/HD)      // 32 chunks
#define BH  (B_*H_)      // 32

// ---------------- scratch (device globals) ----------------
__device__ float g_qkvff[BT*(size_t)C5];          // q,k,v fp32 (cols < 3C used)
__device__ float g_W [BH*(size_t)NC*HD*HD];
__device__ float g_S [BH*(size_t)NC*HD*HD];
__device__ float g_y [BT*(size_t)C_];             // GN'd attention out
__device__ float g_yp[BT*(size_t)C_];             // proj out
// split-bf16 GEMM operands (A: [hi|lo|hi], B: [hi|hi|lo] along K' = 3K)
__device__ __nv_bfloat16 g_a_qkv [BT*(size_t)3*C_];
__device__ __nv_bfloat16 g_b_qkv [C5*(size_t)3*C_];
__device__ __nv_bfloat16 g_a_x   [BT*(size_t)3*C_];
__device__ __nv_bfloat16 g_b_gat [C_*(size_t)3*C_];
__device__ __nv_bfloat16 g_a_prj [BT*(size_t)3*C_];
__device__ __nv_bfloat16 g_b_prj [C_*(size_t)3*C_];
__device__ __nv_bfloat16 g_a_ff  [BT*(size_t)6*C_];   // gelu(ff) split, K=2048
__device__ __nv_bfloat16 g_b_ff  [C_*(size_t)6*C_];

// ---------------- PTX helpers ----------------
__device__ __forceinline__ uint32_t smem_u32(const void* p) {
    uint32_t a;
    asm("{ .reg .u64 t; cvta.to.shared.u64 t, %1; cvt.u32.u64 %0, t; }" : "=r"(a) : "l"(p));
    return a;
}
#define CPA(dst, src)  asm volatile("cp.async.cg.shared.global [%0], [%1], 16;" :: "r"(dst), "l"(src) : "memory")
#define CPC()          asm volatile("cp.async.commit_group;" ::: "memory")
#define CPW(n)         asm volatile("cp.async.wait_group %0;" :: "n"(n) : "memory")
#define SWZ(o) ((o) ^ (((o) >> 3) & 0x70))

#define LDM_X4(r0, r1, r2, r3, a) \
    asm volatile("ldmatrix.sync.aligned.m8n8.x4.shared.b16 {%0,%1,%2,%3}, [%4];" \
        : "=r"(r0), "=r"(r1), "=r"(r2), "=r"(r3) : "r"(a))

#define MMA_BF16(d, a, b0, b1) \
    asm volatile("mma.sync.aligned.m16n8k16.row.col.f32.bf16.bf16.f32 " \
        "{%0,%1,%2,%3}, {%4,%5,%6,%7}, {%8,%9}, {%0,%1,%2,%3};" \
        : "+f"((d)[0]), "+f"((d)[1]), "+f"((d)[2]), "+f"((d)[3]) \
        : "r"((a)[0]), "r"((a)[1]), "r"((a)[2]), "r"((a)[3]), "r"(b0), "r"(b1))

// ---------------- warp-MMA split-bf16 NT GEMM (proven R4 mainloop) ----------------
// C[M, N] = A'[M, Kp] * B'[N, Kp]^T   (Kp = 3K split encoding [hi|lo|hi] x [hi|hi|lo])
// block tile 128x256, BK=64, S=4 cp.async stages, 8 warps (2m x 4n), warp 64x64
// EPI 0 (qkvff): n<3072 -> fp32 Cout ; n>=3072 -> fused gelu + split into osplit (stride 6144)
// EPI 1: silu(v+bias[n])*aux0 -> split osplit (stride 3072)
// EPI 2: v+bias[n] -> Cout     EPI 3: v+aux0+aux1 -> Cout
template<int EPI>
__global__ void __launch_bounds__(256, 1) mma_gemm(
    const __nv_bfloat16* __restrict__ A, const __nv_bfloat16* __restrict__ Bm,
    int Kp, int N, float* __restrict__ Cout,
    const float* __restrict__ bias, const float* __restrict__ aux0,
    const float* __restrict__ aux1, __nv_bfloat16* __restrict__ osplit)
{
    extern __shared__ __align__(1024) char smem_raw[];
    const int S = 4;
    const uint32_t STAGE = 49152;   // A 16KB + B 32KB
    uint32_t sbase = (smem_u32(smem_raw) + 1023) & ~1023u;

    int tid = threadIdx.x;
    int wid = tid >> 5, lane = tid & 31;
    int warp_m = wid & 1, warp_n = wid >> 1;
    int bm = blockIdx.y << 7, bn = blockIdx.x << 8;

    const int nk = Kp >> 6;

    auto load_stage = [&](int s, int k) {
        uint32_t a_s = sbase + s * STAGE;
        uint32_t b_s = a_s + 16384u;
        const __nv_bfloat16* Ag = A + (size_t)bm * Kp + (size_t)k * 64;
        const __nv_bfloat16* Bg = Bm + (size_t)bn * Kp + (size_t)k * 64;
        #pragma unroll
        for (int q = 0; q < 4; q++) {
            int i = tid + (q << 8);
            int r = i >> 3, c = i & 7;
            uint32_t off = SWZ(r * 128 + c * 16);
            CPA(a_s + off, (const char*)(Ag + (size_t)r * Kp + c * 8));
        }
        #pragma unroll
        for (int q = 0; q < 8; q++) {
            int i = tid + (q << 8);
            int r = i >> 3, c = i & 7;
            uint32_t off = SWZ(r * 128 + c * 16);
            CPA(b_s + off, (const char*)(Bg + (size_t)r * Kp + c * 8));
        }
    };

    float acc[4][8][4];
    #pragma unroll
    for (int mt = 0; mt < 4; mt++)
        #pragma unroll
        for (int nt = 0; nt < 8; nt++)
            #pragma unroll
            for (int u = 0; u < 4; u++) acc[mt][nt][u] = 0.f;

    int j = lane >> 3;
    int lrow = lane & 7;
    int a_row_off = ((j & 1) << 3) + lrow;
    int a_byte_off = (j >> 1) << 4;
    int b_row_off = ((j >> 1) << 3) + lrow;
    int b_byte_off = (j & 1) << 4;

    #pragma unroll
    for (int p = 0; p < S - 1; p++) { load_stage(p, p); CPC(); }

    for (int k = 0; k < nk; k++) {
        CPW(S - 2);
        __syncthreads();
        if (k + S - 1 < nk) load_stage((k + S - 1) % S, k + S - 1);
        CPC();

        uint32_t a_s = sbase + (uint32_t)(k % S) * STAGE;
        uint32_t b_s = a_s + 16384u;
        #pragma unroll
        for (int ks = 0; ks < 4; ks++) {
            uint32_t af[4][4], bf[4][4];
            #pragma unroll
            for (int mt = 0; mt < 4; mt++) {
                int row = warp_m * 64 + mt * 16 + a_row_off;
                uint32_t ad = a_s + SWZ(row * 128 + ks * 32 + a_byte_off);
                LDM_X4(af[mt][0], af[mt][1], af[mt][2], af[mt][3], ad);
            }
            #pragma unroll
            for (int ng = 0; ng < 4; ng++) {
                int row = warp_n * 64 + ng * 16 + b_row_off;
                uint32_t bd = b_s + SWZ(row * 128 + ks * 32 + b_byte_off);
                LDM_X4(bf[ng][0], bf[ng][1], bf[ng][2], bf[ng][3], bd);
            }
            #pragma unroll
            for (int mt = 0; mt < 4; mt++)
                #pragma unroll
                for (int nt = 0; nt < 8; nt++) {
                    uint32_t b0 = bf[nt >> 1][(nt & 1) ? 2 : 0];
                    uint32_t b1 = bf[nt >> 1][(nt & 1) ? 3 : 1];
                    MMA_BF16(acc[mt][nt], af[mt], b0, b1);
                }
        }
    }

    // ---------------- epilogue ----------------
    int gid = lane >> 2;
    int tig = lane & 3;
    #pragma unroll
    for (int mt = 0; mt < 4; mt++) {
        int m0 = bm + warp_m * 64 + mt * 16 + gid;
        #pragma unroll
        for (int nt = 0; nt < 8; nt++) {
            int n0 = bn + warp_n * 64 + nt * 8 + tig * 2;
            float* ac = acc[mt][nt];
            #pragma unroll
            for (int half = 0; half < 2; half++) {
                int m = m0 + half * 8;
                float v0 = ac[half * 2], v1 = ac[half * 2 + 1];
                if (EPI == 0) {
                    if (n0 < 3 * C_) {
                        float2 w; w.x = v0; w.y = v1;
                        *(float2*)&Cout[(size_t)m * N + n0] = w;
                    } else {
                        int e = n0 - 3 * C_;
                        float g0 = 0.5f * v0 * (1.0f + erff(v0 * 0.70710678118654752f));
                        float g1 = 0.5f * v1 * (1.0f + erff(v1 * 0.70710678118654752f));
                        __nv_bfloat16 h0 = __float2bfloat16(g0);
                        __nv_bfloat16 h1 = __float2bfloat16(g1);
                        __nv_bfloat16 l0 = __float2bfloat16(g0 - __bfloat162float(h0));
                        __nv_bfloat16 l1 = __float2bfloat16(g1 - __bfloat162float(h1));
                        size_t ob = (size_t)m * 6144 + e;
                        *(__nv_bfloat162*)(osplit + ob)        = __nv_bfloat162(h0, h1);
                        *(__nv_bfloat162*)(osplit + ob + 2048) = __nv_bfloat162(l0, l1);
                        *(__nv_bfloat162*)(osplit + ob + 4096) = __nv_bfloat162(h0, h1);
                    }
                } else if (EPI == 1) {
                    float z0 = v0 + bias[n0], z1 = v1 + bias[n0 + 1];
                    float w0 = (z0 / (1.f + expf(-z0))) * aux0[(size_t)m * 1024 + n0];
                    float w1 = (z1 / (1.f + expf(-z1))) * aux0[(size_t)m * 1024 + n0 + 1];
                    __nv_bfloat16 h0 = __float2bfloat16(w0);
                    __nv_bfloat16 h1 = __float2bfloat16(w1);
                    __nv_bfloat16 l0 = __float2bfloat16(w0 - __bfloat162float(h0));
                    __nv_bfloat16 l1 = __float2bfloat16(w1 - __bfloat162float(h1));
                    size_t ob = (size_t)m * 3072 + n0;
                    *(__nv_bfloat162*)(osplit + ob)        = __nv_bfloat162(h0, h1);
                    *(__nv_bfloat162*)(osplit + ob + 1024) = __nv_bfloat162(l0, l1);
                    *(__nv_bfloat162*)(osplit + ob + 2048) = __nv_bfloat162(h0, h1);
                } else {
                    size_t o = (size_t)m * N + n0;
                    if (EPI == 2) { v0 += bias[n0]; v1 += bias[n0 + 1]; }
                    else if (EPI == 3) {
                        v0 += aux0[o] + aux1[o];
                        v1 += aux0[o + 1] + aux1[o + 1];
                    }
                    float2 w; w.x = v0; w.y = v1;
                    *(float2*)&Cout[o] = w;
                }
            }
        }
    }
}

// ---------------- split helpers ----------------
// SIDE 0 (A): [hi|lo|hi]   SIDE 1 (B): [hi|hi|lo]
template<int SIDE>
__global__ void k_split(const float* __restrict__ in, __nv_bfloat16* __restrict__ out, int K) {
    int idx = blockIdx.x * 256 + threadIdx.x;
    int r = idx / K, k = idx - r * K;
    float v = in[idx];
    __nv_bfloat16 hi = __float2bfloat16(v);
    __nv_bfloat16 lo = __float2bfloat16(v - __bfloat162float(hi));
    size_t b = (size_t)r * 3 * K + k;
    out[b] = hi;
    out[b + K]     = SIDE ? hi : lo;
    out[b + 2 * K] = SIDE ? lo : hi;
}

// ---------------- K1: RMSNorm -> split A ----------------
__global__ void k_rmsnorm(const float* __restrict__ x, const float* __restrict__ rms_w) {
    int n = blockIdx.x;
    const float* xr = x + (size_t)n * C_;
    __shared__ float red[256];
    float s = 0.f;
    for (int c = threadIdx.x; c < C_; c += 256) { float v = xr[c]; s += v * v; }
    red[threadIdx.x] = s; __syncthreads();
    for (int o = 128; o > 0; o >>= 1) {
        if (threadIdx.x < o) red[threadIdx.x] += red[threadIdx.x + o];
        __syncthreads();
    }
    float nrm = sqrtf(red[0]) * 0.03125f;
    float inv = 1.0f / fmaxf(nrm, 1e-8f);
    size_t ob = (size_t)n * 3072;
    for (int c = threadIdx.x; c < C_; c += 256) {
        float v = xr[c] * inv * rms_w[c];
        __nv_bfloat16 hi = __float2bfloat16(v);
        __nv_bfloat16 lo = __float2bfloat16(v - __bfloat162float(hi));
        g_a_qkv[ob + c] = hi;
        g_a_qkv[ob + 1024 + c] = lo;
        g_a_qkv[ob + 2048 + c] = hi;
    }
}

// ---------------- K3: xPos rotary (one thread serves both batches) ----------------
__global__ void k_xpos() {
    int idx = blockIdx.x * 256 + threadIdx.x;        // over T_*512
    int t = idx >> 9;
    int j = idx & 511;
    float invf  = powf(10000.0f, -(float)j / 512.0f);
    float theta = (float)t * invf;
    float sn, cs;
    sincosf(theta, &sn, &cs);
    float svec  = (2.0f * (float)j + 0.4f * 1024.0f) / (1.4f * 1024.0f);
    float pw    = ((float)t - 1024.0f) * (1.0f / 512.0f);
    float scale = powf(svec, pw);
    float cq = cs * scale, sq = sn * scale;
    float ck = cs / scale, sk = sn / scale;
    #pragma unroll
    for (int b = 0; b < 2; b++) {
        float* q = g_qkvff + (size_t)(b * T_ + t) * C5 + 2 * j;
        float* k = q + C_;
        float q0 = q[0], q1 = q[1];
        q[0] = q0 * cq - q1 * sq;  q[1] = q1 * cq + q0 * sq;
        float k0 = k[0], k1 = k[1];
        k[0] = k0 * ck - k1 * sk;  k[1] = k1 * ck + k0 * sk;
    }
}

// ---------------- K4: chunk KV summaries ----------------
__global__ void k_chunk_kv() {
    int blk = blockIdx.x;
    int bh = blk / NC, c = blk % NC;
    int b = bh / H_, h = bh % H_;
    float gamma = 1.0f - exp2f(-5.0f - (float)h);
    __shared__ float Ks[64 * 65], Vs[64 * 64], dec[64];
    if (threadIdx.x < 64) dec[threadIdx.x] = powf(gamma, (float)(HD - threadIdx.x));
    __syncthreads();
    for (int i = threadIdx.x; i < HD * HD; i += 256) {
        int j = i >> 6, d = i & 63;
        size_t base = (size_t)(b * T_ + c * HD + j) * C5 + h * HD + d;
        Ks[j * 65 + d] = g_qkvff[base + C_] * dec[j];
        Vs[j * 64 + d] = g_qkvff[base + 2 * C_];
    }
    __syncthreads();
    float* Wout = g_W + ((size_t)bh * NC + c) * HD * HD;
    for (int p = threadIdx.x; p < 1024; p += 256) {
        int d = p >> 4, e0 = (p & 15) << 2;
        float s0 = 0, s1 = 0, s2 = 0, s3 = 0;
        #pragma unroll 8
        for (int j = 0; j < 64; j++) {
            float kd = Ks[j * 65 + d];
            float4 v4 = *(const float4*)&Vs[j * 64 + e0];
            s0 += kd * v4.x; s1 += kd * v4.y; s2 += kd * v4.z; s3 += kd * v4.w;
        }
        float4 r; r.x = s0; r.y = s1; r.z = s2; r.w = s3;
        *(float4*)&Wout[d * 64 + e0] = r;
    }
}

// ---------------- K5: state scan ----------------
__global__ void k_scan() {
    int bh = blockIdx.x;
    int h = bh % H_;
    float gamma = 1.0f - exp2f(-5.0f - (float)h);
    float g64 = powf(gamma, 64.0f);
    float st[16];
    #pragma unroll
    for (int r = 0; r < 16; r++) st[r] = 0.f;
    size_t base0 = (size_t)bh * NC * 4096;
    for (int c = 0; c < NC; c++) {
        size_t base = base0 + (size_t)c * 4096;
        #pragma unroll
        for (int r = 0; r < 16; r++) {
            int i = threadIdx.x + r * 256;
            g_S[base + i] = st[r];
            st[r] = st[r] * g64 + g_W[base + i];
        }
    }
}

// ---------------- K6: per-chunk attention + fused GroupNorm ----------------
__global__ void k_chunk_attn(const float* __restrict__ gn_w, const float* __restrict__ gn_b) {
    extern __shared__ float sm[];
    float* Qs   = sm;              // 64*65
    float* Kt   = Qs + 64 * 65;    // 64*68 (d-major)
    float* Vs   = Kt + 64 * 68;    // 64*64
    float* Ss   = Vs + 64 * 64;    // 64*64
    float* As   = Ss + 64 * 64;    // 64*68
    float* gpow = As + 64 * 68;    // 64
    int blk = blockIdx.x;
    int bh = blk / NC, c = blk % NC;
    int b = bh / H_, h = bh % H_;
    float gamma = 1.0f - exp2f(-5.0f - (float)h);
    if (threadIdx.x < 64) gpow[threadIdx.x] = powf(gamma, (float)threadIdx.x);
    for (int i = threadIdx.x; i < 4096; i += 256) {
        int j = i >> 6, d = i & 63;
        size_t base = (size_t)(b * T_ + c * HD + j) * C5 + h * HD + d;
        Qs[j * 65 + d] = g_qkvff[base];
        Kt[d * 68 + j] = g_qkvff[base + C_];
        Vs[j * 64 + d] = g_qkvff[base + 2 * C_];
        Ss[i] = g_S[((size_t)bh * NC + c) * 4096 + i];
    }
    __syncthreads();
    for (int p = threadIdx.x; p < 1024; p += 256) {
        int i = p >> 4, j0 = (p & 15) << 2;
        float s0 = 0, s1 = 0, s2 = 0, s3 = 0;
        #pragma unroll 8
        for (int d = 0; d < 64; d++) {
            float q = Qs[i * 65 + d];
            float4 k4 = *(const float4*)&Kt[d * 68 + j0];
            s0 += q * k4.x; s1 += q * k4.y; s2 += q * k4.z; s3 += q * k4.w;
        }
        float4 r;
        r.x = (j0     <= i) ? s0 * gpow[i - j0]     : 0.f;
        r.y = (j0 + 1 <= i) ? s1 * gpow[i - j0 - 1] : 0.f;
        r.z = (j0 + 2 <= i) ? s2 * gpow[i - j0 - 2] : 0.f;
        r.w = (j0 + 3 <= i) ? s3 * gpow[i - j0 - 3] : 0.f;
        *(float4*)&As[i * 68 + j0] = r;
    }
    __syncthreads();
    for (int p = threadIdx.x; p < 1024; p += 256) {
        int i = p >> 4, e0 = (p & 15) << 2;
        float a0 = 0, a1 = 0, a2 = 0, a3 = 0;
        float c0 = 0, c1 = 0, c2 = 0, c3 = 0;
        #pragma unroll 8
        for (int jj = 0; jj < 64; jj++) {
            float av = As[i * 68 + jj];
            float qv = Qs[i * 65 + jj];
            float4 v4 = *(const float4*)&Vs[jj * 64 + e0];
            float4 s4 = *(const float4*)&Ss[jj * 64 + e0];
            a0 += av * v4.x; a1 += av * v4.y; a2 += av * v4.z; a3 += av * v4.w;
            c0 += qv * s4.x; c1 += qv * s4.y; c2 += qv * s4.z; c3 += qv * s4.w;
        }
        float gi = gpow[i];
        float y0 = (a0 + gi * c0) * 0.125f;
        float y1 = (a1 + gi * c1) * 0.125f;
        float y2 = (a2 + gi * c2) * 0.125f;
        float y3 = (a3 + gi * c3) * 0.125f;
        float sum = y0 + y1 + y2 + y3;
        float sq  = y0 * y0 + y1 * y1 + y2 * y2 + y3 * y3;
        #pragma unroll
        for (int o = 8; o >= 1; o >>= 1) {
            sum += __shfl_xor_sync(~0u, sum, o);
            sq  += __shfl_xor_sync(~0u, sq, o);
        }
        float mu  = sum * (1.0f / 64.0f);
        float var = sq * (1.0f / 64.0f) - mu * mu;
        float inv = rsqrtf(var + 1e-5f);
        int cb = h * 64 + e0;
        float4 o4;
        o4.x = (y0 - mu) * inv * gn_w[cb]     + gn_b[cb];
        o4.y = (y1 - mu) * inv * gn_w[cb + 1] + gn_b[cb + 1];
        o4.z = (y2 - mu) * inv * gn_w[cb + 2] + gn_b[cb + 2];
        o4.w = (y3 - mu) * inv * gn_w[cb + 3] + gn_b[cb + 3];
        *(float4*)&g_y[(size_t)(b * T_ + c * HD + i) * C_ + cb] = o4;
    }
}

// ---------------- launch ----------------
extern "C" void kernel_launch(void* const* d_in, const int* in_sizes, int n_in,
                              void* d_out, int out_size) {
    const float* x       = (const float*)d_in[0];
    const float* w_qkvff = (const float*)d_in[1];
    const float* w_gated = (const float*)d_in[2];
    const float* b_gated = (const float*)d_in[3];
    const float* w_proj  = (const float*)d_in[4];
    const float* b_proj  = (const float*)d_in[5];
    const float* gn_w    = (const float*)d_in[6];
    const float* gn_b    = (const float*)d_in[7];
    const float* w_ff    = (const float*)d_in[8];
    const float* rms_w   = (const float*)d_in[9];
    float* out = (float*)d_out;

    float *p_qkvff, *p_y, *p_yp;
    __nv_bfloat16 *p_a_qkv, *p_b_qkv, *p_a_x, *p_b_gat, *p_a_prj, *p_b_prj, *p_a_ff, *p_b_ff;
    cudaGetSymbolAddress((void**)&p_qkvff, g_qkvff);
    cudaGetSymbolAddress((void**)&p_y,     g_y);
    cudaGetSymbolAddress((void**)&p_yp,    g_yp);
    cudaGetSymbolAddress((void**)&p_a_qkv, g_a_qkv);
    cudaGetSymbolAddress((void**)&p_b_qkv, g_b_qkv);
    cudaGetSymbolAddress((void**)&p_a_x,   g_a_x);
    cudaGetSymbolAddress((void**)&p_b_gat, g_b_gat);
    cudaGetSymbolAddress((void**)&p_a_prj, g_a_prj);
    cudaGetSymbolAddress((void**)&p_b_prj, g_b_prj);
    cudaGetSymbolAddress((void**)&p_a_ff,  g_a_ff);
    cudaGetSymbolAddress((void**)&p_b_ff,  g_b_ff);

    const int SMEM = 1024 + 4 * 49152;               // 197632
    const int ATTN_SMEM = (64*65 + 64*68 + 64*64 + 64*64 + 64*68 + 64) * 4;
    cudaFuncSetAttribute(mma_gemm<0>, cudaFuncAttributeMaxDynamicSharedMemorySize, SMEM);
    cudaFuncSetAttribute(mma_gemm<1>, cudaFuncAttributeMaxDynamicSharedMemorySize, SMEM);
    cudaFuncSetAttribute(mma_gemm<2>, cudaFuncAttributeMaxDynamicSharedMemorySize, SMEM);
    cudaFuncSetAttribute(mma_gemm<3>, cudaFuncAttributeMaxDynamicSharedMemorySize, SMEM);
    cudaFuncSetAttribute(k_chunk_attn, cudaFuncAttributeMaxDynamicSharedMemorySize, ATTN_SMEM);

    // weight + x splits
    k_split<1><<<(C5 * C_) / 256, 256>>>(w_qkvff, p_b_qkv, C_);
    k_split<1><<<(C_ * C_) / 256, 256>>>(w_gated, p_b_gat, C_);
    k_split<1><<<(C_ * C_) / 256, 256>>>(w_proj,  p_b_prj, C_);
    k_split<1><<<(C_ * 2 * C_) / 256, 256>>>(w_ff, p_b_ff, 2 * C_);
    k_split<0><<<(BT * C_) / 256, 256>>>(x, p_a_x, C_);

    // 1. RMSNorm (-> split A)
    k_rmsnorm<<<BT, 256>>>(x, rms_w);
    // 2. qkvff GEMM: K'=3072; q,k,v fp32; ff -> fused gelu+split
    mma_gemm<0><<<dim3(C5 / 256, BT / 128), 256, SMEM>>>(
        p_a_qkv, p_b_qkv, 3 * C_, C5, p_qkvff, nullptr, nullptr, nullptr, p_a_ff);
    // 3. xPos
    k_xpos<<<(T_ * 512) / 256, 256>>>();
    // 4-6. chunked retention (+ fused GN)
    k_chunk_kv<<<BH * NC, 256>>>();
    k_scan<<<BH, 256>>>();
    k_chunk_attn<<<BH * NC, 256, ATTN_SMEM>>>(gn_w, gn_b);
    // 7. gate GEMM: silu(x @ w_gated^T + b) * y -> split for proj
    mma_gemm<1><<<dim3(C_ / 256, BT / 128), 256, SMEM>>>(
        p_a_x, p_b_gat, 3 * C_, C_, nullptr, b_gated, p_y, nullptr, p_a_prj);
    // 8. proj GEMM
    mma_gemm<2><<<dim3(C_ / 256, BT / 128), 256, SMEM>>>(
        p_a_prj, p_b_prj, 3 * C_, C_, p_yp, b_proj, nullptr, nullptr, nullptr);
    // 9. ff GEMM + residuals: out = gelu(ff) @ w_ff^T + x + yp  (K'=6144)
    mma_gemm<3><<<dim3(C_ / 256, BT / 128), 256, SMEM>>>(
        p_a_ff, p_b_ff, 6 * C_, C_, out, nullptr, x, p_yp, nullptr);
}

// round 8
// speedup vs baseline: 1.2507x; 1.1702x over previous
#include <cuda_runtime.h>
#include <cuda_bf16.h>
#include <math.h>
#include <stdint.h>

#define B_  2
#define T_  2048
#define C_  1024
#define H_  16
#define HD  64
#define BT  (B_*T_)      // 4096
#define C5  (5*C_)       // 5120
#define NC  (T_/HD)      // 32 chunks
#define BH  (B_*H_)      // 32

// ---------------- scratch (device globals) ----------------
__device__ float g_qkvff[BT*(size_t)C5];          // q,k,v fp32 (cols < 3C used)
__device__ float g_W [BH*(size_t)NC*HD*HD];
__device__ float g_S [BH*(size_t)NC*HD*HD];
__device__ float g_y [BT*(size_t)C_];             // GN'd attention out
__device__ float g_z [BT*(size_t)C_];             // silu(gate) fp32
__device__ float g_ffout[BT*(size_t)C_];          // ff GEMM result
// split-bf16 GEMM operands (A: [hi|lo|hi], B: [hi|hi|lo] along K' = 3K)
__device__ __nv_bfloat16 g_a_qkv [BT*(size_t)3*C_];
__device__ __nv_bfloat16 g_b_qkv [C5*(size_t)3*C_];
__device__ __nv_bfloat16 g_a_x   [BT*(size_t)3*C_];
__device__ __nv_bfloat16 g_b_gat [C_*(size_t)3*C_];
__device__ __nv_bfloat16 g_a_prj [BT*(size_t)3*C_];
__device__ __nv_bfloat16 g_b_prj [C_*(size_t)3*C_];
__device__ __nv_bfloat16 g_a_ff  [BT*(size_t)6*C_];   // gelu(ff) split, K=2048
__device__ __nv_bfloat16 g_b_ff  [C_*(size_t)6*C_];

// ---------------- PTX helpers ----------------
__device__ __forceinline__ uint32_t smem_u32(const void* p) {
    uint32_t a;
    asm("{ .reg .u64 t; cvta.to.shared.u64 t, %1; cvt.u32.u64 %0, t; }" : "=r"(a) : "l"(p));
    return a;
}
#define CPA(dst, src)  asm volatile("cp.async.cg.shared.global [%0], [%1], 16;" :: "r"(dst), "l"(src) : "memory")
#define CPC()          asm volatile("cp.async.commit_group;" ::: "memory")
#define CPW(n)         asm volatile("cp.async.wait_group %0;" :: "n"(n) : "memory")
#define SWZ(o) ((o) ^ (((o) >> 3) & 0x70))

#define LDM_X4(r0, r1, r2, r3, a) \
    asm volatile("ldmatrix.sync.aligned.m8n8.x4.shared.b16 {%0,%1,%2,%3}, [%4];" \
        : "=r"(r0), "=r"(r1), "=r"(r2), "=r"(r3) : "r"(a))

#define MMA_BF16(d, a, b0, b1) \
    asm volatile("mma.sync.aligned.m16n8k16.row.col.f32.bf16.bf16.f32 " \
        "{%0,%1,%2,%3}, {%4,%5,%6,%7}, {%8,%9}, {%0,%1,%2,%3};" \
        : "+f"((d)[0]), "+f"((d)[1]), "+f"((d)[2]), "+f"((d)[3]) \
        : "r"((a)[0]), "r"((a)[1]), "r"((a)[2]), "r"((a)[3]), "r"(b0), "r"(b1))

// ---------------- warp-MMA split-bf16 NT GEMM (proven R4 mainloop) ----------------
// C[M, N] = A'[M, Kp] * B'[N, Kp]^T   (Kp = 3K split encoding [hi|lo|hi] x [hi|hi|lo])
// block tile 128x256, BK=64, S=4 cp.async stages, 8 warps (2m x 4n), warp 64x64
// EPI 0 (qkvff): n<3072 -> fp32 Cout ; n>=3072 -> fused gelu + split into osplit (stride 6144)
// EPI 1: silu(v+bias[n]) -> fp32 Cout
// EPI 2: plain -> Cout
// EPI 3: v + bias[n] + aux0[o] + aux1[o] -> Cout
template<int EPI>
__global__ void __launch_bounds__(256, 1) mma_gemm(
    const __nv_bfloat16* __restrict__ A, const __nv_bfloat16* __restrict__ Bm,
    int Kp, int N, float* __restrict__ Cout,
    const float* __restrict__ bias, const float* __restrict__ aux0,
    const float* __restrict__ aux1, __nv_bfloat16* __restrict__ osplit)
{
    extern __shared__ __align__(1024) char smem_raw[];
    const int S = 4;
    const uint32_t STAGE = 49152;   // A 16KB + B 32KB
    uint32_t sbase = (smem_u32(smem_raw) + 1023) & ~1023u;

    int tid = threadIdx.x;
    int wid = tid >> 5, lane = tid & 31;
    int warp_m = wid & 1, warp_n = wid >> 1;
    int bm = blockIdx.y << 7, bn = blockIdx.x << 8;

    const int nk = Kp >> 6;

    auto load_stage = [&](int s, int k) {
        uint32_t a_s = sbase + s * STAGE;
        uint32_t b_s = a_s + 16384u;
        const __nv_bfloat16* Ag = A + (size_t)bm * Kp + (size_t)k * 64;
        const __nv_bfloat16* Bg = Bm + (size_t)bn * Kp + (size_t)k * 64;
        #pragma unroll
        for (int q = 0; q < 4; q++) {
            int i = tid + (q << 8);
            int r = i >> 3, c = i & 7;
            uint32_t off = SWZ(r * 128 + c * 16);
            CPA(a_s + off, (const char*)(Ag + (size_t)r * Kp + c * 8));
        }
        #pragma unroll
        for (int q = 0; q < 8; q++) {
            int i = tid + (q << 8);
            int r = i >> 3, c = i & 7;
            uint32_t off = SWZ(r * 128 + c * 16);
            CPA(b_s + off, (const char*)(Bg + (size_t)r * Kp + c * 8));
        }
    };

    float acc[4][8][4];
    #pragma unroll
    for (int mt = 0; mt < 4; mt++)
        #pragma unroll
        for (int nt = 0; nt < 8; nt++)
            #pragma unroll
            for (int u = 0; u < 4; u++) acc[mt][nt][u] = 0.f;

    int j = lane >> 3;
    int lrow = lane & 7;
    int a_row_off = ((j & 1) << 3) + lrow;
    int a_byte_off = (j >> 1) << 4;
    int b_row_off = ((j >> 1) << 3) + lrow;
    int b_byte_off = (j & 1) << 4;

    #pragma unroll
    for (int p = 0; p < S - 1; p++) { load_stage(p, p); CPC(); }

    for (int k = 0; k < nk; k++) {
        CPW(S - 2);
        __syncthreads();
        if (k + S - 1 < nk) load_stage((k + S - 1) % S, k + S - 1);
        CPC();

        uint32_t a_s = sbase + (uint32_t)(k % S) * STAGE;
        uint32_t b_s = a_s + 16384u;
        #pragma unroll
        for (int ks = 0; ks < 4; ks++) {
            uint32_t af[4][4], bf[4][4];
            #pragma unroll
            for (int mt = 0; mt < 4; mt++) {
                int row = warp_m * 64 + mt * 16 + a_row_off;
                uint32_t ad = a_s + SWZ(row * 128 + ks * 32 + a_byte_off);
                LDM_X4(af[mt][0], af[mt][1], af[mt][2], af[mt][3], ad);
            }
            #pragma unroll
            for (int ng = 0; ng < 4; ng++) {
                int row = warp_n * 64 + ng * 16 + b_row_off;
                uint32_t bd = b_s + SWZ(row * 128 + ks * 32 + b_byte_off);
                LDM_X4(bf[ng][0], bf[ng][1], bf[ng][2], bf[ng][3], bd);
            }
            #pragma unroll
            for (int mt = 0; mt < 4; mt++)
                #pragma unroll
                for (int nt = 0; nt < 8; nt++) {
                    uint32_t b0 = bf[nt >> 1][(nt & 1) ? 2 : 0];
                    uint32_t b1 = bf[nt >> 1][(nt & 1) ? 3 : 1];
                    MMA_BF16(acc[mt][nt], af[mt], b0, b1);
                }
        }
    }

    // ---------------- epilogue ----------------
    int gid = lane >> 2;
    int tig = lane & 3;
    #pragma unroll
    for (int mt = 0; mt < 4; mt++) {
        int m0 = bm + warp_m * 64 + mt * 16 + gid;
        #pragma unroll
        for (int nt = 0; nt < 8; nt++) {
            int n0 = bn + warp_n * 64 + nt * 8 + tig * 2;
            float* ac = acc[mt][nt];
            #pragma unroll
            for (int half = 0; half < 2; half++) {
                int m = m0 + half * 8;
                float v0 = ac[half * 2], v1 = ac[half * 2 + 1];
                if (EPI == 0) {
                    if (n0 < 3 * C_) {
                        float2 w; w.x = v0; w.y = v1;
                        *(float2*)&Cout[(size_t)m * N + n0] = w;
                    } else {
                        int e = n0 - 3 * C_;
                        float g0 = 0.5f * v0 * (1.0f + erff(v0 * 0.70710678118654752f));
                        float g1 = 0.5f * v1 * (1.0f + erff(v1 * 0.70710678118654752f));
                        __nv_bfloat16 h0 = __float2bfloat16(g0);
                        __nv_bfloat16 h1 = __float2bfloat16(g1);
                        __nv_bfloat16 l0 = __float2bfloat16(g0 - __bfloat162float(h0));
                        __nv_bfloat16 l1 = __float2bfloat16(g1 - __bfloat162float(h1));
                        size_t ob = (size_t)m * 6144 + e;
                        *(__nv_bfloat162*)(osplit + ob)        = __nv_bfloat162(h0, h1);
                        *(__nv_bfloat162*)(osplit + ob + 2048) = __nv_bfloat162(l0, l1);
                        *(__nv_bfloat162*)(osplit + ob + 4096) = __nv_bfloat162(h0, h1);
                    }
                } else if (EPI == 1) {
                    float z0 = v0 + bias[n0], z1 = v1 + bias[n0 + 1];
                    float2 w;
                    w.x = z0 / (1.f + expf(-z0));
                    w.y = z1 / (1.f + expf(-z1));
                    *(float2*)&Cout[(size_t)m * N + n0] = w;
                } else if (EPI == 2) {
                    float2 w; w.x = v0; w.y = v1;
                    *(float2*)&Cout[(size_t)m * N + n0] = w;
                } else {
                    size_t o = (size_t)m * N + n0;
                    float2 w;
                    w.x = v0 + bias[n0]     + aux0[o]     + aux1[o];
                    w.y = v1 + bias[n0 + 1] + aux0[o + 1] + aux1[o + 1];
                    *(float2*)&Cout[o] = w;
                }
            }
        }
    }
}

// ---------------- vectorized split: fp32 -> [hi|hi|lo] (B side) ----------------
__global__ void k_splitv(const float4* __restrict__ in, __nv_bfloat16* __restrict__ out, int K) {
    int idx = blockIdx.x * 256 + threadIdx.x;      // one float4 = 4 elems
    int k4 = K >> 2;
    int r = idx / k4, k = (idx - r * k4) << 2;
    float4 v = in[idx];
    float vv[4] = {v.x, v.y, v.z, v.w};
    __nv_bfloat16 hi[4], lo[4];
    #pragma unroll
    for (int u = 0; u < 4; u++) {
        hi[u] = __float2bfloat16(vv[u]);
        lo[u] = __float2bfloat16(vv[u] - __bfloat162float(hi[u]));
    }
    uint2 hp, lp;
    ((__nv_bfloat162*)&hp)[0] = __nv_bfloat162(hi[0], hi[1]);
    ((__nv_bfloat162*)&hp)[1] = __nv_bfloat162(hi[2], hi[3]);
    ((__nv_bfloat162*)&lp)[0] = __nv_bfloat162(lo[0], lo[1]);
    ((__nv_bfloat162*)&lp)[1] = __nv_bfloat162(lo[2], lo[3]);
    size_t b = (size_t)r * 3 * K + k;
    *(uint2*)(out + b)         = hp;
    *(uint2*)(out + b + K)     = hp;
    *(uint2*)(out + b + 2 * K) = lp;
}

// ---------------- K1: RMSNorm -> a_qkv split, plus raw-x A-split ----------------
__global__ void k_rmsnorm(const float* __restrict__ x, const float* __restrict__ rms_w) {
    int n = blockIdx.x;
    const float* xr = x + (size_t)n * C_;
    __shared__ float red[256];
    float s = 0.f;
    for (int c = threadIdx.x; c < C_; c += 256) { float v = xr[c]; s += v * v; }
    red[threadIdx.x] = s; __syncthreads();
    for (int o = 128; o > 0; o >>= 1) {
        if (threadIdx.x < o) red[threadIdx.x] += red[threadIdx.x + o];
        __syncthreads();
    }
    float nrm = sqrtf(red[0]) * 0.03125f;
    float inv = 1.0f / fmaxf(nrm, 1e-8f);
    size_t ob = (size_t)n * 3072;
    for (int c = threadIdx.x; c < C_; c += 256) {
        float xv = xr[c];
        float v = xv * inv * rms_w[c];
        __nv_bfloat16 hi = __float2bfloat16(v);
        __nv_bfloat16 lo = __float2bfloat16(v - __bfloat162float(hi));
        g_a_qkv[ob + c] = hi;
        g_a_qkv[ob + 1024 + c] = lo;
        g_a_qkv[ob + 2048 + c] = hi;
        __nv_bfloat16 hx = __float2bfloat16(xv);
        __nv_bfloat16 lx = __float2bfloat16(xv - __bfloat162float(hx));
        g_a_x[ob + c] = hx;
        g_a_x[ob + 1024 + c] = lx;
        g_a_x[ob + 2048 + c] = hx;
    }
}

// ---------------- mulsplit: a_prj = split(z * y_gn) ----------------
__global__ void k_mulsplit() {
    int idx = blockIdx.x * 256 + threadIdx.x;      // one float4
    int r = idx >> 8;
    int c = (idx & 255) << 2;
    size_t o = (size_t)r * 1024 + c;
    float4 zv = *(const float4*)&g_z[o];
    float4 yv = *(const float4*)&g_y[o];
    float vv[4] = {zv.x * yv.x, zv.y * yv.y, zv.z * yv.z, zv.w * yv.w};
    __nv_bfloat16 hi[4], lo[4];
    #pragma unroll
    for (int u = 0; u < 4; u++) {
        hi[u] = __float2bfloat16(vv[u]);
        lo[u] = __float2bfloat16(vv[u] - __bfloat162float(hi[u]));
    }
    uint2 hp, lp;
    ((__nv_bfloat162*)&hp)[0] = __nv_bfloat162(hi[0], hi[1]);
    ((__nv_bfloat162*)&hp)[1] = __nv_bfloat162(hi[2], hi[3]);
    ((__nv_bfloat162*)&lp)[0] = __nv_bfloat162(lo[0], lo[1]);
    ((__nv_bfloat162*)&lp)[1] = __nv_bfloat162(lo[2], lo[3]);
    size_t b = (size_t)r * 3072 + c;
    *(uint2*)(g_a_prj + b)        = hp;
    *(uint2*)(g_a_prj + b + 1024) = lp;
    *(uint2*)(g_a_prj + b + 2048) = hp;
}

// ---------------- K3: xPos rotary (one thread serves both batches) ----------------
__global__ void k_xpos() {
    int idx = blockIdx.x * 256 + threadIdx.x;        // over T_*512
    int t = idx >> 9;
    int j = idx & 511;
    float invf  = powf(10000.0f, -(float)j / 512.0f);
    float theta = (float)t * invf;
    float sn, cs;
    sincosf(theta, &sn, &cs);
    float svec  = (2.0f * (float)j + 0.4f * 1024.0f) / (1.4f * 1024.0f);
    float pw    = ((float)t - 1024.0f) * (1.0f / 512.0f);
    float scale = powf(svec, pw);
    float cq = cs * scale, sq = sn * scale;
    float ck = cs / scale, sk = sn / scale;
    #pragma unroll
    for (int b = 0; b < 2; b++) {
        float* q = g_qkvff + (size_t)(b * T_ + t) * C5 + 2 * j;
        float* k = q + C_;
        float q0 = q[0], q1 = q[1];
        q[0] = q0 * cq - q1 * sq;  q[1] = q1 * cq + q0 * sq;
        float k0 = k[0], k1 = k[1];
        k[0] = k0 * ck - k1 * sk;  k[1] = k1 * ck + k0 * sk;
    }
}

// ---------------- K4: chunk KV summaries ----------------
__global__ void k_chunk_kv() {
    int blk = blockIdx.x;
    int bh = blk / NC, c = blk % NC;
    int b = bh / H_, h = bh % H_;
    float gamma = 1.0f - exp2f(-5.0f - (float)h);
    __shared__ float Ks[64 * 65], Vs[64 * 64], dec[64];
    if (threadIdx.x < 64) dec[threadIdx.x] = powf(gamma, (float)(HD - threadIdx.x));
    __syncthreads();
    for (int i = threadIdx.x; i < HD * HD; i += 256) {
        int j = i >> 6, d = i & 63;
        size_t base = (size_t)(b * T_ + c * HD + j) * C5 + h * HD + d;
        Ks[j * 65 + d] = g_qkvff[base + C_] * dec[j];
        Vs[j * 64 + d] = g_qkvff[base + 2 * C_];
    }
    __syncthreads();
    float* Wout = g_W + ((size_t)bh * NC + c) * HD * HD;
    for (int p = threadIdx.x; p < 1024; p += 256) {
        int d = p >> 4, e0 = (p & 15) << 2;
        float s0 = 0, s1 = 0, s2 = 0, s3 = 0;
        #pragma unroll 8
        for (int j = 0; j < 64; j++) {
            float kd = Ks[j * 65 + d];
            float4 v4 = *(const float4*)&Vs[j * 64 + e0];
            s0 += kd * v4.x; s1 += kd * v4.y; s2 += kd * v4.z; s3 += kd * v4.w;
        }
        float4 r; r.x = s0; r.y = s1; r.z = s2; r.w = s3;
        *(float4*)&Wout[d * 64 + e0] = r;
    }
}

// ---------------- K5: state scan ----------------
__global__ void k_scan() {
    int bh = blockIdx.x;
    int h = bh % H_;
    float gamma = 1.0f - exp2f(-5.0f - (float)h);
    float g64 = powf(gamma, 64.0f);
    float st[16];
    #pragma unroll
    for (int r = 0; r < 16; r++) st[r] = 0.f;
    size_t base0 = (size_t)bh * NC * 4096;
    for (int c = 0; c < NC; c++) {
        size_t base = base0 + (size_t)c * 4096;
        #pragma unroll
        for (int r = 0; r < 16; r++) {
            int i = threadIdx.x + r * 256;
            g_S[base + i] = st[r];
            st[r] = st[r] * g64 + g_W[base + i];
        }
    }
}

// ---------------- K6: per-chunk attention + fused GroupNorm ----------------
__global__ void k_chunk_attn(const float* __restrict__ gn_w, const float* __restrict__ gn_b) {
    extern __shared__ float sm[];
    float* Qs   = sm;              // 64*65
    float* Kt   = Qs + 64 * 65;    // 64*68 (d-major)
    float* Vs   = Kt + 64 * 68;    // 64*64
    float* Ss   = Vs + 64 * 64;    // 64*64
    float* As   = Ss + 64 * 64;    // 64*68
    float* gpow = As + 64 * 68;    // 64
    int blk = blockIdx.x;
    int bh = blk / NC, c = blk % NC;
    int b = bh / H_, h = bh % H_;
    float gamma = 1.0f - exp2f(-5.0f - (float)h);
    if (threadIdx.x < 64) gpow[threadIdx.x] = powf(gamma, (float)threadIdx.x);
    for (int i = threadIdx.x; i < 4096; i += 256) {
        int j = i >> 6, d = i & 63;
        size_t base = (size_t)(b * T_ + c * HD + j) * C5 + h * HD + d;
        Qs[j * 65 + d] = g_qkvff[base];
        Kt[d * 68 + j] = g_qkvff[base + C_];
        Vs[j * 64 + d] = g_qkvff[base + 2 * C_];
        Ss[i] = g_S[((size_t)bh * NC + c) * 4096 + i];
    }
    __syncthreads();
    for (int p = threadIdx.x; p < 1024; p += 256) {
        int i = p >> 4, j0 = (p & 15) << 2;
        float s0 = 0, s1 = 0, s2 = 0, s3 = 0;
        #pragma unroll 8
        for (int d = 0; d < 64; d++) {
            float q = Qs[i * 65 + d];
            float4 k4 = *(const float4*)&Kt[d * 68 + j0];
            s0 += q * k4.x; s1 += q * k4.y; s2 += q * k4.z; s3 += q * k4.w;
        }
        float4 r;
        r.x = (j0     <= i) ? s0 * gpow[i - j0]     : 0.f;
        r.y = (j0 + 1 <= i) ? s1 * gpow[i - j0 - 1] : 0.f;
        r.z = (j0 + 2 <= i) ? s2 * gpow[i - j0 - 2] : 0.f;
        r.w = (j0 + 3 <= i) ? s3 * gpow[i - j0 - 3] : 0.f;
        *(float4*)&As[i * 68 + j0] = r;
    }
    __syncthreads();
    for (int p = threadIdx.x; p < 1024; p += 256) {
        int i = p >> 4, e0 = (p & 15) << 2;
        float a0 = 0, a1 = 0, a2 = 0, a3 = 0;
        float c0 = 0, c1 = 0, c2 = 0, c3 = 0;
        #pragma unroll 8
        for (int jj = 0; jj < 64; jj++) {
            float av = As[i * 68 + jj];
            float qv = Qs[i * 65 + jj];
            float4 v4 = *(const float4*)&Vs[jj * 64 + e0];
            float4 s4 = *(const float4*)&Ss[jj * 64 + e0];
            a0 += av * v4.x; a1 += av * v4.y; a2 += av * v4.z; a3 += av * v4.w;
            c0 += qv * s4.x; c1 += qv * s4.y; c2 += qv * s4.z; c3 += qv * s4.w;
        }
        float gi = gpow[i];
        float y0 = (a0 + gi * c0) * 0.125f;
        float y1 = (a1 + gi * c1) * 0.125f;
        float y2 = (a2 + gi * c2) * 0.125f;
        float y3 = (a3 + gi * c3) * 0.125f;
        float sum = y0 + y1 + y2 + y3;
        float sq  = y0 * y0 + y1 * y1 + y2 * y2 + y3 * y3;
        #pragma unroll
        for (int o = 8; o >= 1; o >>= 1) {
            sum += __shfl_xor_sync(~0u, sum, o);
            sq  += __shfl_xor_sync(~0u, sq, o);
        }
        float mu  = sum * (1.0f / 64.0f);
        float var = sq * (1.0f / 64.0f) - mu * mu;
        float inv = rsqrtf(var + 1e-5f);
        int cb = h * 64 + e0;
        float4 o4;
        o4.x = (y0 - mu) * inv * gn_w[cb]     + gn_b[cb];
        o4.y = (y1 - mu) * inv * gn_w[cb + 1] + gn_b[cb + 1];
        o4.z = (y2 - mu) * inv * gn_w[cb + 2] + gn_b[cb + 2];
        o4.w = (y3 - mu) * inv * gn_w[cb + 3] + gn_b[cb + 3];
        *(float4*)&g_y[(size_t)(b * T_ + c * HD + i) * C_ + cb] = o4;
    }
}

// ---------------- launch ----------------
extern "C" void kernel_launch(void* const* d_in, const int* in_sizes, int n_in,
                              void* d_out, int out_size) {
    const float* x       = (const float*)d_in[0];
    const float* w_qkvff = (const float*)d_in[1];
    const float* w_gated = (const float*)d_in[2];
    const float* b_gated = (const float*)d_in[3];
    const float* w_proj  = (const float*)d_in[4];
    const float* b_proj  = (const float*)d_in[5];
    const float* gn_w    = (const float*)d_in[6];
    const float* gn_b    = (const float*)d_in[7];
    const float* w_ff    = (const float*)d_in[8];
    const float* rms_w   = (const float*)d_in[9];
    float* out = (float*)d_out;

    float *p_qkvff, *p_z, *p_ffout;
    __nv_bfloat16 *p_a_qkv, *p_b_qkv, *p_a_x, *p_b_gat, *p_a_prj, *p_b_prj, *p_a_ff, *p_b_ff;
    cudaGetSymbolAddress((void**)&p_qkvff, g_qkvff);
    cudaGetSymbolAddress((void**)&p_z,     g_z);
    cudaGetSymbolAddress((void**)&p_ffout, g_ffout);
    cudaGetSymbolAddress((void**)&p_a_qkv, g_a_qkv);
    cudaGetSymbolAddress((void**)&p_b_qkv, g_b_qkv);
    cudaGetSymbolAddress((void**)&p_a_x,   g_a_x);
    cudaGetSymbolAddress((void**)&p_b_gat, g_b_gat);
    cudaGetSymbolAddress((void**)&p_a_prj, g_a_prj);
    cudaGetSymbolAddress((void**)&p_b_prj, g_b_prj);
    cudaGetSymbolAddress((void**)&p_a_ff,  g_a_ff);
    cudaGetSymbolAddress((void**)&p_b_ff,  g_b_ff);

    const int SMEM = 1024 + 4 * 49152;               // 197632
    const int ATTN_SMEM = (64*65 + 64*68 + 64*64 + 64*64 + 64*68 + 64) * 4;

    // one-time infra (created on the uncaptured correctness call; reused thereafter;
    // identical GPU work is enqueued on every call)
    static cudaStream_t s1 = nullptr;
    static cudaEvent_t ev0, ev_ax, ev_qkv, ev_gate, ev_ff;
    if (s1 == nullptr) {
        cudaStreamCreateWithFlags(&s1, cudaStreamNonBlocking);
        cudaEventCreateWithFlags(&ev0,     cudaEventDisableTiming);
        cudaEventCreateWithFlags(&ev_ax,   cudaEventDisableTiming);
        cudaEventCreateWithFlags(&ev_qkv,  cudaEventDisableTiming);
        cudaEventCreateWithFlags(&ev_gate, cudaEventDisableTiming);
        cudaEventCreateWithFlags(&ev_ff,   cudaEventDisableTiming);
        cudaFuncSetAttribute(mma_gemm<0>, cudaFuncAttributeMaxDynamicSharedMemorySize, SMEM);
        cudaFuncSetAttribute(mma_gemm<1>, cudaFuncAttributeMaxDynamicSharedMemorySize, SMEM);
        cudaFuncSetAttribute(mma_gemm<2>, cudaFuncAttributeMaxDynamicSharedMemorySize, SMEM);
        cudaFuncSetAttribute(mma_gemm<3>, cudaFuncAttributeMaxDynamicSharedMemorySize, SMEM);
        cudaFuncSetAttribute(k_chunk_attn, cudaFuncAttributeMaxDynamicSharedMemorySize, ATTN_SMEM);
    }

    // ---- fork: s1 joins capture via ev0 ----
    cudaEventRecord(ev0, 0);
    cudaStreamWaitEvent(s1, ev0, 0);

    // s1: weight splits for gate / proj / ff (independent of main chain)
    k_splitv<<<(C_ * C_) / 1024, 256, 0, s1>>>((const float4*)w_gated, p_b_gat, C_);
    k_splitv<<<(C_ * C_) / 1024, 256, 0, s1>>>((const float4*)w_proj,  p_b_prj, C_);
    k_splitv<<<(C_ * 2 * C_) / 1024, 256, 0, s1>>>((const float4*)w_ff, p_b_ff, 2 * C_);

    // main: qkv weight split + RMSNorm (also emits raw-x split)
    k_splitv<<<(C5 * C_) / 1024, 256>>>((const float4*)w_qkvff, p_b_qkv, C_);
    k_rmsnorm<<<BT, 256>>>(x, rms_w);
    cudaEventRecord(ev_ax, 0);

    // s1: gate GEMM z = silu(x @ w_gated^T + b)   (needs a_x)
    cudaStreamWaitEvent(s1, ev_ax, 0);
    mma_gemm<1><<<dim3(C_ / 256, BT / 128), 256, SMEM, s1>>>(
        p_a_x, p_b_gat, 3 * C_, C_, p_z, b_gated, nullptr, nullptr, nullptr);
    cudaEventRecord(ev_gate, s1);

    // main: qkvff GEMM (q,k,v fp32; ff -> fused gelu+split)
    mma_gemm<0><<<dim3(C5 / 256, BT / 128), 256, SMEM>>>(
        p_a_qkv, p_b_qkv, 3 * C_, C5, p_qkvff, nullptr, nullptr, nullptr, p_a_ff);
    cudaEventRecord(ev_qkv, 0);

    // s1: ff GEMM ffout = gelu(ff) @ w_ff^T   (needs a_ff)
    cudaStreamWaitEvent(s1, ev_qkv, 0);
    mma_gemm<2><<<dim3(C_ / 256, BT / 128), 256, SMEM, s1>>>(
        p_a_ff, p_b_ff, 6 * C_, C_, p_ffout, nullptr, nullptr, nullptr, nullptr);
    cudaEventRecord(ev_ff, s1);

    // main: attention chain (overlaps with s1's gate + ff GEMMs)
    k_xpos<<<(T_ * 512) / 256, 256>>>();
    k_chunk_kv<<<BH * NC, 256>>>();
    k_scan<<<BH, 256>>>();
    k_chunk_attn<<<BH * NC, 256, ATTN_SMEM>>>(gn_w, gn_b);

    // join: a_prj = split(z * y_gn)
    cudaStreamWaitEvent(0, ev_gate, 0);
    k_mulsplit<<<BT, 256>>>();

    // join ff, then final proj GEMM: out = y2 @ w_proj^T + b_proj + x + ffout
    cudaStreamWaitEvent(0, ev_ff, 0);
    mma_gemm<3><<<dim3(C_ / 256, BT / 128), 256, SMEM>>>(
        p_a_prj, p_b_prj, 3 * C_, C_, out, b_proj, x, p_ffout, nullptr);
}

// round 9
// speedup vs baseline: 1.5729x; 1.2576x over previous
#include <cuda_runtime.h>
#include <cuda_fp16.h>
#include <math.h>
#include <stdint.h>

#define B_  2
#define T_  2048
#define C_  1024
#define H_  16
#define HD  64
#define BT  (B_*T_)      // 4096
#define C5  (5*C_)       // 5120
#define NC  (T_/HD)      // 32 chunks
#define BH  (B_*H_)      // 32

// ---------------- scratch (device globals) ----------------
__device__ float g_qkvff[BT*(size_t)C5];          // q,k,v fp32 (cols < 3C used)
__device__ float g_W [BH*(size_t)NC*HD*HD];
__device__ float g_S [BH*(size_t)NC*HD*HD];
__device__ float g_y [BT*(size_t)C_];             // GN'd attention out
__device__ float g_z [BT*(size_t)C_];             // silu(gate) fp32
__device__ float g_ffout[BT*(size_t)C_];          // ff GEMM result
// split-fp16 GEMM operands: A = [hi|lo], B = [b|b] along K' = 2K
__device__ __half g_a_qkv [BT*(size_t)2*C_];
__device__ __half g_b_qkv [C5*(size_t)2*C_];
__device__ __half g_a_x   [BT*(size_t)2*C_];
__device__ __half g_b_gat [C_*(size_t)2*C_];
__device__ __half g_a_prj [BT*(size_t)2*C_];
__device__ __half g_b_prj [C_*(size_t)2*C_];
__device__ __half g_a_ff  [BT*(size_t)4*C_];      // gelu(ff) split, K=2048
__device__ __half g_b_ff  [C_*(size_t)4*C_];

// ---------------- PTX helpers ----------------
__device__ __forceinline__ uint32_t smem_u32(const void* p) {
    uint32_t a;
    asm("{ .reg .u64 t; cvta.to.shared.u64 t, %1; cvt.u32.u64 %0, t; }" : "=r"(a) : "l"(p));
    return a;
}
#define CPA(dst, src)  asm volatile("cp.async.cg.shared.global [%0], [%1], 16;" :: "r"(dst), "l"(src) : "memory")
#define CPC()          asm volatile("cp.async.commit_group;" ::: "memory")
#define CPW(n)         asm volatile("cp.async.wait_group %0;" :: "n"(n) : "memory")
#define SWZ(o) ((o) ^ (((o) >> 3) & 0x70))

#define LDM_X4(r0, r1, r2, r3, a) \
    asm volatile("ldmatrix.sync.aligned.m8n8.x4.shared.b16 {%0,%1,%2,%3}, [%4];" \
        : "=r"(r0), "=r"(r1), "=r"(r2), "=r"(r3) : "r"(a))

#define MMA_F16(d, a, b0, b1) \
    asm volatile("mma.sync.aligned.m16n8k16.row.col.f32.f16.f16.f32 " \
        "{%0,%1,%2,%3}, {%4,%5,%6,%7}, {%8,%9}, {%0,%1,%2,%3};" \
        : "+f"((d)[0]), "+f"((d)[1]), "+f"((d)[2]), "+f"((d)[3]) \
        : "r"((a)[0]), "r"((a)[1]), "r"((a)[2]), "r"((a)[3]), "r"(b0), "r"(b1))

// ---------------- warp-MMA split-fp16 NT GEMM (proven R4 mainloop) ----------------
// C[M, N] = A'[M, Kp] * B'[N, Kp]^T   (Kp = 2K; A = [hi|lo] fp16, B = [b|b] fp16)
// block tile 128x256, BK=64, S=4 cp.async stages, 8 warps (2m x 4n), warp 64x64
// EPI 0 (qkvff): n<3072 -> fp32 Cout ; n>=3072 -> fused gelu + split into osplit (stride 4096)
// EPI 1: silu(v+bias[n]) -> fp32 Cout
// EPI 2: plain -> Cout
// EPI 3: v + bias[n] + aux0[o] + aux1[o] -> Cout
template<int EPI>
__global__ void __launch_bounds__(256, 1) mma_gemm(
    const __half* __restrict__ A, const __half* __restrict__ Bm,
    int Kp, int N, float* __restrict__ Cout,
    const float* __restrict__ bias, const float* __restrict__ aux0,
    const float* __restrict__ aux1, __half* __restrict__ osplit)
{
    extern __shared__ __align__(1024) char smem_raw[];
    const int S = 4;
    const uint32_t STAGE = 49152;   // A 16KB + B 32KB
    uint32_t sbase = (smem_u32(smem_raw) + 1023) & ~1023u;

    int tid = threadIdx.x;
    int wid = tid >> 5, lane = tid & 31;
    int warp_m = wid & 1, warp_n = wid >> 1;
    int bm = blockIdx.y << 7, bn = blockIdx.x << 8;

    const int nk = Kp >> 6;

    auto load_stage = [&](int s, int k) {
        uint32_t a_s = sbase + s * STAGE;
        uint32_t b_s = a_s + 16384u;
        const __half* Ag = A + (size_t)bm * Kp + (size_t)k * 64;
        const __half* Bg = Bm + (size_t)bn * Kp + (size_t)k * 64;
        #pragma unroll
        for (int q = 0; q < 4; q++) {
            int i = tid + (q << 8);
            int r = i >> 3, c = i & 7;
            uint32_t off = SWZ(r * 128 + c * 16);
            CPA(a_s + off, (const char*)(Ag + (size_t)r * Kp + c * 8));
        }
        #pragma unroll
        for (int q = 0; q < 8; q++) {
            int i = tid + (q << 8);
            int r = i >> 3, c = i & 7;
            uint32_t off = SWZ(r * 128 + c * 16);
            CPA(b_s + off, (const char*)(Bg + (size_t)r * Kp + c * 8));
        }
    };

    float acc[4][8][4];
    #pragma unroll
    for (int mt = 0; mt < 4; mt++)
        #pragma unroll
        for (int nt = 0; nt < 8; nt++)
            #pragma unroll
            for (int u = 0; u < 4; u++) acc[mt][nt][u] = 0.f;

    int j = lane >> 3;
    int lrow = lane & 7;
    int a_row_off = ((j & 1) << 3) + lrow;
    int a_byte_off = (j >> 1) << 4;
    int b_row_off = ((j >> 1) << 3) + lrow;
    int b_byte_off = (j & 1) << 4;

    #pragma unroll
    for (int p = 0; p < S - 1; p++) { load_stage(p, p); CPC(); }

    for (int k = 0; k < nk; k++) {
        CPW(S - 2);
        __syncthreads();
        if (k + S - 1 < nk) load_stage((k + S - 1) % S, k + S - 1);
        CPC();

        uint32_t a_s = sbase + (uint32_t)(k % S) * STAGE;
        uint32_t b_s = a_s + 16384u;
        #pragma unroll
        for (int ks = 0; ks < 4; ks++) {
            uint32_t af[4][4], bf[4][4];
            #pragma unroll
            for (int mt = 0; mt < 4; mt++) {
                int row = warp_m * 64 + mt * 16 + a_row_off;
                uint32_t ad = a_s + SWZ(row * 128 + ks * 32 + a_byte_off);
                LDM_X4(af[mt][0], af[mt][1], af[mt][2], af[mt][3], ad);
            }
            #pragma unroll
            for (int ng = 0; ng < 4; ng++) {
                int row = warp_n * 64 + ng * 16 + b_row_off;
                uint32_t bd = b_s + SWZ(row * 128 + ks * 32 + b_byte_off);
                LDM_X4(bf[ng][0], bf[ng][1], bf[ng][2], bf[ng][3], bd);
            }
            #pragma unroll
            for (int mt = 0; mt < 4; mt++)
                #pragma unroll
                for (int nt = 0; nt < 8; nt++) {
                    uint32_t b0 = bf[nt >> 1][(nt & 1) ? 2 : 0];
                    uint32_t b1 = bf[nt >> 1][(nt & 1) ? 3 : 1];
                    MMA_F16(acc[mt][nt], af[mt], b0, b1);
                }
        }
    }

    // ---------------- epilogue ----------------
    int gid = lane >> 2;
    int tig = lane & 3;
    #pragma unroll
    for (int mt = 0; mt < 4; mt++) {
        int m0 = bm + warp_m * 64 + mt * 16 + gid;
        #pragma unroll
        for (int nt = 0; nt < 8; nt++) {
            int n0 = bn + warp_n * 64 + nt * 8 + tig * 2;
            float* ac = acc[mt][nt];
            #pragma unroll
            for (int half_ = 0; half_ < 2; half_++) {
                int m = m0 + half_ * 8;
                float v0 = ac[half_ * 2], v1 = ac[half_ * 2 + 1];
                if (EPI == 0) {
                    if (n0 < 3 * C_) {
                        float2 w; w.x = v0; w.y = v1;
                        *(float2*)&Cout[(size_t)m * N + n0] = w;
                    } else {
                        int e = n0 - 3 * C_;
                        float g0 = 0.5f * v0 * (1.0f + erff(v0 * 0.70710678118654752f));
                        float g1 = 0.5f * v1 * (1.0f + erff(v1 * 0.70710678118654752f));
                        __half h0 = __float2half(g0);
                        __half h1 = __float2half(g1);
                        __half l0 = __float2half(g0 - __half2float(h0));
                        __half l1 = __float2half(g1 - __half2float(h1));
                        size_t ob = (size_t)m * 4096 + e;
                        *(__half2*)(osplit + ob)        = __halves2half2(h0, h1);
                        *(__half2*)(osplit + ob + 2048) = __halves2half2(l0, l1);
                    }
                } else if (EPI == 1) {
                    float z0 = v0 + bias[n0], z1 = v1 + bias[n0 + 1];
                    float2 w;
                    w.x = z0 / (1.f + expf(-z0));
                    w.y = z1 / (1.f + expf(-z1));
                    *(float2*)&Cout[(size_t)m * N + n0] = w;
                } else if (EPI == 2) {
                    float2 w; w.x = v0; w.y = v1;
                    *(float2*)&Cout[(size_t)m * N + n0] = w;
                } else {
                    size_t o = (size_t)m * N + n0;
                    float2 w;
                    w.x = v0 + bias[n0]     + aux0[o]     + aux1[o];
                    w.y = v1 + bias[n0 + 1] + aux0[o + 1] + aux1[o + 1];
                    *(float2*)&Cout[o] = w;
                }
            }
        }
    }
}

// ---------------- vectorized B split: fp32 -> [b|b] fp16 duplicated ----------------
__global__ void k_splitv(const float4* __restrict__ in, __half* __restrict__ out, int K) {
    int idx = blockIdx.x * 256 + threadIdx.x;      // one float4 = 4 elems
    int k4 = K >> 2;
    int r = idx / k4, k = (idx - r * k4) << 2;
    float4 v = in[idx];
    __half2 h01 = __halves2half2(__float2half(v.x), __float2half(v.y));
    __half2 h23 = __halves2half2(__float2half(v.z), __float2half(v.w));
    uint2 hp;
    ((__half2*)&hp)[0] = h01;
    ((__half2*)&hp)[1] = h23;
    size_t b = (size_t)r * 2 * K + k;
    *(uint2*)(out + b)     = hp;
    *(uint2*)(out + b + K) = hp;
}

// ---------------- K1: RMSNorm -> a_qkv [hi|lo], plus raw-x [hi|lo] ----------------
__global__ void k_rmsnorm(const float* __restrict__ x, const float* __restrict__ rms_w) {
    int n = blockIdx.x;
    const float* xr = x + (size_t)n * C_;
    __shared__ float red[256];
    float s = 0.f;
    for (int c = threadIdx.x; c < C_; c += 256) { float v = xr[c]; s += v * v; }
    red[threadIdx.x] = s; __syncthreads();
    for (int o = 128; o > 0; o >>= 1) {
        if (threadIdx.x < o) red[threadIdx.x] += red[threadIdx.x + o];
        __syncthreads();
    }
    float nrm = sqrtf(red[0]) * 0.03125f;
    float inv = 1.0f / fmaxf(nrm, 1e-8f);
    size_t ob = (size_t)n * 2048;
    for (int c = threadIdx.x; c < C_; c += 256) {
        float xv = xr[c];
        float v = xv * inv * rms_w[c];
        __half hi = __float2half(v);
        __half lo = __float2half(v - __half2float(hi));
        g_a_qkv[ob + c] = hi;
        g_a_qkv[ob + 1024 + c] = lo;
        __half hx = __float2half(xv);
        __half lx = __float2half(xv - __half2float(hx));
        g_a_x[ob + c] = hx;
        g_a_x[ob + 1024 + c] = lx;
    }
}

// ---------------- mulsplit: a_prj = split_fp16(z * y_gn) ----------------
__global__ void k_mulsplit() {
    int idx = blockIdx.x * 256 + threadIdx.x;      // one float4
    int r = idx >> 8;
    int c = (idx & 255) << 2;
    size_t o = (size_t)r * 1024 + c;
    float4 zv = *(const float4*)&g_z[o];
    float4 yv = *(const float4*)&g_y[o];
    float vv[4] = {zv.x * yv.x, zv.y * yv.y, zv.z * yv.z, zv.w * yv.w};
    __half hi[4], lo[4];
    #pragma unroll
    for (int u = 0; u < 4; u++) {
        hi[u] = __float2half(vv[u]);
        lo[u] = __float2half(vv[u] - __half2float(hi[u]));
    }
    uint2 hp, lp;
    ((__half2*)&hp)[0] = __halves2half2(hi[0], hi[1]);
    ((__half2*)&hp)[1] = __halves2half2(hi[2], hi[3]);
    ((__half2*)&lp)[0] = __halves2half2(lo[0], lo[1]);
    ((__half2*)&lp)[1] = __halves2half2(lo[2], lo[3]);
    size_t b = (size_t)r * 2048 + c;
    *(uint2*)(g_a_prj + b)        = hp;
    *(uint2*)(g_a_prj + b + 1024) = lp;
}

// ---------------- K3: xPos rotary (one thread serves both batches) ----------------
__global__ void k_xpos() {
    int idx = blockIdx.x * 256 + threadIdx.x;        // over T_*512
    int t = idx >> 9;
    int j = idx & 511;
    float invf  = powf(10000.0f, -(float)j / 512.0f);
    float theta = (float)t * invf;
    float sn, cs;
    sincosf(theta, &sn, &cs);
    float svec  = (2.0f * (float)j + 0.4f * 1024.0f) / (1.4f * 1024.0f);
    float pw    = ((float)t - 1024.0f) * (1.0f / 512.0f);
    float scale = powf(svec, pw);
    float cq = cs * scale, sq = sn * scale;
    float ck = cs / scale, sk = sn / scale;
    #pragma unroll
    for (int b = 0; b < 2; b++) {
        float* q = g_qkvff + (size_t)(b * T_ + t) * C5 + 2 * j;
        float* k = q + C_;
        float q0 = q[0], q1 = q[1];
        q[0] = q0 * cq - q1 * sq;  q[1] = q1 * cq + q0 * sq;
        float k0 = k[0], k1 = k[1];
        k[0] = k0 * ck - k1 * sk;  k[1] = k1 * ck + k0 * sk;
    }
}

// ---------------- K4: chunk KV summaries ----------------
__global__ void k_chunk_kv() {
    int blk = blockIdx.x;
    int bh = blk / NC, c = blk % NC;
    int b = bh / H_, h = bh % H_;
    float gamma = 1.0f - exp2f(-5.0f - (float)h);
    __shared__ float Ks[64 * 65], Vs[64 * 64], dec[64];
    if (threadIdx.x < 64) dec[threadIdx.x] = powf(gamma, (float)(HD - threadIdx.x));
    __syncthreads();
    for (int i = threadIdx.x; i < HD * HD; i += 256) {
        int j = i >> 6, d = i & 63;
        size_t base = (size_t)(b * T_ + c * HD + j) * C5 + h * HD + d;
        Ks[j * 65 + d] = g_qkvff[base + C_] * dec[j];
        Vs[j * 64 + d] = g_qkvff[base + 2 * C_];
    }
    __syncthreads();
    float* Wout = g_W + ((size_t)bh * NC + c) * HD * HD;
    for (int p = threadIdx.x; p < 1024; p += 256) {
        int d = p >> 4, e0 = (p & 15) << 2;
        float s0 = 0, s1 = 0, s2 = 0, s3 = 0;
        #pragma unroll 8
        for (int j = 0; j < 64; j++) {
            float kd = Ks[j * 65 + d];
            float4 v4 = *(const float4*)&Vs[j * 64 + e0];
            s0 += kd * v4.x; s1 += kd * v4.y; s2 += kd * v4.z; s3 += kd * v4.w;
        }
        float4 r; r.x = s0; r.y = s1; r.z = s2; r.w = s3;
        *(float4*)&Wout[d * 64 + e0] = r;
    }
}

// ---------------- K5: state scan ----------------
__global__ void k_scan() {
    int bh = blockIdx.x;
    int h = bh % H_;
    float gamma = 1.0f - exp2f(-5.0f - (float)h);
    float g64 = powf(gamma, 64.0f);
    float st[16];
    #pragma unroll
    for (int r = 0; r < 16; r++) st[r] = 0.f;
    size_t base0 = (size_t)bh * NC * 4096;
    for (int c = 0; c < NC; c++) {
        size_t base = base0 + (size_t)c * 4096;
        #pragma unroll
        for (int r = 0; r < 16; r++) {
            int i = threadIdx.x + r * 256;
            g_S[base + i] = st[r];
            st[r] = st[r] * g64 + g_W[base + i];
        }
    }
}

// ---------------- K6: per-chunk attention + fused GroupNorm ----------------
__global__ void k_chunk_attn(const float* __restrict__ gn_w, const float* __restrict__ gn_b) {
    extern __shared__ float sm[];
    float* Qs   = sm;              // 64*65
    float* Kt   = Qs + 64 * 65;    // 64*68 (d-major)
    float* Vs   = Kt + 64 * 68;    // 64*64
    float* Ss   = Vs + 64 * 64;    // 64*64
    float* As   = Ss + 64 * 64;    // 64*68
    float* gpow = As + 64 * 68;    // 64
    int blk = blockIdx.x;
    int bh = blk / NC, c = blk % NC;
    int b = bh / H_, h = bh % H_;
    float gamma = 1.0f - exp2f(-5.0f - (float)h);
    if (threadIdx.x < 64) gpow[threadIdx.x] = powf(gamma, (float)threadIdx.x);
    for (int i = threadIdx.x; i < 4096; i += 256) {
        int j = i >> 6, d = i & 63;
        size_t base = (size_t)(b * T_ + c * HD + j) * C5 + h * HD + d;
        Qs[j * 65 + d] = g_qkvff[base];
        Kt[d * 68 + j] = g_qkvff[base + C_];
        Vs[j * 64 + d] = g_qkvff[base + 2 * C_];
        Ss[i] = g_S[((size_t)bh * NC + c) * 4096 + i];
    }
    __syncthreads();
    for (int p = threadIdx.x; p < 1024; p += 256) {
        int i = p >> 4, j0 = (p & 15) << 2;
        float s0 = 0, s1 = 0, s2 = 0, s3 = 0;
        #pragma unroll 8
        for (int d = 0; d < 64; d++) {
            float q = Qs[i * 65 + d];
            float4 k4 = *(const float4*)&Kt[d * 68 + j0];
            s0 += q * k4.x; s1 += q * k4.y; s2 += q * k4.z; s3 += q * k4.w;
        }
        float4 r;
        r.x = (j0     <= i) ? s0 * gpow[i - j0]     : 0.f;
        r.y = (j0 + 1 <= i) ? s1 * gpow[i - j0 - 1] : 0.f;
        r.z = (j0 + 2 <= i) ? s2 * gpow[i - j0 - 2] : 0.f;
        r.w = (j0 + 3 <= i) ? s3 * gpow[i - j0 - 3] : 0.f;
        *(float4*)&As[i * 68 + j0] = r;
    }
    __syncthreads();
    for (int p = threadIdx.x; p < 1024; p += 256) {
        int i = p >> 4, e0 = (p & 15) << 2;
        float a0 = 0, a1 = 0, a2 = 0, a3 = 0;
        float c0 = 0, c1 = 0, c2 = 0, c3 = 0;
        #pragma unroll 8
        for (int jj = 0; jj < 64; jj++) {
            float av = As[i * 68 + jj];
            float qv = Qs[i * 65 + jj];
            float4 v4 = *(const float4*)&Vs[jj * 64 + e0];
            float4 s4 = *(const float4*)&Ss[jj * 64 + e0];
            a0 += av * v4.x; a1 += av * v4.y; a2 += av * v4.z; a3 += av * v4.w;
            c0 += qv * s4.x; c1 += qv * s4.y; c2 += qv * s4.z; c3 += qv * s4.w;
        }
        float gi = gpow[i];
        float y0 = (a0 + gi * c0) * 0.125f;
        float y1 = (a1 + gi * c1) * 0.125f;
        float y2 = (a2 + gi * c2) * 0.125f;
        float y3 = (a3 + gi * c3) * 0.125f;
        float sum = y0 + y1 + y2 + y3;
        float sq  = y0 * y0 + y1 * y1 + y2 * y2 + y3 * y3;
        #pragma unroll
        for (int o = 8; o >= 1; o >>= 1) {
            sum += __shfl_xor_sync(~0u, sum, o);
            sq  += __shfl_xor_sync(~0u, sq, o);
        }
        float mu  = sum * (1.0f / 64.0f);
        float var = sq * (1.0f / 64.0f) - mu * mu;
        float inv = rsqrtf(var + 1e-5f);
        int cb = h * 64 + e0;
        float4 o4;
        o4.x = (y0 - mu) * inv * gn_w[cb]     + gn_b[cb];
        o4.y = (y1 - mu) * inv * gn_w[cb + 1] + gn_b[cb + 1];
        o4.z = (y2 - mu) * inv * gn_w[cb + 2] + gn_b[cb + 2];
        o4.w = (y3 - mu) * inv * gn_w[cb + 3] + gn_b[cb + 3];
        *(float4*)&g_y[(size_t)(b * T_ + c * HD + i) * C_ + cb] = o4;
    }
}

// ---------------- launch ----------------
extern "C" void kernel_launch(void* const* d_in, const int* in_sizes, int n_in,
                              void* d_out, int out_size) {
    const float* x       = (const float*)d_in[0];
    const float* w_qkvff = (const float*)d_in[1];
    const float* w_gated = (const float*)d_in[2];
    const float* b_gated = (const float*)d_in[3];
    const float* w_proj  = (const float*)d_in[4];
    const float* b_proj  = (const float*)d_in[5];
    const float* gn_w    = (const float*)d_in[6];
    const float* gn_b    = (const float*)d_in[7];
    const float* w_ff    = (const float*)d_in[8];
    const float* rms_w   = (const float*)d_in[9];
    float* out = (float*)d_out;

    float *p_qkvff, *p_z, *p_ffout;
    __half *p_a_qkv, *p_b_qkv, *p_a_x, *p_b_gat, *p_a_prj, *p_b_prj, *p_a_ff, *p_b_ff;
    cudaGetSymbolAddress((void**)&p_qkvff, g_qkvff);
    cudaGetSymbolAddress((void**)&p_z,     g_z);
    cudaGetSymbolAddress((void**)&p_ffout, g_ffout);
    cudaGetSymbolAddress((void**)&p_a_qkv, g_a_qkv);
    cudaGetSymbolAddress((void**)&p_b_qkv, g_b_qkv);
    cudaGetSymbolAddress((void**)&p_a_x,   g_a_x);
    cudaGetSymbolAddress((void**)&p_b_gat, g_b_gat);
    cudaGetSymbolAddress((void**)&p_a_prj, g_a_prj);
    cudaGetSymbolAddress((void**)&p_b_prj, g_b_prj);
    cudaGetSymbolAddress((void**)&p_a_ff,  g_a_ff);
    cudaGetSymbolAddress((void**)&p_b_ff,  g_b_ff);

    const int SMEM = 1024 + 4 * 49152;               // 197632
    const int ATTN_SMEM = (64*65 + 64*68 + 64*64 + 64*64 + 64*68 + 64) * 4;

    // one-time infra (created on the uncaptured correctness call; reused thereafter;
    // identical GPU work is enqueued on every call)
    static cudaStream_t s1 = nullptr;
    static cudaEvent_t ev0, ev_ax, ev_qkv, ev_gate, ev_ff;
    if (s1 == nullptr) {
        cudaStreamCreateWithFlags(&s1, cudaStreamNonBlocking);
        cudaEventCreateWithFlags(&ev0,     cudaEventDisableTiming);
        cudaEventCreateWithFlags(&ev_ax,   cudaEventDisableTiming);
        cudaEventCreateWithFlags(&ev_qkv,  cudaEventDisableTiming);
        cudaEventCreateWithFlags(&ev_gate, cudaEventDisableTiming);
        cudaEventCreateWithFlags(&ev_ff,   cudaEventDisableTiming);
        cudaFuncSetAttribute(mma_gemm<0>, cudaFuncAttributeMaxDynamicSharedMemorySize, SMEM);
        cudaFuncSetAttribute(mma_gemm<1>, cudaFuncAttributeMaxDynamicSharedMemorySize, SMEM);
        cudaFuncSetAttribute(mma_gemm<2>, cudaFuncAttributeMaxDynamicSharedMemorySize, SMEM);
        cudaFuncSetAttribute(mma_gemm<3>, cudaFuncAttributeMaxDynamicSharedMemorySize, SMEM);
        cudaFuncSetAttribute(k_chunk_attn, cudaFuncAttributeMaxDynamicSharedMemorySize, ATTN_SMEM);
    }

    // ---- fork: s1 joins capture via ev0 ----
    cudaEventRecord(ev0, 0);
    cudaStreamWaitEvent(s1, ev0, 0);

    // s1: weight splits for gate / proj / ff (independent of main chain)
    k_splitv<<<(C_ * C_) / 1024, 256, 0, s1>>>((const float4*)w_gated, p_b_gat, C_);
    k_splitv<<<(C_ * C_) / 1024, 256, 0, s1>>>((const float4*)w_proj,  p_b_prj, C_);
    k_splitv<<<(C_ * 2 * C_) / 1024, 256, 0, s1>>>((const float4*)w_ff, p_b_ff, 2 * C_);

    // main: qkv weight split + RMSNorm (also emits raw-x split)
    k_splitv<<<(C5 * C_) / 1024, 256>>>((const float4*)w_qkvff, p_b_qkv, C_);
    k_rmsnorm<<<BT, 256>>>(x, rms_w);
    cudaEventRecord(ev_ax, 0);

    // s1: gate GEMM z = silu(x @ w_gated^T + b)   (needs a_x)
    cudaStreamWaitEvent(s1, ev_ax, 0);
    mma_gemm<1><<<dim3(C_ / 256, BT / 128), 256, SMEM, s1>>>(
        p_a_x, p_b_gat, 2 * C_, C_, p_z, b_gated, nullptr, nullptr, nullptr);
    cudaEventRecord(ev_gate, s1);

    // main: qkvff GEMM (q,k,v fp32; ff -> fused gelu+split)
    mma_gemm<0><<<dim3(C5 / 256, BT / 128), 256, SMEM>>>(
        p_a_qkv, p_b_qkv, 2 * C_, C5, p_qkvff, nullptr, nullptr, nullptr, p_a_ff);
    cudaEventRecord(ev_qkv, 0);

    // s1: ff GEMM ffout = gelu(ff) @ w_ff^T   (needs a_ff)
    cudaStreamWaitEvent(s1, ev_qkv, 0);
    mma_gemm<2><<<dim3(C_ / 256, BT / 128), 256, SMEM, s1>>>(
        p_a_ff, p_b_ff, 4 * C_, C_, p_ffout, nullptr, nullptr, nullptr, nullptr);
    cudaEventRecord(ev_ff, s1);

    // main: attention chain (overlaps with s1's gate + ff GEMMs)
    k_xpos<<<(T_ * 512) / 256, 256>>>();
    k_chunk_kv<<<BH * NC, 256>>>();
    k_scan<<<BH, 256>>>();
    k_chunk_attn<<<BH * NC, 256, ATTN_SMEM>>>(gn_w, gn_b);

    // join: a_prj = split(z * y_gn)
    cudaStreamWaitEvent(0, ev_gate, 0);
    k_mulsplit<<<BT, 256>>>();

    // join ff, then final proj GEMM: out = y2 @ w_proj^T + b_proj + x + ffout
    cudaStreamWaitEvent(0, ev_ff, 0);
    mma_gemm<3><<<dim3(C_ / 256, BT / 128), 256, SMEM>>>(
        p_a_prj, p_b_prj, 2 * C_, C_, out, b_proj, x, p_ffout, nullptr);
}

// round 10
// speedup vs baseline: 1.8150x; 1.1539x over previous
#include <cuda_runtime.h>
#include <cuda_fp16.h>
#include <math.h>
#include <stdint.h>

#define B_  2
#define T_  2048
#define C_  1024
#define H_  16
#define HD  64
#define BT  (B_*T_)      // 4096
#define C3  (3*C_)       // 3072
#define C5  (5*C_)       // 5120
#define NC  (T_/HD)      // 32 chunks
#define BH  (B_*H_)      // 32

// ---------------- scratch (device globals) ----------------
__device__ float g_qkv [BT*(size_t)C3];           // q,k,v fp32 (stride 3C)
__device__ float g_W [BH*(size_t)NC*HD*HD];
__device__ float g_S [BH*(size_t)NC*HD*HD];
__device__ float g_y [BT*(size_t)C_];             // GN'd attention out
__device__ float g_z [BT*(size_t)C_];             // silu(gate) fp32
__device__ float g_ffout[BT*(size_t)C_];          // ff GEMM result
// 2-term fp16 operands (A = [hi|lo], B = [b|b], Kp = 2K) for the qkv/ffpart GEMMs
__device__ __half g_a_qkv [BT*(size_t)2*C_];
__device__ __half g_b_qkv [C5*(size_t)2*C_];
// single-term fp16 operands for gate / proj / ff
__device__ __half g_a_x1  [BT*(size_t)C_];
__device__ __half g_b_gat1[C_*(size_t)C_];
__device__ __half g_a_prj1[BT*(size_t)C_];
__device__ __half g_b_prj1[C_*(size_t)C_];
__device__ __half g_a_ff1 [BT*(size_t)2*C_];      // gelu(ff) fp16
__device__ __half g_b_ff1 [C_*(size_t)2*C_];

// ---------------- PTX helpers ----------------
__device__ __forceinline__ uint32_t smem_u32(const void* p) {
    uint32_t a;
    asm("{ .reg .u64 t; cvta.to.shared.u64 t, %1; cvt.u32.u64 %0, t; }" : "=r"(a) : "l"(p));
    return a;
}
#define CPA(dst, src)  asm volatile("cp.async.cg.shared.global [%0], [%1], 16;" :: "r"(dst), "l"(src) : "memory")
#define CPC()          asm volatile("cp.async.commit_group;" ::: "memory")
#define CPW(n)         asm volatile("cp.async.wait_group %0;" :: "n"(n) : "memory")
#define SWZ(o) ((o) ^ (((o) >> 3) & 0x70))

#define LDM_X4(r0, r1, r2, r3, a) \
    asm volatile("ldmatrix.sync.aligned.m8n8.x4.shared.b16 {%0,%1,%2,%3}, [%4];" \
        : "=r"(r0), "=r"(r1), "=r"(r2), "=r"(r3) : "r"(a))

#define MMA_F16(d, a, b0, b1) \
    asm volatile("mma.sync.aligned.m16n8k16.row.col.f32.f16.f16.f32 " \
        "{%0,%1,%2,%3}, {%4,%5,%6,%7}, {%8,%9}, {%0,%1,%2,%3};" \
        : "+f"((d)[0]), "+f"((d)[1]), "+f"((d)[2]), "+f"((d)[3]) \
        : "r"((a)[0]), "r"((a)[1]), "r"((a)[2]), "r"((a)[3]), "r"(b0), "r"(b1))

// ---------------- warp-MMA fp16 NT GEMM (proven R4 mainloop) ----------------
// C[M, N] = A[M, Kp] * B[N, Kp]^T
// block tile 128x256, BK=64, S=4 cp.async stages, 8 warps (2m x 4n), warp 64x64
// EPI 1: silu(v+bias[n]) -> fp32 Cout
// EPI 2: plain -> Cout
// EPI 3: v + bias[n] + aux0[o] + aux1[o] -> Cout
// EPI 4: gelu(v) -> fp16 osplit (row stride N)
template<int EPI>
__global__ void __launch_bounds__(256, 1) mma_gemm(
    const __half* __restrict__ A, const __half* __restrict__ Bm,
    int Kp, int N, float* __restrict__ Cout,
    const float* __restrict__ bias, const float* __restrict__ aux0,
    const float* __restrict__ aux1, __half* __restrict__ osplit)
{
    extern __shared__ __align__(1024) char smem_raw[];
    const int S = 4;
    const uint32_t STAGE = 49152;   // A 16KB + B 32KB
    uint32_t sbase = (smem_u32(smem_raw) + 1023) & ~1023u;

    int tid = threadIdx.x;
    int wid = tid >> 5, lane = tid & 31;
    int warp_m = wid & 1, warp_n = wid >> 1;
    int bm = blockIdx.y << 7, bn = blockIdx.x << 8;

    const int nk = Kp >> 6;

    auto load_stage = [&](int s, int k) {
        uint32_t a_s = sbase + s * STAGE;
        uint32_t b_s = a_s + 16384u;
        const __half* Ag = A + (size_t)bm * Kp + (size_t)k * 64;
        const __half* Bg = Bm + (size_t)bn * Kp + (size_t)k * 64;
        #pragma unroll
        for (int q = 0; q < 4; q++) {
            int i = tid + (q << 8);
            int r = i >> 3, c = i & 7;
            uint32_t off = SWZ(r * 128 + c * 16);
            CPA(a_s + off, (const char*)(Ag + (size_t)r * Kp + c * 8));
        }
        #pragma unroll
        for (int q = 0; q < 8; q++) {
            int i = tid + (q << 8);
            int r = i >> 3, c = i & 7;
            uint32_t off = SWZ(r * 128 + c * 16);
            CPA(b_s + off, (const char*)(Bg + (size_t)r * Kp + c * 8));
        }
    };

    float acc[4][8][4];
    #pragma unroll
    for (int mt = 0; mt < 4; mt++)
        #pragma unroll
        for (int nt = 0; nt < 8; nt++)
            #pragma unroll
            for (int u = 0; u < 4; u++) acc[mt][nt][u] = 0.f;

    int j = lane >> 3;
    int lrow = lane & 7;
    int a_row_off = ((j & 1) << 3) + lrow;
    int a_byte_off = (j >> 1) << 4;
    int b_row_off = ((j >> 1) << 3) + lrow;
    int b_byte_off = (j & 1) << 4;

    #pragma unroll
    for (int p = 0; p < S - 1; p++) { load_stage(p, p); CPC(); }

    for (int k = 0; k < nk; k++) {
        CPW(S - 2);
        __syncthreads();
        if (k + S - 1 < nk) load_stage((k + S - 1) % S, k + S - 1);
        CPC();

        uint32_t a_s = sbase + (uint32_t)(k % S) * STAGE;
        uint32_t b_s = a_s + 16384u;
        #pragma unroll
        for (int ks = 0; ks < 4; ks++) {
            uint32_t af[4][4], bf[4][4];
            #pragma unroll
            for (int mt = 0; mt < 4; mt++) {
                int row = warp_m * 64 + mt * 16 + a_row_off;
                uint32_t ad = a_s + SWZ(row * 128 + ks * 32 + a_byte_off);
                LDM_X4(af[mt][0], af[mt][1], af[mt][2], af[mt][3], ad);
            }
            #pragma unroll
            for (int ng = 0; ng < 4; ng++) {
                int row = warp_n * 64 + ng * 16 + b_row_off;
                uint32_t bd = b_s + SWZ(row * 128 + ks * 32 + b_byte_off);
                LDM_X4(bf[ng][0], bf[ng][1], bf[ng][2], bf[ng][3], bd);
            }
            #pragma unroll
            for (int mt = 0; mt < 4; mt++)
                #pragma unroll
                for (int nt = 0; nt < 8; nt++) {
                    uint32_t b0 = bf[nt >> 1][(nt & 1) ? 2 : 0];
                    uint32_t b1 = bf[nt >> 1][(nt & 1) ? 3 : 1];
                    MMA_F16(acc[mt][nt], af[mt], b0, b1);
                }
        }
    }

    // ---------------- epilogue ----------------
    int gid = lane >> 2;
    int tig = lane & 3;
    #pragma unroll
    for (int mt = 0; mt < 4; mt++) {
        int m0 = bm + warp_m * 64 + mt * 16 + gid;
        #pragma unroll
        for (int nt = 0; nt < 8; nt++) {
            int n0 = bn + warp_n * 64 + nt * 8 + tig * 2;
            float* ac = acc[mt][nt];
            #pragma unroll
            for (int half_ = 0; half_ < 2; half_++) {
                int m = m0 + half_ * 8;
                float v0 = ac[half_ * 2], v1 = ac[half_ * 2 + 1];
                if (EPI == 1) {
                    float z0 = v0 + bias[n0], z1 = v1 + bias[n0 + 1];
                    float2 w;
                    w.x = z0 / (1.f + expf(-z0));
                    w.y = z1 / (1.f + expf(-z1));
                    *(float2*)&Cout[(size_t)m * N + n0] = w;
                } else if (EPI == 2) {
                    float2 w; w.x = v0; w.y = v1;
                    *(float2*)&Cout[(size_t)m * N + n0] = w;
                } else if (EPI == 3) {
                    size_t o = (size_t)m * N + n0;
                    float2 w;
                    w.x = v0 + bias[n0]     + aux0[o]     + aux1[o];
                    w.y = v1 + bias[n0 + 1] + aux0[o + 1] + aux1[o + 1];
                    *(float2*)&Cout[o] = w;
                } else {  // EPI 4: gelu -> fp16
                    float g0 = 0.5f * v0 * (1.0f + erff(v0 * 0.70710678118654752f));
                    float g1 = 0.5f * v1 * (1.0f + erff(v1 * 0.70710678118654752f));
                    *(__half2*)(osplit + (size_t)m * N + n0) =
                        __halves2half2(__float2half(g0), __float2half(g1));
                }
            }
        }
    }
}

// ---------------- B split (2-term GEMMs): fp32 -> [b|b] fp16 duplicated ----------------
__global__ void k_splitv(const float4* __restrict__ in, __half* __restrict__ out, int K) {
    int idx = blockIdx.x * 256 + threadIdx.x;      // one float4 = 4 elems
    int k4 = K >> 2;
    int r = idx / k4, k = (idx - r * k4) << 2;
    float4 v = in[idx];
    uint2 hp;
    ((__half2*)&hp)[0] = __halves2half2(__float2half(v.x), __float2half(v.y));
    ((__half2*)&hp)[1] = __halves2half2(__float2half(v.z), __float2half(v.w));
    size_t b = (size_t)r * 2 * K + k;
    *(uint2*)(out + b)     = hp;
    *(uint2*)(out + b + K) = hp;
}

// ---------------- flat fp32 -> fp16 convert (single-term operands) ----------------
__global__ void k_half1(const float4* __restrict__ in, __half* __restrict__ out) {
    int idx = blockIdx.x * 256 + threadIdx.x;      // one float4
    float4 v = in[idx];
    uint2 hp;
    ((__half2*)&hp)[0] = __halves2half2(__float2half(v.x), __float2half(v.y));
    ((__half2*)&hp)[1] = __halves2half2(__float2half(v.z), __float2half(v.w));
    *(uint2*)(out + (size_t)idx * 4) = hp;
}

// ---------------- K1: RMSNorm -> a_qkv [hi|lo], plus raw-x single fp16 ----------------
__global__ void k_rmsnorm(const float* __restrict__ x, const float* __restrict__ rms_w) {
    int n = blockIdx.x;
    const float* xr = x + (size_t)n * C_;
    __shared__ float red[256];
    float s = 0.f;
    for (int c = threadIdx.x; c < C_; c += 256) { float v = xr[c]; s += v * v; }
    red[threadIdx.x] = s; __syncthreads();
    for (int o = 128; o > 0; o >>= 1) {
        if (threadIdx.x < o) red[threadIdx.x] += red[threadIdx.x + o];
        __syncthreads();
    }
    float nrm = sqrtf(red[0]) * 0.03125f;
    float inv = 1.0f / fmaxf(nrm, 1e-8f);
    size_t ob = (size_t)n * 2048;
    for (int c = threadIdx.x; c < C_; c += 256) {
        float xv = xr[c];
        float v = xv * inv * rms_w[c];
        __half hi = __float2half(v);
        __half lo = __float2half(v - __half2float(hi));
        g_a_qkv[ob + c] = hi;
        g_a_qkv[ob + 1024 + c] = lo;
        g_a_x1[(size_t)n * C_ + c] = __float2half(xv);
    }
}

// ---------------- mulsplit: a_prj1 = fp16(z * y_gn) ----------------
__global__ void k_mulsplit() {
    int idx = blockIdx.x * 256 + threadIdx.x;      // one float4
    size_t o = (size_t)idx * 4;
    float4 zv = *(const float4*)&g_z[o];
    float4 yv = *(const float4*)&g_y[o];
    uint2 hp;
    ((__half2*)&hp)[0] = __halves2half2(__float2half(zv.x * yv.x), __float2half(zv.y * yv.y));
    ((__half2*)&hp)[1] = __halves2half2(__float2half(zv.z * yv.z), __float2half(zv.w * yv.w));
    *(uint2*)(g_a_prj1 + o) = hp;
}

// ---------------- K3: xPos rotary (one thread serves both batches) ----------------
__global__ void k_xpos() {
    int idx = blockIdx.x * 256 + threadIdx.x;        // over T_*512
    int t = idx >> 9;
    int j = idx & 511;
    float invf  = powf(10000.0f, -(float)j / 512.0f);
    float theta = (float)t * invf;
    float sn, cs;
    sincosf(theta, &sn, &cs);
    float svec  = (2.0f * (float)j + 0.4f * 1024.0f) / (1.4f * 1024.0f);
    float pw    = ((float)t - 1024.0f) * (1.0f / 512.0f);
    float scale = powf(svec, pw);
    float cq = cs * scale, sq = sn * scale;
    float ck = cs / scale, sk = sn / scale;
    #pragma unroll
    for (int b = 0; b < 2; b++) {
        float* q = g_qkv + (size_t)(b * T_ + t) * C3 + 2 * j;
        float* k = q + C_;
        float q0 = q[0], q1 = q[1];
        q[0] = q0 * cq - q1 * sq;  q[1] = q1 * cq + q0 * sq;
        float k0 = k[0], k1 = k[1];
        k[0] = k0 * ck - k1 * sk;  k[1] = k1 * ck + k0 * sk;
    }
}

// ---------------- K4: chunk KV summaries ----------------
__global__ void k_chunk_kv() {
    int blk = blockIdx.x;
    int bh = blk / NC, c = blk % NC;
    int b = bh / H_, h = bh % H_;
    float gamma = 1.0f - exp2f(-5.0f - (float)h);
    __shared__ float Ks[64 * 65], Vs[64 * 64], dec[64];
    if (threadIdx.x < 64) dec[threadIdx.x] = powf(gamma, (float)(HD - threadIdx.x));
    __syncthreads();
    for (int i = threadIdx.x; i < HD * HD; i += 256) {
        int j = i >> 6, d = i & 63;
        size_t base = (size_t)(b * T_ + c * HD + j) * C3 + h * HD + d;
        Ks[j * 65 + d] = g_qkv[base + C_] * dec[j];
        Vs[j * 64 + d] = g_qkv[base + 2 * C_];
    }
    __syncthreads();
    float* Wout = g_W + ((size_t)bh * NC + c) * HD * HD;
    for (int p = threadIdx.x; p < 1024; p += 256) {
        int d = p >> 4, e0 = (p & 15) << 2;
        float s0 = 0, s1 = 0, s2 = 0, s3 = 0;
        #pragma unroll 8
        for (int j = 0; j < 64; j++) {
            float kd = Ks[j * 65 + d];
            float4 v4 = *(const float4*)&Vs[j * 64 + e0];
            s0 += kd * v4.x; s1 += kd * v4.y; s2 += kd * v4.z; s3 += kd * v4.w;
        }
        float4 r; r.x = s0; r.y = s1; r.z = s2; r.w = s3;
        *(float4*)&Wout[d * 64 + e0] = r;
    }
}

// ---------------- K5: state scan ----------------
__global__ void k_scan() {
    int bh = blockIdx.x;
    int h = bh % H_;
    float gamma = 1.0f - exp2f(-5.0f - (float)h);
    float g64 = powf(gamma, 64.0f);
    float st[16];
    #pragma unroll
    for (int r = 0; r < 16; r++) st[r] = 0.f;
    size_t base0 = (size_t)bh * NC * 4096;
    for (int c = 0; c < NC; c++) {
        size_t base = base0 + (size_t)c * 4096;
        #pragma unroll
        for (int r = 0; r < 16; r++) {
            int i = threadIdx.x + r * 256;
            g_S[base + i] = st[r];
            st[r] = st[r] * g64 + g_W[base + i];
        }
    }
}

// ---------------- K6: per-chunk attention + fused GroupNorm ----------------
__global__ void k_chunk_attn(const float* __restrict__ gn_w, const float* __restrict__ gn_b) {
    extern __shared__ float sm[];
    float* Qs   = sm;              // 64*65
    float* Kt   = Qs + 64 * 65;    // 64*68 (d-major)
    float* Vs   = Kt + 64 * 68;    // 64*64
    float* Ss   = Vs + 64 * 64;    // 64*64
    float* As   = Ss + 64 * 64;    // 64*68
    float* gpow = As + 64 * 68;    // 64
    int blk = blockIdx.x;
    int bh = blk / NC, c = blk % NC;
    int b = bh / H_, h = bh % H_;
    float gamma = 1.0f - exp2f(-5.0f - (float)h);
    if (threadIdx.x < 64) gpow[threadIdx.x] = powf(gamma, (float)threadIdx.x);
    for (int i = threadIdx.x; i < 4096; i += 256) {
        int j = i >> 6, d = i & 63;
        size_t base = (size_t)(b * T_ + c * HD + j) * C3 + h * HD + d;
        Qs[j * 65 + d] = g_qkv[base];
        Kt[d * 68 + j] = g_qkv[base + C_];
        Vs[j * 64 + d] = g_qkv[base + 2 * C_];
        Ss[i] = g_S[((size_t)bh * NC + c) * 4096 + i];
    }
    __syncthreads();
    for (int p = threadIdx.x; p < 1024; p += 256) {
        int i = p >> 4, j0 = (p & 15) << 2;
        float s0 = 0, s1 = 0, s2 = 0, s3 = 0;
        #pragma unroll 8
        for (int d = 0; d < 64; d++) {
            float q = Qs[i * 65 + d];
            float4 k4 = *(const float4*)&Kt[d * 68 + j0];
            s0 += q * k4.x; s1 += q * k4.y; s2 += q * k4.z; s3 += q * k4.w;
        }
        float4 r;
        r.x = (j0     <= i) ? s0 * gpow[i - j0]     : 0.f;
        r.y = (j0 + 1 <= i) ? s1 * gpow[i - j0 - 1] : 0.f;
        r.z = (j0 + 2 <= i) ? s2 * gpow[i - j0 - 2] : 0.f;
        r.w = (j0 + 3 <= i) ? s3 * gpow[i - j0 - 3] : 0.f;
        *(float4*)&As[i * 68 + j0] = r;
    }
    __syncthreads();
    for (int p = threadIdx.x; p < 1024; p += 256) {
        int i = p >> 4, e0 = (p & 15) << 2;
        float a0 = 0, a1 = 0, a2 = 0, a3 = 0;
        float c0 = 0, c1 = 0, c2 = 0, c3 = 0;
        #pragma unroll 8
        for (int jj = 0; jj < 64; jj++) {
            float av = As[i * 68 + jj];
            float qv = Qs[i * 65 + jj];
            float4 v4 = *(const float4*)&Vs[jj * 64 + e0];
            float4 s4 = *(const float4*)&Ss[jj * 64 + e0];
            a0 += av * v4.x; a1 += av * v4.y; a2 += av * v4.z; a3 += av * v4.w;
            c0 += qv * s4.x; c1 += qv * s4.y; c2 += qv * s4.z; c3 += qv * s4.w;
        }
        float gi = gpow[i];
        float y0 = (a0 + gi * c0) * 0.125f;
        float y1 = (a1 + gi * c1) * 0.125f;
        float y2 = (a2 + gi * c2) * 0.125f;
        float y3 = (a3 + gi * c3) * 0.125f;
        float sum = y0 + y1 + y2 + y3;
        float sq  = y0 * y0 + y1 * y1 + y2 * y2 + y3 * y3;
        #pragma unroll
        for (int o = 8; o >= 1; o >>= 1) {
            sum += __shfl_xor_sync(~0u, sum, o);
            sq  += __shfl_xor_sync(~0u, sq, o);
        }
        float mu  = sum * (1.0f / 64.0f);
        float var = sq * (1.0f / 64.0f) - mu * mu;
        float inv = rsqrtf(var + 1e-5f);
        int cb = h * 64 + e0;
        float4 o4;
        o4.x = (y0 - mu) * inv * gn_w[cb]     + gn_b[cb];
        o4.y = (y1 - mu) * inv * gn_w[cb + 1] + gn_b[cb + 1];
        o4.z = (y2 - mu) * inv * gn_w[cb + 2] + gn_b[cb + 2];
        o4.w = (y3 - mu) * inv * gn_w[cb + 3] + gn_b[cb + 3];
        *(float4*)&g_y[(size_t)(b * T_ + c * HD + i) * C_ + cb] = o4;
    }
}

// ---------------- launch ----------------
extern "C" void kernel_launch(void* const* d_in, const int* in_sizes, int n_in,
                              void* d_out, int out_size) {
    const float* x       = (const float*)d_in[0];
    const float* w_qkvff = (const float*)d_in[1];
    const float* w_gated = (const float*)d_in[2];
    const float* b_gated = (const float*)d_in[3];
    const float* w_proj  = (const float*)d_in[4];
    const float* b_proj  = (const float*)d_in[5];
    const float* gn_w    = (const float*)d_in[6];
    const float* gn_b    = (const float*)d_in[7];
    const float* w_ff    = (const float*)d_in[8];
    const float* rms_w   = (const float*)d_in[9];
    float* out = (float*)d_out;

    float *p_qkv, *p_z, *p_ffout;
    __half *p_a_qkv, *p_b_qkv, *p_a_x1, *p_b_gat1, *p_a_prj1, *p_b_prj1, *p_a_ff1, *p_b_ff1;
    cudaGetSymbolAddress((void**)&p_qkv,   g_qkv);
    cudaGetSymbolAddress((void**)&p_z,     g_z);
    cudaGetSymbolAddress((void**)&p_ffout, g_ffout);
    cudaGetSymbolAddress((void**)&p_a_qkv, g_a_qkv);
    cudaGetSymbolAddress((void**)&p_b_qkv, g_b_qkv);
    cudaGetSymbolAddress((void**)&p_a_x1,  g_a_x1);
    cudaGetSymbolAddress((void**)&p_b_gat1, g_b_gat1);
    cudaGetSymbolAddress((void**)&p_a_prj1, g_a_prj1);
    cudaGetSymbolAddress((void**)&p_b_prj1, g_b_prj1);
    cudaGetSymbolAddress((void**)&p_a_ff1, g_a_ff1);
    cudaGetSymbolAddress((void**)&p_b_ff1, g_b_ff1);

    const int SMEM = 1024 + 4 * 49152;               // 197632
    const int ATTN_SMEM = (64*65 + 64*68 + 64*64 + 64*64 + 64*68 + 64) * 4;

    // one-time infra (created on the uncaptured correctness call; reused thereafter;
    // identical GPU work is enqueued on every call)
    static cudaStream_t s1 = nullptr;
    static cudaEvent_t ev0, ev_ax, ev_gate, ev_ff;
    if (s1 == nullptr) {
        cudaStreamCreateWithFlags(&s1, cudaStreamNonBlocking);
        cudaEventCreateWithFlags(&ev0,     cudaEventDisableTiming);
        cudaEventCreateWithFlags(&ev_ax,   cudaEventDisableTiming);
        cudaEventCreateWithFlags(&ev_gate, cudaEventDisableTiming);
        cudaEventCreateWithFlags(&ev_ff,   cudaEventDisableTiming);
        cudaFuncSetAttribute(mma_gemm<1>, cudaFuncAttributeMaxDynamicSharedMemorySize, SMEM);
        cudaFuncSetAttribute(mma_gemm<2>, cudaFuncAttributeMaxDynamicSharedMemorySize, SMEM);
        cudaFuncSetAttribute(mma_gemm<3>, cudaFuncAttributeMaxDynamicSharedMemorySize, SMEM);
        cudaFuncSetAttribute(mma_gemm<4>, cudaFuncAttributeMaxDynamicSharedMemorySize, SMEM);
        cudaFuncSetAttribute(k_chunk_attn, cudaFuncAttributeMaxDynamicSharedMemorySize, ATTN_SMEM);
    }

    // ---- fork: s1 joins capture via ev0 ----
    cudaEventRecord(ev0, 0);
    cudaStreamWaitEvent(s1, ev0, 0);

    // s1: single-fp16 weight converts for gate / proj / ff
    k_half1<<<(C_ * C_) / 1024, 256, 0, s1>>>((const float4*)w_gated, p_b_gat1);
    k_half1<<<(C_ * C_) / 1024, 256, 0, s1>>>((const float4*)w_proj,  p_b_prj1);
    k_half1<<<(C_ * 2 * C_) / 1024, 256, 0, s1>>>((const float4*)w_ff, p_b_ff1);

    // main: qkvff weight split (dup-B) + RMSNorm (a_qkv 2-term, a_x1 single)
    k_splitv<<<(C5 * C_) / 1024, 256>>>((const float4*)w_qkvff, p_b_qkv, C_);
    k_rmsnorm<<<BT, 256>>>(x, rms_w);
    cudaEventRecord(ev_ax, 0);

    // s1: gate GEMM z = silu(x @ w_gated^T + b)  (single fp16, Kp=1024)
    cudaStreamWaitEvent(s1, ev_ax, 0);
    mma_gemm<1><<<dim3(C_ / 256, BT / 128), 256, SMEM, s1>>>(
        p_a_x1, p_b_gat1, C_, C_, p_z, b_gated, nullptr, nullptr, nullptr);
    cudaEventRecord(ev_gate, s1);

    // s1: ffpart GEMM (2-term, Kp=2048, B rows 3072..5119 of b_qkv) -> gelu fp16 a_ff1
    mma_gemm<4><<<dim3(2 * C_ / 256, BT / 128), 256, SMEM, s1>>>(
        p_a_qkv, p_b_qkv + (size_t)C3 * 2 * C_, 2 * C_, 2 * C_,
        nullptr, nullptr, nullptr, nullptr, p_a_ff1);

    // s1: ff GEMM ffout = gelu(ff) @ w_ff^T  (single fp16, Kp=2048)
    mma_gemm<2><<<dim3(C_ / 256, BT / 128), 256, SMEM, s1>>>(
        p_a_ff1, p_b_ff1, 2 * C_, C_, p_ffout, nullptr, nullptr, nullptr, nullptr);
    cudaEventRecord(ev_ff, s1);

    // main: qkv GEMM (2-term, Kp=2048, N=3072) -> g_qkv fp32
    mma_gemm<2><<<dim3(C3 / 256, BT / 128), 256, SMEM>>>(
        p_a_qkv, p_b_qkv, 2 * C_, C3, p_qkv, nullptr, nullptr, nullptr, nullptr);

    // main: attention chain (overlaps with s1)
    k_xpos<<<(T_ * 512) / 256, 256>>>();
    k_chunk_kv<<<BH * NC, 256>>>();
    k_scan<<<BH, 256>>>();
    k_chunk_attn<<<BH * NC, 256, ATTN_SMEM>>>(gn_w, gn_b);

    // join: a_prj1 = fp16(z * y_gn)
    cudaStreamWaitEvent(0, ev_gate, 0);
    k_mulsplit<<<(BT * C_) / 1024, 256>>>();

    // join ff, then final proj GEMM: out = y2 @ w_proj^T + b_proj + x + ffout
    cudaStreamWaitEvent(0, ev_ff, 0);
    mma_gemm<3><<<dim3(C_ / 256, BT / 128), 256, SMEM>>>(
        p_a_prj1, p_b_prj1, C_, C_, out, b_proj, x, p_ffout, nullptr);
}

// round 11
// speedup vs baseline: 2.0361x; 1.1218x over previous
#include <cuda_runtime.h>
#include <cuda_fp16.h>
#include <math.h>
#include <stdint.h>

#define B_  2
#define T_  2048
#define C_  1024
#define H_  16
#define HD  64
#define BT  (B_*T_)      // 4096
#define C3  (3*C_)       // 3072
#define C5  (5*C_)       // 5120
#define NC  (T_/HD)      // 32 chunks
#define BH  (B_*H_)      // 32

// ---------------- scratch (device globals) ----------------
__device__ float g_qkv [BT*(size_t)C3];           // q,k,v fp32 (stride 3C), rotary applied
__device__ float g_W [BH*(size_t)NC*HD*HD];
__device__ float g_S [BH*(size_t)NC*HD*HD];
__device__ float g_y [BT*(size_t)C_];             // GN'd attention out
__device__ float g_z [BT*(size_t)C_];             // silu(gate) fp32
__device__ float g_ffout[BT*(size_t)C_];          // ff GEMM result
__device__ float4 g_rot [T_*(size_t)512];         // (cq,sq,ck,sk) per (t,j)
// single fp16 operands
__device__ __half g_a_q1  [BT*(size_t)C_];        // rms-normed x
__device__ __half g_b_qkv1[C5*(size_t)C_];
__device__ __half g_a_x1  [BT*(size_t)C_];        // raw x
__device__ __half g_b_gat1[C_*(size_t)C_];
__device__ __half g_a_prj1[BT*(size_t)C_];
__device__ __half g_b_prj1[C_*(size_t)C_];
__device__ __half g_a_ff1 [BT*(size_t)2*C_];      // gelu(ff) fp16
__device__ __half g_b_ff1 [C_*(size_t)2*C_];

// ---------------- PTX helpers ----------------
__device__ __forceinline__ uint32_t smem_u32(const void* p) {
    uint32_t a;
    asm("{ .reg .u64 t; cvta.to.shared.u64 t, %1; cvt.u32.u64 %0, t; }" : "=r"(a) : "l"(p));
    return a;
}
#define CPA(dst, src)  asm volatile("cp.async.cg.shared.global [%0], [%1], 16;" :: "r"(dst), "l"(src) : "memory")
#define CPC()          asm volatile("cp.async.commit_group;" ::: "memory")
#define CPW(n)         asm volatile("cp.async.wait_group %0;" :: "n"(n) : "memory")
#define SWZ(o) ((o) ^ (((o) >> 3) & 0x70))

#define LDM_X4(r0, r1, r2, r3, a) \
    asm volatile("ldmatrix.sync.aligned.m8n8.x4.shared.b16 {%0,%1,%2,%3}, [%4];" \
        : "=r"(r0), "=r"(r1), "=r"(r2), "=r"(r3) : "r"(a))

#define MMA_F16(d, a, b0, b1) \
    asm volatile("mma.sync.aligned.m16n8k16.row.col.f32.f16.f16.f32 " \
        "{%0,%1,%2,%3}, {%4,%5,%6,%7}, {%8,%9}, {%0,%1,%2,%3};" \
        : "+f"((d)[0]), "+f"((d)[1]), "+f"((d)[2]), "+f"((d)[3]) \
        : "r"((a)[0]), "r"((a)[1]), "r"((a)[2]), "r"((a)[3]), "r"(b0), "r"(b1))

// ---------------- warp-MMA fp16 NT GEMM (proven R4 mainloop) ----------------
// C[M, N] = A[M, Kp] * B[N, Kp]^T
// block tile 128x256, BK=64, S=4 cp.async stages, 8 warps (2m x 4n), warp 64x64
// EPI 1: silu(v+bias[n]) -> fp32 Cout
// EPI 2: plain -> Cout
// EPI 3: v + bias[n] + aux0[o] + aux1[o] -> Cout
// EPI 4: gelu(v) -> fp16 osplit (row stride N)
// EPI 5: qkv with fused xPos rotary (n<2048 rotate via aux0 table; v pass) -> fp32 Cout
template<int EPI>
__global__ void __launch_bounds__(256, 1) mma_gemm(
    const __half* __restrict__ A, const __half* __restrict__ Bm,
    int Kp, int N, float* __restrict__ Cout,
    const float* __restrict__ bias, const float* __restrict__ aux0,
    const float* __restrict__ aux1, __half* __restrict__ osplit)
{
    extern __shared__ __align__(1024) char smem_raw[];
    const int S = 4;
    const uint32_t STAGE = 49152;   // A 16KB + B 32KB
    uint32_t sbase = (smem_u32(smem_raw) + 1023) & ~1023u;

    int tid = threadIdx.x;
    int wid = tid >> 5, lane = tid & 31;
    int warp_m = wid & 1, warp_n = wid >> 1;
    int bm = blockIdx.y << 7, bn = blockIdx.x << 8;

    const int nk = Kp >> 6;

    auto load_stage = [&](int s, int k) {
        uint32_t a_s = sbase + s * STAGE;
        uint32_t b_s = a_s + 16384u;
        const __half* Ag = A + (size_t)bm * Kp + (size_t)k * 64;
        const __half* Bg = Bm + (size_t)bn * Kp + (size_t)k * 64;
        #pragma unroll
        for (int q = 0; q < 4; q++) {
            int i = tid + (q << 8);
            int r = i >> 3, c = i & 7;
            uint32_t off = SWZ(r * 128 + c * 16);
            CPA(a_s + off, (const char*)(Ag + (size_t)r * Kp + c * 8));
        }
        #pragma unroll
        for (int q = 0; q < 8; q++) {
            int i = tid + (q << 8);
            int r = i >> 3, c = i & 7;
            uint32_t off = SWZ(r * 128 + c * 16);
            CPA(b_s + off, (const char*)(Bg + (size_t)r * Kp + c * 8));
        }
    };

    float acc[4][8][4];
    #pragma unroll
    for (int mt = 0; mt < 4; mt++)
        #pragma unroll
        for (int nt = 0; nt < 8; nt++)
            #pragma unroll
            for (int u = 0; u < 4; u++) acc[mt][nt][u] = 0.f;

    int j = lane >> 3;
    int lrow = lane & 7;
    int a_row_off = ((j & 1) << 3) + lrow;
    int a_byte_off = (j >> 1) << 4;
    int b_row_off = ((j >> 1) << 3) + lrow;
    int b_byte_off = (j & 1) << 4;

    #pragma unroll
    for (int p = 0; p < S - 1; p++) { load_stage(p, p); CPC(); }

    for (int k = 0; k < nk; k++) {
        CPW(S - 2);
        __syncthreads();
        if (k + S - 1 < nk) load_stage((k + S - 1) % S, k + S - 1);
        CPC();

        uint32_t a_s = sbase + (uint32_t)(k % S) * STAGE;
        uint32_t b_s = a_s + 16384u;
        #pragma unroll
        for (int ks = 0; ks < 4; ks++) {
            uint32_t af[4][4], bf[4][4];
            #pragma unroll
            for (int mt = 0; mt < 4; mt++) {
                int row = warp_m * 64 + mt * 16 + a_row_off;
                uint32_t ad = a_s + SWZ(row * 128 + ks * 32 + a_byte_off);
                LDM_X4(af[mt][0], af[mt][1], af[mt][2], af[mt][3], ad);
            }
            #pragma unroll
            for (int ng = 0; ng < 4; ng++) {
                int row = warp_n * 64 + ng * 16 + b_row_off;
                uint32_t bd = b_s + SWZ(row * 128 + ks * 32 + b_byte_off);
                LDM_X4(bf[ng][0], bf[ng][1], bf[ng][2], bf[ng][3], bd);
            }
            #pragma unroll
            for (int mt = 0; mt < 4; mt++)
                #pragma unroll
                for (int nt = 0; nt < 8; nt++) {
                    uint32_t b0 = bf[nt >> 1][(nt & 1) ? 2 : 0];
                    uint32_t b1 = bf[nt >> 1][(nt & 1) ? 3 : 1];
                    MMA_F16(acc[mt][nt], af[mt], b0, b1);
                }
        }
    }

    // ---------------- epilogue ----------------
    int gid = lane >> 2;
    int tig = lane & 3;
    #pragma unroll
    for (int mt = 0; mt < 4; mt++) {
        int m0 = bm + warp_m * 64 + mt * 16 + gid;
        #pragma unroll
        for (int nt = 0; nt < 8; nt++) {
            int n0 = bn + warp_n * 64 + nt * 8 + tig * 2;
            float* ac = acc[mt][nt];
            #pragma unroll
            for (int half_ = 0; half_ < 2; half_++) {
                int m = m0 + half_ * 8;
                float v0 = ac[half_ * 2], v1 = ac[half_ * 2 + 1];
                if (EPI == 1) {
                    float z0 = v0 + bias[n0], z1 = v1 + bias[n0 + 1];
                    float2 w;
                    w.x = z0 / (1.f + expf(-z0));
                    w.y = z1 / (1.f + expf(-z1));
                    *(float2*)&Cout[(size_t)m * N + n0] = w;
                } else if (EPI == 2) {
                    float2 w; w.x = v0; w.y = v1;
                    *(float2*)&Cout[(size_t)m * N + n0] = w;
                } else if (EPI == 3) {
                    size_t o = (size_t)m * N + n0;
                    float2 w;
                    w.x = v0 + bias[n0]     + aux0[o]     + aux1[o];
                    w.y = v1 + bias[n0 + 1] + aux0[o + 1] + aux1[o + 1];
                    *(float2*)&Cout[o] = w;
                } else if (EPI == 4) {  // gelu -> fp16
                    float g0 = 0.5f * v0 * (1.0f + erff(v0 * 0.70710678118654752f));
                    float g1 = 0.5f * v1 * (1.0f + erff(v1 * 0.70710678118654752f));
                    *(__half2*)(osplit + (size_t)m * N + n0) =
                        __halves2half2(__float2half(g0), __float2half(g1));
                } else {  // EPI 5: fused xPos rotary on q,k
                    float2 w;
                    if (n0 < 2048) {
                        const float4* rot = (const float4*)aux0;
                        float4 rt = rot[((size_t)(m & (T_ - 1)) << 9) + ((n0 & 1023) >> 1)];
                        float cc = (n0 < 1024) ? rt.x : rt.z;
                        float ss = (n0 < 1024) ? rt.y : rt.w;
                        w.x = v0 * cc - v1 * ss;
                        w.y = v1 * cc + v0 * ss;
                    } else {
                        w.x = v0; w.y = v1;
                    }
                    *(float2*)&Cout[(size_t)m * N + n0] = w;
                }
            }
        }
    }
}

// ---------------- flat fp32 -> fp16 convert ----------------
__global__ void k_half1(const float4* __restrict__ in, __half* __restrict__ out) {
    int idx = blockIdx.x * 256 + threadIdx.x;      // one float4
    float4 v = in[idx];
    uint2 hp;
    ((__half2*)&hp)[0] = __halves2half2(__float2half(v.x), __float2half(v.y));
    ((__half2*)&hp)[1] = __halves2half2(__float2half(v.z), __float2half(v.w));
    *(uint2*)(out + (size_t)idx * 4) = hp;
}

// ---------------- rotary table: (cq,sq,ck,sk) per (t,j) ----------------
__global__ void k_rotab() {
    int idx = blockIdx.x * 256 + threadIdx.x;        // over T_*512
    int t = idx >> 9;
    int j = idx & 511;
    float invf  = powf(10000.0f, -(float)j / 512.0f);
    float theta = (float)t * invf;
    float sn, cs;
    sincosf(theta, &sn, &cs);
    float svec  = (2.0f * (float)j + 0.4f * 1024.0f) / (1.4f * 1024.0f);
    float pw    = ((float)t - 1024.0f) * (1.0f / 512.0f);
    float scale = powf(svec, pw);
    float4 r;
    r.x = cs * scale;  r.y = sn * scale;      // q: *scale
    r.z = cs / scale;  r.w = sn / scale;      // k: /scale
    g_rot[idx] = r;
}

// ---------------- K1: RMSNorm -> a_q1 fp16, plus raw-x fp16 ----------------
__global__ void k_rmsnorm(const float* __restrict__ x, const float* __restrict__ rms_w) {
    int n = blockIdx.x;
    const float* xr = x + (size_t)n * C_;
    __shared__ float red[256];
    float s = 0.f;
    for (int c = threadIdx.x; c < C_; c += 256) { float v = xr[c]; s += v * v; }
    red[threadIdx.x] = s; __syncthreads();
    for (int o = 128; o > 0; o >>= 1) {
        if (threadIdx.x < o) red[threadIdx.x] += red[threadIdx.x + o];
        __syncthreads();
    }
    float nrm = sqrtf(red[0]) * 0.03125f;
    float inv = 1.0f / fmaxf(nrm, 1e-8f);
    for (int c = threadIdx.x; c < C_; c += 256) {
        float xv = xr[c];
        g_a_q1[(size_t)n * C_ + c] = __float2half(xv * inv * rms_w[c]);
        g_a_x1[(size_t)n * C_ + c] = __float2half(xv);
    }
}

// ---------------- mulsplit: a_prj1 = fp16(z * y_gn) ----------------
__global__ void k_mulsplit() {
    int idx = blockIdx.x * 256 + threadIdx.x;      // one float4
    size_t o = (size_t)idx * 4;
    float4 zv = *(const float4*)&g_z[o];
    float4 yv = *(const float4*)&g_y[o];
    uint2 hp;
    ((__half2*)&hp)[0] = __halves2half2(__float2half(zv.x * yv.x), __float2half(zv.y * yv.y));
    ((__half2*)&hp)[1] = __halves2half2(__float2half(zv.z * yv.z), __float2half(zv.w * yv.w));
    *(uint2*)(g_a_prj1 + o) = hp;
}

// ---------------- K4: chunk KV summaries ----------------
__global__ void k_chunk_kv() {
    int blk = blockIdx.x;
    int bh = blk / NC, c = blk % NC;
    int b = bh / H_, h = bh % H_;
    float gamma = 1.0f - exp2f(-5.0f - (float)h);
    __shared__ float Ks[64 * 65], Vs[64 * 64], dec[64];
    if (threadIdx.x < 64) dec[threadIdx.x] = powf(gamma, (float)(HD - threadIdx.x));
    __syncthreads();
    for (int i = threadIdx.x; i < HD * HD; i += 256) {
        int j = i >> 6, d = i & 63;
        size_t base = (size_t)(b * T_ + c * HD + j) * C3 + h * HD + d;
        Ks[j * 65 + d] = g_qkv[base + C_] * dec[j];
        Vs[j * 64 + d] = g_qkv[base + 2 * C_];
    }
    __syncthreads();
    float* Wout = g_W + ((size_t)bh * NC + c) * HD * HD;
    for (int p = threadIdx.x; p < 1024; p += 256) {
        int d = p >> 4, e0 = (p & 15) << 2;
        float s0 = 0, s1 = 0, s2 = 0, s3 = 0;
        #pragma unroll 8
        for (int j = 0; j < 64; j++) {
            float kd = Ks[j * 65 + d];
            float4 v4 = *(const float4*)&Vs[j * 64 + e0];
            s0 += kd * v4.x; s1 += kd * v4.y; s2 += kd * v4.z; s3 += kd * v4.w;
        }
        float4 r; r.x = s0; r.y = s1; r.z = s2; r.w = s3;
        *(float4*)&Wout[d * 64 + e0] = r;
    }
}

// ---------------- K5: state scan ----------------
__global__ void k_scan() {
    int bh = blockIdx.x;
    int h = bh % H_;
    float gamma = 1.0f - exp2f(-5.0f - (float)h);
    float g64 = powf(gamma, 64.0f);
    float st[16];
    #pragma unroll
    for (int r = 0; r < 16; r++) st[r] = 0.f;
    size_t base0 = (size_t)bh * NC * 4096;
    for (int c = 0; c < NC; c++) {
        size_t base = base0 + (size_t)c * 4096;
        #pragma unroll
        for (int r = 0; r < 16; r++) {
            int i = threadIdx.x + r * 256;
            g_S[base + i] = st[r];
            st[r] = st[r] * g64 + g_W[base + i];
        }
    }
}

// ---------------- K6: per-chunk attention + fused GroupNorm ----------------
__global__ void k_chunk_attn(const float* __restrict__ gn_w, const float* __restrict__ gn_b) {
    extern __shared__ float sm[];
    float* Qs   = sm;              // 64*65
    float* Kt   = Qs + 64 * 65;    // 64*68 (d-major)
    float* Vs   = Kt + 64 * 68;    // 64*64
    float* Ss   = Vs + 64 * 64;    // 64*64
    float* As   = Ss + 64 * 64;    // 64*68
    float* gpow = As + 64 * 68;    // 64
    int blk = blockIdx.x;
    int bh = blk / NC, c = blk % NC;
    int b = bh / H_, h = bh % H_;
    float gamma = 1.0f - exp2f(-5.0f - (float)h);
    if (threadIdx.x < 64) gpow[threadIdx.x] = powf(gamma, (float)threadIdx.x);
    for (int i = threadIdx.x; i < 4096; i += 256) {
        int j = i >> 6, d = i & 63;
        size_t base = (size_t)(b * T_ + c * HD + j) * C3 + h * HD + d;
        Qs[j * 65 + d] = g_qkv[base];
        Kt[d * 68 + j] = g_qkv[base + C_];
        Vs[j * 64 + d] = g_qkv[base + 2 * C_];
        Ss[i] = g_S[((size_t)bh * NC + c) * 4096 + i];
    }
    __syncthreads();
    for (int p = threadIdx.x; p < 1024; p += 256) {
        int i = p >> 4, j0 = (p & 15) << 2;
        float s0 = 0, s1 = 0, s2 = 0, s3 = 0;
        #pragma unroll 8
        for (int d = 0; d < 64; d++) {
            float q = Qs[i * 65 + d];
            float4 k4 = *(const float4*)&Kt[d * 68 + j0];
            s0 += q * k4.x; s1 += q * k4.y; s2 += q * k4.z; s3 += q * k4.w;
        }
        float4 r;
        r.x = (j0     <= i) ? s0 * gpow[i - j0]     : 0.f;
        r.y = (j0 + 1 <= i) ? s1 * gpow[i - j0 - 1] : 0.f;
        r.z = (j0 + 2 <= i) ? s2 * gpow[i - j0 - 2] : 0.f;
        r.w = (j0 + 3 <= i) ? s3 * gpow[i - j0 - 3] : 0.f;
        *(float4*)&As[i * 68 + j0] = r;
    }
    __syncthreads();
    for (int p = threadIdx.x; p < 1024; p += 256) {
        int i = p >> 4, e0 = (p & 15) << 2;
        float a0 = 0, a1 = 0, a2 = 0, a3 = 0;
        float c0 = 0, c1 = 0, c2 = 0, c3 = 0;
        #pragma unroll 8
        for (int jj = 0; jj < 64; jj++) {
            float av = As[i * 68 + jj];
            float qv = Qs[i * 65 + jj];
            float4 v4 = *(const float4*)&Vs[jj * 64 + e0];
            float4 s4 = *(const float4*)&Ss[jj * 64 + e0];
            a0 += av * v4.x; a1 += av * v4.y; a2 += av * v4.z; a3 += av * v4.w;
            c0 += qv * s4.x; c1 += qv * s4.y; c2 += qv * s4.z; c3 += qv * s4.w;
        }
        float gi = gpow[i];
        float y0 = (a0 + gi * c0) * 0.125f;
        float y1 = (a1 + gi * c1) * 0.125f;
        float y2 = (a2 + gi * c2) * 0.125f;
        float y3 = (a3 + gi * c3) * 0.125f;
        float sum = y0 + y1 + y2 + y3;
        float sq  = y0 * y0 + y1 * y1 + y2 * y2 + y3 * y3;
        #pragma unroll
        for (int o = 8; o >= 1; o >>= 1) {
            sum += __shfl_xor_sync(~0u, sum, o);
            sq  += __shfl_xor_sync(~0u, sq, o);
        }
        float mu  = sum * (1.0f / 64.0f);
        float var = sq * (1.0f / 64.0f) - mu * mu;
        float inv = rsqrtf(var + 1e-5f);
        int cb = h * 64 + e0;
        float4 o4;
        o4.x = (y0 - mu) * inv * gn_w[cb]     + gn_b[cb];
        o4.y = (y1 - mu) * inv * gn_w[cb + 1] + gn_b[cb + 1];
        o4.z = (y2 - mu) * inv * gn_w[cb + 2] + gn_b[cb + 2];
        o4.w = (y3 - mu) * inv * gn_w[cb + 3] + gn_b[cb + 3];
        *(float4*)&g_y[(size_t)(b * T_ + c * HD + i) * C_ + cb] = o4;
    }
}

// ---------------- launch ----------------
extern "C" void kernel_launch(void* const* d_in, const int* in_sizes, int n_in,
                              void* d_out, int out_size) {
    const float* x       = (const float*)d_in[0];
    const float* w_qkvff = (const float*)d_in[1];
    const float* w_gated = (const float*)d_in[2];
    const float* b_gated = (const float*)d_in[3];
    const float* w_proj  = (const float*)d_in[4];
    const float* b_proj  = (const float*)d_in[5];
    const float* gn_w    = (const float*)d_in[6];
    const float* gn_b    = (const float*)d_in[7];
    const float* w_ff    = (const float*)d_in[8];
    const float* rms_w   = (const float*)d_in[9];
    float* out = (float*)d_out;

    float *p_qkv, *p_z, *p_ffout;
    float4* p_rot;
    __half *p_a_q1, *p_b_qkv1, *p_a_x1, *p_b_gat1, *p_a_prj1, *p_b_prj1, *p_a_ff1, *p_b_ff1;
    cudaGetSymbolAddress((void**)&p_qkv,   g_qkv);
    cudaGetSymbolAddress((void**)&p_z,     g_z);
    cudaGetSymbolAddress((void**)&p_ffout, g_ffout);
    cudaGetSymbolAddress((void**)&p_rot,   g_rot);
    cudaGetSymbolAddress((void**)&p_a_q1,  g_a_q1);
    cudaGetSymbolAddress((void**)&p_b_qkv1, g_b_qkv1);
    cudaGetSymbolAddress((void**)&p_a_x1,  g_a_x1);
    cudaGetSymbolAddress((void**)&p_b_gat1, g_b_gat1);
    cudaGetSymbolAddress((void**)&p_a_prj1, g_a_prj1);
    cudaGetSymbolAddress((void**)&p_b_prj1, g_b_prj1);
    cudaGetSymbolAddress((void**)&p_a_ff1, g_a_ff1);
    cudaGetSymbolAddress((void**)&p_b_ff1, g_b_ff1);

    const int SMEM = 1024 + 4 * 49152;               // 197632
    const int ATTN_SMEM = (64*65 + 64*68 + 64*64 + 64*64 + 64*68 + 64) * 4;

    // one-time infra (created on the uncaptured correctness call; reused thereafter;
    // identical GPU work is enqueued on every call)
    static cudaStream_t s1 = nullptr;
    static cudaEvent_t ev0, ev_ax, ev_gate, ev_ff;
    if (s1 == nullptr) {
        cudaStreamCreateWithFlags(&s1, cudaStreamNonBlocking);
        cudaEventCreateWithFlags(&ev0,     cudaEventDisableTiming);
        cudaEventCreateWithFlags(&ev_ax,   cudaEventDisableTiming);
        cudaEventCreateWithFlags(&ev_gate, cudaEventDisableTiming);
        cudaEventCreateWithFlags(&ev_ff,   cudaEventDisableTiming);
        cudaFuncSetAttribute(mma_gemm<1>, cudaFuncAttributeMaxDynamicSharedMemorySize, SMEM);
        cudaFuncSetAttribute(mma_gemm<2>, cudaFuncAttributeMaxDynamicSharedMemorySize, SMEM);
        cudaFuncSetAttribute(mma_gemm<3>, cudaFuncAttributeMaxDynamicSharedMemorySize, SMEM);
        cudaFuncSetAttribute(mma_gemm<4>, cudaFuncAttributeMaxDynamicSharedMemorySize, SMEM);
        cudaFuncSetAttribute(mma_gemm<5>, cudaFuncAttributeMaxDynamicSharedMemorySize, SMEM);
        cudaFuncSetAttribute(k_chunk_attn, cudaFuncAttributeMaxDynamicSharedMemorySize, ATTN_SMEM);
    }

    // ---- fork: s1 joins capture via ev0 ----
    cudaEventRecord(ev0, 0);
    cudaStreamWaitEvent(s1, ev0, 0);

    // s1: fp16 weight converts for gate / proj / ff
    k_half1<<<(C_ * C_) / 1024, 256, 0, s1>>>((const float4*)w_gated, p_b_gat1);
    k_half1<<<(C_ * C_) / 1024, 256, 0, s1>>>((const float4*)w_proj,  p_b_prj1);
    k_half1<<<(C_ * 2 * C_) / 1024, 256, 0, s1>>>((const float4*)w_ff, p_b_ff1);

    // main: qkvff weight convert + rotary table + RMSNorm
    k_half1<<<(C5 * C_) / 1024, 256>>>((const float4*)w_qkvff, p_b_qkv1);
    k_rotab<<<(T_ * 512) / 256, 256>>>();
    k_rmsnorm<<<BT, 256>>>(x, rms_w);
    cudaEventRecord(ev_ax, 0);

    // s1: gate GEMM z = silu(x @ w_gated^T + b)  (Kp=1024)
    cudaStreamWaitEvent(s1, ev_ax, 0);
    mma_gemm<1><<<dim3(C_ / 256, BT / 128), 256, SMEM, s1>>>(
        p_a_x1, p_b_gat1, C_, C_, p_z, b_gated, nullptr, nullptr, nullptr);
    cudaEventRecord(ev_gate, s1);

    // s1: ffpart GEMM (B rows 3072..5119 of b_qkv1, Kp=1024) -> gelu fp16 a_ff1
    mma_gemm<4><<<dim3(2 * C_ / 256, BT / 128), 256, SMEM, s1>>>(
        p_a_q1, p_b_qkv1 + (size_t)C3 * C_, C_, 2 * C_,
        nullptr, nullptr, nullptr, nullptr, p_a_ff1);

    // s1: ff GEMM ffout = gelu(ff) @ w_ff^T  (Kp=2048)
    mma_gemm<2><<<dim3(C_ / 256, BT / 128), 256, SMEM, s1>>>(
        p_a_ff1, p_b_ff1, 2 * C_, C_, p_ffout, nullptr, nullptr, nullptr, nullptr);
    cudaEventRecord(ev_ff, s1);

    // main: qkv GEMM (Kp=1024, N=3072) with fused xPos rotary -> g_qkv fp32
    mma_gemm<5><<<dim3(C3 / 256, BT / 128), 256, SMEM>>>(
        p_a_q1, p_b_qkv1, C_, C3, p_qkv, nullptr, (const float*)p_rot, nullptr, nullptr);

    // main: attention chain (overlaps with s1)
    k_chunk_kv<<<BH * NC, 256>>>();
    k_scan<<<BH, 256>>>();
    k_chunk_attn<<<BH * NC, 256, ATTN_SMEM>>>(gn_w, gn_b);

    // join: a_prj1 = fp16(z * y_gn)
    cudaStreamWaitEvent(0, ev_gate, 0);
    k_mulsplit<<<(BT * C_) / 1024, 256>>>();

    // join ff, then final proj GEMM: out = y2 @ w_proj^T + b_proj + x + ffout
    cudaStreamWaitEvent(0, ev_ff, 0);
    mma_gemm<3><<<dim3(C_ / 256, BT / 128), 256, SMEM>>>(
        p_a_prj1, p_b_prj1, C_, C_, out, b_proj, x, p_ffout, nullptr);
}

// round 12
// speedup vs baseline: 2.5598x; 1.2572x over previous
#include <cuda_runtime.h>
#include <cuda_fp16.h>
#include <math.h>
#include <stdint.h>

#define B_  2
#define T_  2048
#define C_  1024
#define H_  16
#define HD  64
#define BT  (B_*T_)      // 4096
#define C3  (3*C_)       // 3072
#define C5  (5*C_)       // 5120
#define NC  (T_/HD)      // 32 chunks
#define BH  (B_*H_)      // 32

// ---------------- scratch (device globals) ----------------
__device__ float g_qkv [BT*(size_t)C3];           // q,k,v fp32 (stride 3C), rotary applied
__device__ float g_W [BH*(size_t)NC*HD*HD];
__device__ float g_S [BH*(size_t)NC*HD*HD];
__device__ float g_z [BT*(size_t)C_];             // silu(gate) fp32
__device__ float g_ffout[BT*(size_t)C_];          // ff GEMM result
__device__ float4 g_rot [T_*(size_t)512];         // (cq,sq,ck,sk) per (t,j)
// single fp16 operands
__device__ __half g_a_q1  [BT*(size_t)C_];        // rms-normed x
__device__ __half g_b_qkv1[C5*(size_t)C_];
__device__ __half g_a_x1  [BT*(size_t)C_];        // raw x
__device__ __half g_b_gat1[C_*(size_t)C_];
__device__ __half g_a_prj1[BT*(size_t)C_];
__device__ __half g_b_prj1[C_*(size_t)C_];
__device__ __half g_a_ff1 [BT*(size_t)2*C_];      // gelu(ff) fp16
__device__ __half g_b_ff1 [C_*(size_t)2*C_];

// ---------------- PTX helpers ----------------
__device__ __forceinline__ uint32_t smem_u32(const void* p) {
    uint32_t a;
    asm("{ .reg .u64 t; cvta.to.shared.u64 t, %1; cvt.u32.u64 %0, t; }" : "=r"(a) : "l"(p));
    return a;
}
#define CPA(dst, src)  asm volatile("cp.async.cg.shared.global [%0], [%1], 16;" :: "r"(dst), "l"(src) : "memory")
#define CPC()          asm volatile("cp.async.commit_group;" ::: "memory")
#define CPW(n)         asm volatile("cp.async.wait_group %0;" :: "n"(n) : "memory")
#define SWZ(o) ((o) ^ (((o) >> 3) & 0x70))

#define LDM_X4(r0, r1, r2, r3, a) \
    asm volatile("ldmatrix.sync.aligned.m8n8.x4.shared.b16 {%0,%1,%2,%3}, [%4];" \
        : "=r"(r0), "=r"(r1), "=r"(r2), "=r"(r3) : "r"(a))

#define MMA_F16(d, a, b0, b1) \
    asm volatile("mma.sync.aligned.m16n8k16.row.col.f32.f16.f16.f32 " \
        "{%0,%1,%2,%3}, {%4,%5,%6,%7}, {%8,%9}, {%0,%1,%2,%3};" \
        : "+f"((d)[0]), "+f"((d)[1]), "+f"((d)[2]), "+f"((d)[3]) \
        : "r"((a)[0]), "r"((a)[1]), "r"((a)[2]), "r"((a)[3]), "r"(b0), "r"(b1))

// ---------------- warp-MMA fp16 NT GEMM (proven R4 mainloop) ----------------
// EPI 1: silu(v+bias[n]) -> fp32 Cout
// EPI 2: plain -> Cout
// EPI 3: v + bias[n] + aux0[o] + aux1[o] -> Cout
// EPI 4: gelu(v) -> fp16 osplit (row stride N)
// EPI 5: qkv with fused xPos rotary (n<2048 rotate via aux0 table; v pass) -> fp32 Cout
template<int EPI>
__global__ void __launch_bounds__(256, 1) mma_gemm(
    const __half* __restrict__ A, const __half* __restrict__ Bm,
    int Kp, int N, float* __restrict__ Cout,
    const float* __restrict__ bias, const float* __restrict__ aux0,
    const float* __restrict__ aux1, __half* __restrict__ osplit)
{
    extern __shared__ __align__(1024) char smem_raw[];
    const int S = 4;
    const uint32_t STAGE = 49152;   // A 16KB + B 32KB
    uint32_t sbase = (smem_u32(smem_raw) + 1023) & ~1023u;

    int tid = threadIdx.x;
    int wid = tid >> 5, lane = tid & 31;
    int warp_m = wid & 1, warp_n = wid >> 1;
    int bm = blockIdx.y << 7, bn = blockIdx.x << 8;

    const int nk = Kp >> 6;

    auto load_stage = [&](int s, int k) {
        uint32_t a_s = sbase + s * STAGE;
        uint32_t b_s = a_s + 16384u;
        const __half* Ag = A + (size_t)bm * Kp + (size_t)k * 64;
        const __half* Bg = Bm + (size_t)bn * Kp + (size_t)k * 64;
        #pragma unroll
        for (int q = 0; q < 4; q++) {
            int i = tid + (q << 8);
            int r = i >> 3, c = i & 7;
            uint32_t off = SWZ(r * 128 + c * 16);
            CPA(a_s + off, (const char*)(Ag + (size_t)r * Kp + c * 8));
        }
        #pragma unroll
        for (int q = 0; q < 8; q++) {
            int i = tid + (q << 8);
            int r = i >> 3, c = i & 7;
            uint32_t off = SWZ(r * 128 + c * 16);
            CPA(b_s + off, (const char*)(Bg + (size_t)r * Kp + c * 8));
        }
    };

    float acc[4][8][4];
    #pragma unroll
    for (int mt = 0; mt < 4; mt++)
        #pragma unroll
        for (int nt = 0; nt < 8; nt++)
            #pragma unroll
            for (int u = 0; u < 4; u++) acc[mt][nt][u] = 0.f;

    int j = lane >> 3;
    int lrow = lane & 7;
    int a_row_off = ((j & 1) << 3) + lrow;
    int a_byte_off = (j >> 1) << 4;
    int b_row_off = ((j >> 1) << 3) + lrow;
    int b_byte_off = (j & 1) << 4;

    #pragma unroll
    for (int p = 0; p < S - 1; p++) { load_stage(p, p); CPC(); }

    for (int k = 0; k < nk; k++) {
        CPW(S - 2);
        __syncthreads();
        if (k + S - 1 < nk) load_stage((k + S - 1) % S, k + S - 1);
        CPC();

        uint32_t a_s = sbase + (uint32_t)(k % S) * STAGE;
        uint32_t b_s = a_s + 16384u;
        #pragma unroll
        for (int ks = 0; ks < 4; ks++) {
            uint32_t af[4][4], bf[4][4];
            #pragma unroll
            for (int mt = 0; mt < 4; mt++) {
                int row = warp_m * 64 + mt * 16 + a_row_off;
                uint32_t ad = a_s + SWZ(row * 128 + ks * 32 + a_byte_off);
                LDM_X4(af[mt][0], af[mt][1], af[mt][2], af[mt][3], ad);
            }
            #pragma unroll
            for (int ng = 0; ng < 4; ng++) {
                int row = warp_n * 64 + ng * 16 + b_row_off;
                uint32_t bd = b_s + SWZ(row * 128 + ks * 32 + b_byte_off);
                LDM_X4(bf[ng][0], bf[ng][1], bf[ng][2], bf[ng][3], bd);
            }
            #pragma unroll
            for (int mt = 0; mt < 4; mt++)
                #pragma unroll
                for (int nt = 0; nt < 8; nt++) {
                    uint32_t b0 = bf[nt >> 1][(nt & 1) ? 2 : 0];
                    uint32_t b1 = bf[nt >> 1][(nt & 1) ? 3 : 1];
                    MMA_F16(acc[mt][nt], af[mt], b0, b1);
                }
        }
    }

    // ---------------- epilogue ----------------
    int gid = lane >> 2;
    int tig = lane & 3;
    #pragma unroll
    for (int mt = 0; mt < 4; mt++) {
        int m0 = bm + warp_m * 64 + mt * 16 + gid;
        #pragma unroll
        for (int nt = 0; nt < 8; nt++) {
            int n0 = bn + warp_n * 64 + nt * 8 + tig * 2;
            float* ac = acc[mt][nt];
            #pragma unroll
            for (int half_ = 0; half_ < 2; half_++) {
                int m = m0 + half_ * 8;
                float v0 = ac[half_ * 2], v1 = ac[half_ * 2 + 1];
                if (EPI == 1) {
                    float z0 = v0 + bias[n0], z1 = v1 + bias[n0 + 1];
                    float2 w;
                    w.x = z0 / (1.f + expf(-z0));
                    w.y = z1 / (1.f + expf(-z1));
                    *(float2*)&Cout[(size_t)m * N + n0] = w;
                } else if (EPI == 2) {
                    float2 w; w.x = v0; w.y = v1;
                    *(float2*)&Cout[(size_t)m * N + n0] = w;
                } else if (EPI == 3) {
                    size_t o = (size_t)m * N + n0;
                    float2 w;
                    w.x = v0 + bias[n0]     + aux0[o]     + aux1[o];
                    w.y = v1 + bias[n0 + 1] + aux0[o + 1] + aux1[o + 1];
                    *(float2*)&Cout[o] = w;
                } else if (EPI == 4) {  // gelu -> fp16
                    float g0 = 0.5f * v0 * (1.0f + erff(v0 * 0.70710678118654752f));
                    float g1 = 0.5f * v1 * (1.0f + erff(v1 * 0.70710678118654752f));
                    *(__half2*)(osplit + (size_t)m * N + n0) =
                        __halves2half2(__float2half(g0), __float2half(g1));
                } else {  // EPI 5: fused xPos rotary on q,k
                    float2 w;
                    if (n0 < 2048) {
                        const float4* rot = (const float4*)aux0;
                        float4 rt = rot[((size_t)(m & (T_ - 1)) << 9) + ((n0 & 1023) >> 1)];
                        float cc = (n0 < 1024) ? rt.x : rt.z;
                        float ss = (n0 < 1024) ? rt.y : rt.w;
                        w.x = v0 * cc - v1 * ss;
                        w.y = v1 * cc + v0 * ss;
                    } else {
                        w.x = v0; w.y = v1;
                    }
                    *(float2*)&Cout[(size_t)m * N + n0] = w;
                }
            }
        }
    }
}

// ---------------- flat fp32 -> fp16 convert ----------------
__global__ void k_half1(const float4* __restrict__ in, __half* __restrict__ out) {
    int idx = blockIdx.x * 256 + threadIdx.x;      // one float4
    float4 v = in[idx];
    uint2 hp;
    ((__half2*)&hp)[0] = __halves2half2(__float2half(v.x), __float2half(v.y));
    ((__half2*)&hp)[1] = __halves2half2(__float2half(v.z), __float2half(v.w));
    *(uint2*)(out + (size_t)idx * 4) = hp;
}

// ---------------- rotary table: (cq,sq,ck,sk) per (t,j) ----------------
__global__ void k_rotab() {
    int idx = blockIdx.x * 256 + threadIdx.x;        // over T_*512
    int t = idx >> 9;
    int j = idx & 511;
    float invf  = powf(10000.0f, -(float)j / 512.0f);
    float theta = (float)t * invf;
    float sn, cs;
    sincosf(theta, &sn, &cs);
    float svec  = (2.0f * (float)j + 0.4f * 1024.0f) / (1.4f * 1024.0f);
    float pw    = ((float)t - 1024.0f) * (1.0f / 512.0f);
    float scale = powf(svec, pw);
    float4 r;
    r.x = cs * scale;  r.y = sn * scale;      // q: *scale
    r.z = cs / scale;  r.w = sn / scale;      // k: /scale
    g_rot[idx] = r;
}

// ---------------- K1: RMSNorm -> a_q1 fp16, plus raw-x fp16 ----------------
__global__ void k_rmsnorm(const float* __restrict__ x, const float* __restrict__ rms_w) {
    int n = blockIdx.x;
    const float* xr = x + (size_t)n * C_;
    __shared__ float red[256];
    float s = 0.f;
    for (int c = threadIdx.x; c < C_; c += 256) { float v = xr[c]; s += v * v; }
    red[threadIdx.x] = s; __syncthreads();
    for (int o = 128; o > 0; o >>= 1) {
        if (threadIdx.x < o) red[threadIdx.x] += red[threadIdx.x + o];
        __syncthreads();
    }
    float nrm = sqrtf(red[0]) * 0.03125f;
    float inv = 1.0f / fmaxf(nrm, 1e-8f);
    for (int c = threadIdx.x; c < C_; c += 256) {
        float xv = xr[c];
        g_a_q1[(size_t)n * C_ + c] = __float2half(xv * inv * rms_w[c]);
        g_a_x1[(size_t)n * C_ + c] = __float2half(xv);
    }
}

// ---------------- K4: chunk KV summaries (4x4 register blocking) ----------------
__global__ void k_chunk_kv() {
    int blk = blockIdx.x;
    int bh = blk / NC, c = blk % NC;
    int b = bh / H_, h = bh % H_;
    float gamma = 1.0f - exp2f(-5.0f - (float)h);
    __shared__ float Ks[64 * 65], Vs[64 * 64], dec[64];
    if (threadIdx.x < 64) dec[threadIdx.x] = powf(gamma, (float)(HD - threadIdx.x));
    __syncthreads();
    for (int i = threadIdx.x; i < HD * HD; i += 256) {
        int j = i >> 6, d = i & 63;
        size_t base = (size_t)(b * T_ + c * HD + j) * C3 + h * HD + d;
        Ks[j * 65 + d] = g_qkv[base + C_] * dec[j];
        Vs[j * 64 + d] = g_qkv[base + 2 * C_];
    }
    __syncthreads();
    float* Wout = g_W + ((size_t)bh * NC + c) * HD * HD;
    int d0 = (threadIdx.x >> 4) << 2;      // 4 rows
    int e0 = (threadIdx.x & 15) << 2;      // 4 cols
    float s[4][4];
    #pragma unroll
    for (int r = 0; r < 4; r++)
        #pragma unroll
        for (int u = 0; u < 4; u++) s[r][u] = 0.f;
    #pragma unroll 4
    for (int j = 0; j < 64; j++) {
        float4 v4 = *(const float4*)&Vs[j * 64 + e0];
        float k0 = Ks[j * 65 + d0];
        float k1 = Ks[j * 65 + d0 + 1];
        float k2 = Ks[j * 65 + d0 + 2];
        float k3 = Ks[j * 65 + d0 + 3];
        s[0][0] += k0 * v4.x; s[0][1] += k0 * v4.y; s[0][2] += k0 * v4.z; s[0][3] += k0 * v4.w;
        s[1][0] += k1 * v4.x; s[1][1] += k1 * v4.y; s[1][2] += k1 * v4.z; s[1][3] += k1 * v4.w;
        s[2][0] += k2 * v4.x; s[2][1] += k2 * v4.y; s[2][2] += k2 * v4.z; s[2][3] += k2 * v4.w;
        s[3][0] += k3 * v4.x; s[3][1] += k3 * v4.y; s[3][2] += k3 * v4.z; s[3][3] += k3 * v4.w;
    }
    #pragma unroll
    for (int r = 0; r < 4; r++) {
        float4 w; w.x = s[r][0]; w.y = s[r][1]; w.z = s[r][2]; w.w = s[r][3];
        *(float4*)&Wout[(d0 + r) * 64 + e0] = w;
    }
}

// ---------------- K5: state scan (128 blocks: 4 per bh) ----------------
__global__ void k_scan() {
    int blk = blockIdx.x;            // BH*4
    int bh = blk >> 2, part = blk & 3;
    int h = bh % H_;
    float gamma = 1.0f - exp2f(-5.0f - (float)h);
    float g64 = powf(gamma, 64.0f);
    int i = part * 1024 + threadIdx.x * 4;
    float4 st; st.x = st.y = st.z = st.w = 0.f;
    size_t base0 = (size_t)bh * NC * 4096 + i;
    for (int c = 0; c < NC; c++) {
        size_t base = base0 + (size_t)c * 4096;
        *(float4*)&g_S[base] = st;
        float4 w = *(const float4*)&g_W[base];
        st.x = st.x * g64 + w.x;
        st.y = st.y * g64 + w.y;
        st.z = st.z * g64 + w.z;
        st.w = st.w * g64 + w.w;
    }
}

// ---------------- K6: per-chunk attention + fused GN + gate-mul -> a_prj1 fp16 ----
__global__ void k_chunk_attn(const float* __restrict__ gn_w, const float* __restrict__ gn_b) {
    extern __shared__ float sm[];
    float* Qs   = sm;              // 64*65
    float* Kt   = Qs + 64 * 65;    // 64*68 (d-major)
    float* Vs   = Kt + 64 * 68;    // 64*64
    float* Ss   = Vs + 64 * 64;    // 64*64
    float* As   = Ss + 64 * 64;    // 64*68
    float* gpow = As + 64 * 68;    // 64
    int blk = blockIdx.x;
    int bh = blk / NC, c = blk % NC;
    int b = bh / H_, h = bh % H_;
    float gamma = 1.0f - exp2f(-5.0f - (float)h);
    if (threadIdx.x < 64) gpow[threadIdx.x] = powf(gamma, (float)threadIdx.x);
    for (int i = threadIdx.x; i < 4096; i += 256) {
        int j = i >> 6, d = i & 63;
        size_t base = (size_t)(b * T_ + c * HD + j) * C3 + h * HD + d;
        Qs[j * 65 + d] = g_qkv[base];
        Kt[d * 68 + j] = g_qkv[base + C_];
        Vs[j * 64 + d] = g_qkv[base + 2 * C_];
        Ss[i] = g_S[((size_t)bh * NC + c) * 4096 + i];
    }
    __syncthreads();
    int i0 = (threadIdx.x >> 4) << 2;      // 4 rows
    int e0 = (threadIdx.x & 15) << 2;      // 4 cols (and j0 for phase 1)
    // ---- phase 1: masked decayed scores (4x4) ----
    {
        float s[4][4];
        #pragma unroll
        for (int r = 0; r < 4; r++)
            #pragma unroll
            for (int u = 0; u < 4; u++) s[r][u] = 0.f;
        #pragma unroll 4
        for (int d = 0; d < 64; d++) {
            float4 k4 = *(const float4*)&Kt[d * 68 + e0];
            float q0 = Qs[(i0 + 0) * 65 + d];
            float q1 = Qs[(i0 + 1) * 65 + d];
            float q2 = Qs[(i0 + 2) * 65 + d];
            float q3 = Qs[(i0 + 3) * 65 + d];
            s[0][0] += q0 * k4.x; s[0][1] += q0 * k4.y; s[0][2] += q0 * k4.z; s[0][3] += q0 * k4.w;
            s[1][0] += q1 * k4.x; s[1][1] += q1 * k4.y; s[1][2] += q1 * k4.z; s[1][3] += q1 * k4.w;
            s[2][0] += q2 * k4.x; s[2][1] += q2 * k4.y; s[2][2] += q2 * k4.z; s[2][3] += q2 * k4.w;
            s[3][0] += q3 * k4.x; s[3][1] += q3 * k4.y; s[3][2] += q3 * k4.z; s[3][3] += q3 * k4.w;
        }
        #pragma unroll
        for (int r = 0; r < 4; r++) {
            int i = i0 + r;
            float4 w;
            w.x = (e0     <= i) ? s[r][0] * gpow[i - e0]     : 0.f;
            w.y = (e0 + 1 <= i) ? s[r][1] * gpow[i - e0 - 1] : 0.f;
            w.z = (e0 + 2 <= i) ? s[r][2] * gpow[i - e0 - 2] : 0.f;
            w.w = (e0 + 3 <= i) ? s[r][3] * gpow[i - e0 - 3] : 0.f;
            *(float4*)&As[i * 68 + e0] = w;
        }
    }
    __syncthreads();
    // ---- phase 2: AV + gamma^i QS (4x4), fused GN + gate ----
    float a[4][4], cc[4][4];
    #pragma unroll
    for (int r = 0; r < 4; r++)
        #pragma unroll
        for (int u = 0; u < 4; u++) { a[r][u] = 0.f; cc[r][u] = 0.f; }
    #pragma unroll 4
    for (int jj = 0; jj < 64; jj++) {
        float4 v4 = *(const float4*)&Vs[jj * 64 + e0];
        float4 s4 = *(const float4*)&Ss[jj * 64 + e0];
        #pragma unroll
        for (int r = 0; r < 4; r++) {
            float av = As[(i0 + r) * 68 + jj];
            float qv = Qs[(i0 + r) * 65 + jj];
            a[r][0] += av * v4.x; a[r][1] += av * v4.y; a[r][2] += av * v4.z; a[r][3] += av * v4.w;
            cc[r][0] += qv * s4.x; cc[r][1] += qv * s4.y; cc[r][2] += qv * s4.z; cc[r][3] += qv * s4.w;
        }
    }
    float y[4][4], sum[4], sq[4];
    #pragma unroll
    for (int r = 0; r < 4; r++) {
        float gi = gpow[i0 + r];
        sum[r] = 0.f; sq[r] = 0.f;
        #pragma unroll
        for (int u = 0; u < 4; u++) {
            float v = (a[r][u] + gi * cc[r][u]) * 0.125f;
            y[r][u] = v;
            sum[r] += v;
            sq[r]  += v * v;
        }
    }
    // reduce over the 16 lanes holding this row group (lanes differ only in e0)
    #pragma unroll
    for (int o = 8; o >= 1; o >>= 1) {
        #pragma unroll
        for (int r = 0; r < 4; r++) {
            sum[r] += __shfl_xor_sync(~0u, sum[r], o);
            sq[r]  += __shfl_xor_sync(~0u, sq[r], o);
        }
    }
    int cb = h * 64 + e0;
    float4 gw = *(const float4*)&gn_w[cb];
    float4 gb = *(const float4*)&gn_b[cb];
    #pragma unroll
    for (int r = 0; r < 4; r++) {
        float mu  = sum[r] * (1.0f / 64.0f);
        float var = sq[r] * (1.0f / 64.0f) - mu * mu;
        float inv = rsqrtf(var + 1e-5f);
        size_t row = (size_t)(b * T_ + c * HD + i0 + r);
        float4 zv = *(const float4*)&g_z[row * C_ + cb];
        float o0 = ((y[r][0] - mu) * inv * gw.x + gb.x) * zv.x;
        float o1 = ((y[r][1] - mu) * inv * gw.y + gb.y) * zv.y;
        float o2 = ((y[r][2] - mu) * inv * gw.z + gb.z) * zv.z;
        float o3 = ((y[r][3] - mu) * inv * gw.w + gb.w) * zv.w;
        uint2 hp;
        ((__half2*)&hp)[0] = __halves2half2(__float2half(o0), __float2half(o1));
        ((__half2*)&hp)[1] = __halves2half2(__float2half(o2), __float2half(o3));
        *(uint2*)(g_a_prj1 + row * C_ + cb) = hp;
    }
}

// ---------------- launch ----------------
extern "C" void kernel_launch(void* const* d_in, const int* in_sizes, int n_in,
                              void* d_out, int out_size) {
    const float* x       = (const float*)d_in[0];
    const float* w_qkvff = (const float*)d_in[1];
    const float* w_gated = (const float*)d_in[2];
    const float* b_gated = (const float*)d_in[3];
    const float* w_proj  = (const float*)d_in[4];
    const float* b_proj  = (const float*)d_in[5];
    const float* gn_w    = (const float*)d_in[6];
    const float* gn_b    = (const float*)d_in[7];
    const float* w_ff    = (const float*)d_in[8];
    const float* rms_w   = (const float*)d_in[9];
    float* out = (float*)d_out;

    float *p_qkv, *p_z, *p_ffout;
    float4* p_rot;
    __half *p_a_q1, *p_b_qkv1, *p_a_x1, *p_b_gat1, *p_a_prj1, *p_b_prj1, *p_a_ff1, *p_b_ff1;
    cudaGetSymbolAddress((void**)&p_qkv,   g_qkv);
    cudaGetSymbolAddress((void**)&p_z,     g_z);
    cudaGetSymbolAddress((void**)&p_ffout, g_ffout);
    cudaGetSymbolAddress((void**)&p_rot,   g_rot);
    cudaGetSymbolAddress((void**)&p_a_q1,  g_a_q1);
    cudaGetSymbolAddress((void**)&p_b_qkv1, g_b_qkv1);
    cudaGetSymbolAddress((void**)&p_a_x1,  g_a_x1);
    cudaGetSymbolAddress((void**)&p_b_gat1, g_b_gat1);
    cudaGetSymbolAddress((void**)&p_a_prj1, g_a_prj1);
    cudaGetSymbolAddress((void**)&p_b_prj1, g_b_prj1);
    cudaGetSymbolAddress((void**)&p_a_ff1, g_a_ff1);
    cudaGetSymbolAddress((void**)&p_b_ff1, g_b_ff1);

    const int SMEM = 1024 + 4 * 49152;               // 197632
    const int ATTN_SMEM = (64*65 + 64*68 + 64*64 + 64*64 + 64*68 + 64) * 4;

    static cudaStream_t s1 = nullptr;
    static cudaEvent_t ev0, ev_ax, ev_gate, ev_ff;
    if (s1 == nullptr) {
        cudaStreamCreateWithFlags(&s1, cudaStreamNonBlocking);
        cudaEventCreateWithFlags(&ev0,     cudaEventDisableTiming);
        cudaEventCreateWithFlags(&ev_ax,   cudaEventDisableTiming);
        cudaEventCreateWithFlags(&ev_gate, cudaEventDisableTiming);
        cudaEventCreateWithFlags(&ev_ff,   cudaEventDisableTiming);
        cudaFuncSetAttribute(mma_gemm<1>, cudaFuncAttributeMaxDynamicSharedMemorySize, SMEM);
        cudaFuncSetAttribute(mma_gemm<2>, cudaFuncAttributeMaxDynamicSharedMemorySize, SMEM);
        cudaFuncSetAttribute(mma_gemm<3>, cudaFuncAttributeMaxDynamicSharedMemorySize, SMEM);
        cudaFuncSetAttribute(mma_gemm<4>, cudaFuncAttributeMaxDynamicSharedMemorySize, SMEM);
        cudaFuncSetAttribute(mma_gemm<5>, cudaFuncAttributeMaxDynamicSharedMemorySize, SMEM);
        cudaFuncSetAttribute(k_chunk_attn, cudaFuncAttributeMaxDynamicSharedMemorySize, ATTN_SMEM);
    }

    // ---- fork: s1 joins capture via ev0 ----
    cudaEventRecord(ev0, 0);
    cudaStreamWaitEvent(s1, ev0, 0);

    // s1: fp16 weight converts for gate / proj / ff
    k_half1<<<(C_ * C_) / 1024, 256, 0, s1>>>((const float4*)w_gated, p_b_gat1);
    k_half1<<<(C_ * C_) / 1024, 256, 0, s1>>>((const float4*)w_proj,  p_b_prj1);
    k_half1<<<(C_ * 2 * C_) / 1024, 256, 0, s1>>>((const float4*)w_ff, p_b_ff1);

    // main: qkvff weight convert + rotary table + RMSNorm
    k_half1<<<(C5 * C_) / 1024, 256>>>((const float4*)w_qkvff, p_b_qkv1);
    k_rotab<<<(T_ * 512) / 256, 256>>>();
    k_rmsnorm<<<BT, 256>>>(x, rms_w);
    cudaEventRecord(ev_ax, 0);

    // s1: gate GEMM z = silu(x @ w_gated^T + b)  (Kp=1024)
    cudaStreamWaitEvent(s1, ev_ax, 0);
    mma_gemm<1><<<dim3(C_ / 256, BT / 128), 256, SMEM, s1>>>(
        p_a_x1, p_b_gat1, C_, C_, p_z, b_gated, nullptr, nullptr, nullptr);
    cudaEventRecord(ev_gate, s1);

    // s1: ffpart GEMM (B rows 3072..5119 of b_qkv1, Kp=1024) -> gelu fp16 a_ff1
    mma_gemm<4><<<dim3(2 * C_ / 256, BT / 128), 256, SMEM, s1>>>(
        p_a_q1, p_b_qkv1 + (size_t)C3 * C_, C_, 2 * C_,
        nullptr, nullptr, nullptr, nullptr, p_a_ff1);

    // s1: ff GEMM ffout = gelu(ff) @ w_ff^T  (Kp=2048)
    mma_gemm<2><<<dim3(C_ / 256, BT / 128), 256, SMEM, s1>>>(
        p_a_ff1, p_b_ff1, 2 * C_, C_, p_ffout, nullptr, nullptr, nullptr, nullptr);
    cudaEventRecord(ev_ff, s1);

    // main: qkv GEMM (Kp=1024, N=3072) with fused xPos rotary -> g_qkv fp32
    mma_gemm<5><<<dim3(C3 / 256, BT / 128), 256, SMEM>>>(
        p_a_q1, p_b_qkv1, C_, C3, p_qkv, nullptr, (const float*)p_rot, nullptr, nullptr);

    // main: attention chain (overlaps with s1)
    k_chunk_kv<<<BH * NC, 256>>>();
    k_scan<<<BH * 4, 256>>>();
    // chunk_attn consumes g_z (gate) in its epilogue
    cudaStreamWaitEvent(0, ev_gate, 0);
    k_chunk_attn<<<BH * NC, 256, ATTN_SMEM>>>(gn_w, gn_b);

    // join ff, then final proj GEMM: out = y2 @ w_proj^T + b_proj + x + ffout
    cudaStreamWaitEvent(0, ev_ff, 0);
    mma_gemm<3><<<dim3(C_ / 256, BT / 128), 256, SMEM>>>(
        p_a_prj1, p_b_prj1, C_, C_, out, b_proj, x, p_ffout, nullptr);
}

// round 13
// speedup vs baseline: 3.0805x; 1.2034x over previous
#include <cuda_runtime.h>
#include <cuda_fp16.h>
#include <math.h>
#include <stdint.h>

#define B_  2
#define T_  2048
#define C_  1024
#define H_  16
#define HD  64
#define BT  (B_*T_)      // 4096
#define C3  (3*C_)       // 3072
#define C5  (5*C_)       // 5120
#define NC  (T_/HD)      // 32 chunks
#define BH  (B_*H_)      // 32

// ---------------- scratch (device globals) ----------------
__device__ __half g_qkv16[BT*(size_t)C3];         // q,k,v fp16 (stride 3C), rotary applied
__device__ float  g_W [BH*(size_t)NC*HD*HD];
__device__ __half g_S16[BH*(size_t)NC*HD*HD];     // scanned states fp16
__device__ float  g_z [BT*(size_t)C_];            // silu(gate) fp32
__device__ float  g_ffout[BT*(size_t)C_];         // ff GEMM result
__device__ float4 g_rot [T_*(size_t)512];         // (cq,sq,ck,sk) per (t,j)
// single fp16 operands
__device__ __half g_a_q1  [BT*(size_t)C_];        // rms-normed x
__device__ __half g_b_qkv1[C5*(size_t)C_];
__device__ __half g_a_x1  [BT*(size_t)C_];        // raw x
__device__ __half g_b_gat1[C_*(size_t)C_];
__device__ __half g_a_prj1[BT*(size_t)C_];
__device__ __half g_b_prj1[C_*(size_t)C_];
__device__ __half g_a_ff1 [BT*(size_t)2*C_];      // gelu(ff) fp16
__device__ __half g_b_ff1 [C_*(size_t)2*C_];

// ---------------- PTX helpers ----------------
__device__ __forceinline__ uint32_t smem_u32(const void* p) {
    uint32_t a;
    asm("{ .reg .u64 t; cvta.to.shared.u64 t, %1; cvt.u32.u64 %0, t; }" : "=r"(a) : "l"(p));
    return a;
}
#define CPA(dst, src)  asm volatile("cp.async.cg.shared.global [%0], [%1], 16;" :: "r"(dst), "l"(src) : "memory")
#define CPC()          asm volatile("cp.async.commit_group;" ::: "memory")
#define CPW(n)         asm volatile("cp.async.wait_group %0;" :: "n"(n) : "memory")
#define SWZ(o) ((o) ^ (((o) >> 3) & 0x70))

#define LDM_X4(r0, r1, r2, r3, a) \
    asm volatile("ldmatrix.sync.aligned.m8n8.x4.shared.b16 {%0,%1,%2,%3}, [%4];" \
        : "=r"(r0), "=r"(r1), "=r"(r2), "=r"(r3) : "r"(a))
#define LDM_X4T(r0, r1, r2, r3, a) \
    asm volatile("ldmatrix.sync.aligned.m8n8.x4.trans.shared.b16 {%0,%1,%2,%3}, [%4];" \
        : "=r"(r0), "=r"(r1), "=r"(r2), "=r"(r3) : "r"(a))

#define MMA_F16(d, a, b0, b1) \
    asm volatile("mma.sync.aligned.m16n8k16.row.col.f32.f16.f16.f32 " \
        "{%0,%1,%2,%3}, {%4,%5,%6,%7}, {%8,%9}, {%0,%1,%2,%3};" \
        : "+f"((d)[0]), "+f"((d)[1]), "+f"((d)[2]), "+f"((d)[3]) \
        : "r"((a)[0]), "r"((a)[1]), "r"((a)[2]), "r"((a)[3]), "r"(b0), "r"(b1))

// ---------------- warp-MMA fp16 NT GEMM (proven R4 mainloop) ----------------
// EPI 1: silu(v+bias[n]) -> fp32 Cout
// EPI 2: plain -> Cout
// EPI 3: v + bias[n] + aux0[o] + aux1[o] -> Cout
// EPI 4: gelu(v) -> fp16 osplit (row stride N)
// EPI 5: qkv: fused xPos rotary (n<2048 via aux0 table) -> fp16 osplit (row stride N)
template<int EPI>
__global__ void __launch_bounds__(256, 1) mma_gemm(
    const __half* __restrict__ A, const __half* __restrict__ Bm,
    int Kp, int N, float* __restrict__ Cout,
    const float* __restrict__ bias, const float* __restrict__ aux0,
    const float* __restrict__ aux1, __half* __restrict__ osplit)
{
    extern __shared__ __align__(1024) char smem_raw[];
    const int S = 4;
    const uint32_t STAGE = 49152;   // A 16KB + B 32KB
    uint32_t sbase = (smem_u32(smem_raw) + 1023) & ~1023u;

    int tid = threadIdx.x;
    int wid = tid >> 5, lane = tid & 31;
    int warp_m = wid & 1, warp_n = wid >> 1;
    int bm = blockIdx.y << 7, bn = blockIdx.x << 8;

    const int nk = Kp >> 6;

    auto load_stage = [&](int s, int k) {
        uint32_t a_s = sbase + s * STAGE;
        uint32_t b_s = a_s + 16384u;
        const __half* Ag = A + (size_t)bm * Kp + (size_t)k * 64;
        const __half* Bg = Bm + (size_t)bn * Kp + (size_t)k * 64;
        #pragma unroll
        for (int q = 0; q < 4; q++) {
            int i = tid + (q << 8);
            int r = i >> 3, c = i & 7;
            uint32_t off = SWZ(r * 128 + c * 16);
            CPA(a_s + off, (const char*)(Ag + (size_t)r * Kp + c * 8));
        }
        #pragma unroll
        for (int q = 0; q < 8; q++) {
            int i = tid + (q << 8);
            int r = i >> 3, c = i & 7;
            uint32_t off = SWZ(r * 128 + c * 16);
            CPA(b_s + off, (const char*)(Bg + (size_t)r * Kp + c * 8));
        }
    };

    float acc[4][8][4];
    #pragma unroll
    for (int mt = 0; mt < 4; mt++)
        #pragma unroll
        for (int nt = 0; nt < 8; nt++)
            #pragma unroll
            for (int u = 0; u < 4; u++) acc[mt][nt][u] = 0.f;

    int j = lane >> 3;
    int lrow = lane & 7;
    int a_row_off = ((j & 1) << 3) + lrow;
    int a_byte_off = (j >> 1) << 4;
    int b_row_off = ((j >> 1) << 3) + lrow;
    int b_byte_off = (j & 1) << 4;

    #pragma unroll
    for (int p = 0; p < S - 1; p++) { load_stage(p, p); CPC(); }

    for (int k = 0; k < nk; k++) {
        CPW(S - 2);
        __syncthreads();
        if (k + S - 1 < nk) load_stage((k + S - 1) % S, k + S - 1);
        CPC();

        uint32_t a_s = sbase + (uint32_t)(k % S) * STAGE;
        uint32_t b_s = a_s + 16384u;
        #pragma unroll
        for (int ks = 0; ks < 4; ks++) {
            uint32_t af[4][4], bf[4][4];
            #pragma unroll
            for (int mt = 0; mt < 4; mt++) {
                int row = warp_m * 64 + mt * 16 + a_row_off;
                uint32_t ad = a_s + SWZ(row * 128 + ks * 32 + a_byte_off);
                LDM_X4(af[mt][0], af[mt][1], af[mt][2], af[mt][3], ad);
            }
            #pragma unroll
            for (int ng = 0; ng < 4; ng++) {
                int row = warp_n * 64 + ng * 16 + b_row_off;
                uint32_t bd = b_s + SWZ(row * 128 + ks * 32 + b_byte_off);
                LDM_X4(bf[ng][0], bf[ng][1], bf[ng][2], bf[ng][3], bd);
            }
            #pragma unroll
            for (int mt = 0; mt < 4; mt++)
                #pragma unroll
                for (int nt = 0; nt < 8; nt++) {
                    uint32_t b0 = bf[nt >> 1][(nt & 1) ? 2 : 0];
                    uint32_t b1 = bf[nt >> 1][(nt & 1) ? 3 : 1];
                    MMA_F16(acc[mt][nt], af[mt], b0, b1);
                }
        }
    }

    // ---------------- epilogue ----------------
    int gid = lane >> 2;
    int tig = lane & 3;
    #pragma unroll
    for (int mt = 0; mt < 4; mt++) {
        int m0 = bm + warp_m * 64 + mt * 16 + gid;
        #pragma unroll
        for (int nt = 0; nt < 8; nt++) {
            int n0 = bn + warp_n * 64 + nt * 8 + tig * 2;
            float* ac = acc[mt][nt];
            #pragma unroll
            for (int half_ = 0; half_ < 2; half_++) {
                int m = m0 + half_ * 8;
                float v0 = ac[half_ * 2], v1 = ac[half_ * 2 + 1];
                if (EPI == 1) {
                    float z0 = v0 + bias[n0], z1 = v1 + bias[n0 + 1];
                    float2 w;
                    w.x = z0 / (1.f + expf(-z0));
                    w.y = z1 / (1.f + expf(-z1));
                    *(float2*)&Cout[(size_t)m * N + n0] = w;
                } else if (EPI == 2) {
                    float2 w; w.x = v0; w.y = v1;
                    *(float2*)&Cout[(size_t)m * N + n0] = w;
                } else if (EPI == 3) {
                    size_t o = (size_t)m * N + n0;
                    float2 w;
                    w.x = v0 + bias[n0]     + aux0[o]     + aux1[o];
                    w.y = v1 + bias[n0 + 1] + aux0[o + 1] + aux1[o + 1];
                    *(float2*)&Cout[o] = w;
                } else if (EPI == 4) {  // gelu -> fp16
                    float g0 = 0.5f * v0 * (1.0f + erff(v0 * 0.70710678118654752f));
                    float g1 = 0.5f * v1 * (1.0f + erff(v1 * 0.70710678118654752f));
                    *(__half2*)(osplit + (size_t)m * N + n0) =
                        __halves2half2(__float2half(g0), __float2half(g1));
                } else {  // EPI 5: fused xPos rotary -> fp16
                    float w0 = v0, w1 = v1;
                    if (n0 < 2048) {
                        const float4* rot = (const float4*)aux0;
                        float4 rt = rot[((size_t)(m & (T_ - 1)) << 9) + ((n0 & 1023) >> 1)];
                        float cc = (n0 < 1024) ? rt.x : rt.z;
                        float ss = (n0 < 1024) ? rt.y : rt.w;
                        w0 = v0 * cc - v1 * ss;
                        w1 = v1 * cc + v0 * ss;
                    }
                    *(__half2*)(osplit + (size_t)m * N + n0) =
                        __halves2half2(__float2half(w0), __float2half(w1));
                }
            }
        }
    }
}

// ---------------- flat fp32 -> fp16 convert ----------------
__global__ void k_half1(const float4* __restrict__ in, __half* __restrict__ out) {
    int idx = blockIdx.x * 256 + threadIdx.x;
    float4 v = in[idx];
    uint2 hp;
    ((__half2*)&hp)[0] = __halves2half2(__float2half(v.x), __float2half(v.y));
    ((__half2*)&hp)[1] = __halves2half2(__float2half(v.z), __float2half(v.w));
    *(uint2*)(out + (size_t)idx * 4) = hp;
}

// ---------------- rotary table ----------------
__global__ void k_rotab() {
    int idx = blockIdx.x * 256 + threadIdx.x;        // over T_*512
    int t = idx >> 9;
    int j = idx & 511;
    float invf  = powf(10000.0f, -(float)j / 512.0f);
    float theta = (float)t * invf;
    float sn, cs;
    sincosf(theta, &sn, &cs);
    float svec  = (2.0f * (float)j + 0.4f * 1024.0f) / (1.4f * 1024.0f);
    float pw    = ((float)t - 1024.0f) * (1.0f / 512.0f);
    float scale = powf(svec, pw);
    float4 r;
    r.x = cs * scale;  r.y = sn * scale;
    r.z = cs / scale;  r.w = sn / scale;
    g_rot[idx] = r;
}

// ---------------- K1: RMSNorm -> a_q1 fp16, plus raw-x fp16 ----------------
__global__ void k_rmsnorm(const float* __restrict__ x, const float* __restrict__ rms_w) {
    int n = blockIdx.x;
    const float* xr = x + (size_t)n * C_;
    __shared__ float red[256];
    float s = 0.f;
    for (int c = threadIdx.x; c < C_; c += 256) { float v = xr[c]; s += v * v; }
    red[threadIdx.x] = s; __syncthreads();
    for (int o = 128; o > 0; o >>= 1) {
        if (threadIdx.x < o) red[threadIdx.x] += red[threadIdx.x + o];
        __syncthreads();
    }
    float nrm = sqrtf(red[0]) * 0.03125f;
    float inv = 1.0f / fmaxf(nrm, 1e-8f);
    for (int c = threadIdx.x; c < C_; c += 256) {
        float xv = xr[c];
        g_a_q1[(size_t)n * C_ + c] = __float2half(xv * inv * rms_w[c]);
        g_a_x1[(size_t)n * C_ + c] = __float2half(xv);
    }
}

// ---------------- K4: chunk KV summaries via tensor cores ----------------
// W[d][e] = sum_j dec_j K[j][d] V[j][e]  (trans-A, trans-B MMA)
__global__ void __launch_bounds__(256) k_chunk_kv() {
    __shared__ __align__(16) __half Kd[64 * 72], Vt[64 * 72];
    __shared__ float dec[64];
    int blk = blockIdx.x;
    int bh = blk / NC, c = blk % NC;
    int b = bh / H_, h = bh % H_;
    float gamma = 1.0f - exp2f(-5.0f - (float)h);
    if (threadIdx.x < 64) dec[threadIdx.x] = powf(gamma, (float)(HD - threadIdx.x));
    __syncthreads();
    for (int i = threadIdx.x; i < 4096; i += 256) {
        int j = i >> 6, d = i & 63;
        size_t base = (size_t)(b * T_ + c * HD + j) * C3 + h * HD + d;
        Kd[j * 72 + d] = __float2half(__half2float(g_qkv16[base + C_]) * dec[j]);
        Vt[j * 72 + d] = g_qkv16[base + 2 * C_];
    }
    __syncthreads();
    int wid = threadIdx.x >> 5, lane = threadIdx.x & 31;
    int m0 = (wid & 3) << 4, n0 = (wid >> 2) << 5;
    int jj = lane >> 3, lrow = lane & 7;
    int off1_row = ((jj & 1) << 3) + lrow, off1_byte = (jj >> 1) << 4;   // A-style
    int off2_row = ((jj >> 1) << 3) + lrow, off2_byte = (jj & 1) << 4;   // B-style
    uint32_t sK = smem_u32(Kd), sV = smem_u32(Vt);
    const int RS = 144;
    float acc[4][4];
    #pragma unroll
    for (int nt = 0; nt < 4; nt++)
        #pragma unroll
        for (int u = 0; u < 4; u++) acc[nt][u] = 0.f;
    #pragma unroll
    for (int ks = 0; ks < 4; ks++) {
        uint32_t af[4];
        // trans A from Kd[k=j][m=d]: row k, byte m  (B-style offsets)
        LDM_X4T(af[0], af[1], af[2], af[3],
                sK + (ks * 16 + off2_row) * RS + m0 * 2 + off2_byte);
        #pragma unroll
        for (int nb = 0; nb < 2; nb++) {
            uint32_t bf[4];
            // trans B from Vt[k=j][n=e]: row k, byte n  (A-style offsets)
            LDM_X4T(bf[0], bf[1], bf[2], bf[3],
                    sV + (ks * 16 + off1_row) * RS + (n0 + nb * 16) * 2 + off1_byte);
            MMA_F16(acc[nb * 2],     af, bf[0], bf[1]);
            MMA_F16(acc[nb * 2 + 1], af, bf[2], bf[3]);
        }
    }
    int gid = lane >> 2, tig = lane & 3;
    float* Wout = g_W + ((size_t)bh * NC + c) * 4096;
    #pragma unroll
    for (int nt = 0; nt < 4; nt++) {
        int e = n0 + nt * 8 + tig * 2;
        #pragma unroll
        for (int hf = 0; hf < 2; hf++) {
            int d = m0 + gid + hf * 8;
            float2 w; w.x = acc[nt][hf * 2]; w.y = acc[nt][hf * 2 + 1];
            *(float2*)&Wout[d * 64 + e] = w;
        }
    }
}

// ---------------- K5: state scan (fp32 state, fp16 output) ----------------
__global__ void k_scan() {
    int blk = blockIdx.x;            // BH*4
    int bh = blk >> 2, part = blk & 3;
    int h = bh % H_;
    float gamma = 1.0f - exp2f(-5.0f - (float)h);
    float g64 = powf(gamma, 64.0f);
    int i = part * 1024 + threadIdx.x * 4;
    float4 st; st.x = st.y = st.z = st.w = 0.f;
    size_t base0 = (size_t)bh * NC * 4096 + i;
    for (int c = 0; c < NC; c++) {
        size_t base = base0 + (size_t)c * 4096;
        uint2 hp;
        ((__half2*)&hp)[0] = __halves2half2(__float2half(st.x), __float2half(st.y));
        ((__half2*)&hp)[1] = __halves2half2(__float2half(st.z), __float2half(st.w));
        *(uint2*)&g_S16[base] = hp;
        float4 w = *(const float4*)&g_W[base];
        st.x = st.x * g64 + w.x;
        st.y = st.y * g64 + w.y;
        st.z = st.z * g64 + w.z;
        st.w = st.w * g64 + w.w;
    }
}

// ---------------- K6: tensor-core chunk attention + fused GN + gate ----------------
__global__ void __launch_bounds__(256) k_chunk_attn(
    const float* __restrict__ gn_w, const float* __restrict__ gn_b) {
    extern __shared__ __align__(16) char smraw[];
    __half* Qs = (__half*)smraw;           // 64*72
    __half* Ks = Qs + 64 * 72;
    __half* Vs = Ks + 64 * 72;
    __half* Ss = Vs + 64 * 72;
    __half* Am = Ss + 64 * 72;
    float* gpow = (float*)(Am + 64 * 72);  // 64
    float* Yb = (float*)smraw;             // aliases Qs+Ks (17408 <= 18432)

    int blk = blockIdx.x;
    int bh = blk / NC, c = blk % NC;
    int b = bh / H_, h = bh % H_;
    float gamma = 1.0f - exp2f(-5.0f - (float)h);
    if (threadIdx.x < 64) gpow[threadIdx.x] = powf(gamma, (float)threadIdx.x);
    for (int i = threadIdx.x; i < 4096; i += 256) {
        int j = i >> 6, d = i & 63;
        size_t base = (size_t)(b * T_ + c * HD + j) * C3 + h * HD + d;
        Qs[j * 72 + d] = g_qkv16[base];
        Ks[j * 72 + d] = g_qkv16[base + C_];
        Vs[j * 72 + d] = g_qkv16[base + 2 * C_];
        Ss[j * 72 + d] = g_S16[((size_t)bh * NC + c) * 4096 + i];
    }
    __syncthreads();
    int wid = threadIdx.x >> 5, lane = threadIdx.x & 31;
    int m0 = (wid & 3) << 4, n0 = (wid >> 2) << 5;
    int jj = lane >> 3, lrow = lane & 7;
    int off1_row = ((jj & 1) << 3) + lrow, off1_byte = (jj >> 1) << 4;   // A-style
    int off2_row = ((jj >> 1) << 3) + lrow, off2_byte = (jj & 1) << 4;   // B-style
    uint32_t sQ = smem_u32(Qs), sK = smem_u32(Ks), sV = smem_u32(Vs);
    uint32_t sS = smem_u32(Ss), sA = smem_u32(Am);
    const int RS = 144;
    int gid = lane >> 2, tig = lane & 3;

    // ---- phase 1: scores = Q K^T, mask+decay -> Am fp16 ----
    {
        float acc[4][4];
        #pragma unroll
        for (int nt = 0; nt < 4; nt++)
            #pragma unroll
            for (int u = 0; u < 4; u++) acc[nt][u] = 0.f;
        #pragma unroll
        for (int ks = 0; ks < 4; ks++) {
            uint32_t af[4];
            LDM_X4(af[0], af[1], af[2], af[3],
                   sQ + (m0 + off1_row) * RS + ks * 32 + off1_byte);
            #pragma unroll
            for (int nb = 0; nb < 2; nb++) {
                uint32_t bf[4];
                LDM_X4(bf[0], bf[1], bf[2], bf[3],
                       sK + (n0 + nb * 16 + off2_row) * RS + ks * 32 + off2_byte);
                MMA_F16(acc[nb * 2],     af, bf[0], bf[1]);
                MMA_F16(acc[nb * 2 + 1], af, bf[2], bf[3]);
            }
        }
        #pragma unroll
        for (int nt = 0; nt < 4; nt++) {
            int n = n0 + nt * 8 + tig * 2;
            #pragma unroll
            for (int hf = 0; hf < 2; hf++) {
                int i = m0 + gid + hf * 8;
                float v0 = acc[nt][hf * 2], v1 = acc[nt][hf * 2 + 1];
                v0 = (n     <= i) ? v0 * gpow[i - n]     : 0.f;
                v1 = (n + 1 <= i) ? v1 * gpow[i - n - 1] : 0.f;
                *(__half2*)(Am + i * 72 + n) =
                    __halves2half2(__float2half(v0), __float2half(v1));
            }
        }
    }
    __syncthreads();
    // ---- phase 2: Y = Am V + gpow[i] * Q S ----
    float a2[4][4], a3[4][4];
    #pragma unroll
    for (int nt = 0; nt < 4; nt++)
        #pragma unroll
        for (int u = 0; u < 4; u++) { a2[nt][u] = 0.f; a3[nt][u] = 0.f; }
    #pragma unroll
    for (int ks = 0; ks < 4; ks++) {
        uint32_t afA[4], afQ[4];
        LDM_X4(afA[0], afA[1], afA[2], afA[3],
               sA + (m0 + off1_row) * RS + ks * 32 + off1_byte);
        LDM_X4(afQ[0], afQ[1], afQ[2], afQ[3],
               sQ + (m0 + off1_row) * RS + ks * 32 + off1_byte);
        #pragma unroll
        for (int nb = 0; nb < 2; nb++) {
            uint32_t bv[4], bs[4];
            LDM_X4T(bv[0], bv[1], bv[2], bv[3],
                    sV + (ks * 16 + off1_row) * RS + (n0 + nb * 16) * 2 + off1_byte);
            LDM_X4T(bs[0], bs[1], bs[2], bs[3],
                    sS + (ks * 16 + off1_row) * RS + (n0 + nb * 16) * 2 + off1_byte);
            MMA_F16(a2[nb * 2],     afA, bv[0], bv[1]);
            MMA_F16(a2[nb * 2 + 1], afA, bv[2], bv[3]);
            MMA_F16(a3[nb * 2],     afQ, bs[0], bs[1]);
            MMA_F16(a3[nb * 2 + 1], afQ, bs[2], bs[3]);
        }
    }
    __syncthreads();    // all ldmatrix reads done; safe to overwrite Qs/Ks via Yb
    #pragma unroll
    for (int nt = 0; nt < 4; nt++) {
        int n = n0 + nt * 8 + tig * 2;
        #pragma unroll
        for (int hf = 0; hf < 2; hf++) {
            int i = m0 + gid + hf * 8;
            float gi = gpow[i];
            Yb[i * 68 + n]     = (a2[nt][hf * 2]     + gi * a3[nt][hf * 2])     * 0.125f;
            Yb[i * 68 + n + 1] = (a2[nt][hf * 2 + 1] + gi * a3[nt][hf * 2 + 1]) * 0.125f;
        }
    }
    __syncthreads();
    // ---- GN + gate -> a_prj1 fp16 ----
    int i = threadIdx.x >> 2;
    int e0 = (threadIdx.x & 3) << 4;
    float vv[16];
    float sum = 0.f, sq = 0.f;
    #pragma unroll
    for (int u = 0; u < 16; u++) {
        float v = Yb[i * 68 + e0 + u];
        vv[u] = v; sum += v; sq += v * v;
    }
    sum += __shfl_xor_sync(~0u, sum, 1); sq += __shfl_xor_sync(~0u, sq, 1);
    sum += __shfl_xor_sync(~0u, sum, 2); sq += __shfl_xor_sync(~0u, sq, 2);
    float mu  = sum * (1.0f / 64.0f);
    float var = sq * (1.0f / 64.0f) - mu * mu;
    float inv = rsqrtf(var + 1e-5f);
    size_t row = (size_t)(b * T_ + c * HD + i);
    int cb = h * 64 + e0;
    #pragma unroll
    for (int u = 0; u < 16; u += 4) {
        float4 gw = *(const float4*)&gn_w[cb + u];
        float4 gb = *(const float4*)&gn_b[cb + u];
        float4 zv = *(const float4*)&g_z[row * C_ + cb + u];
        float o0 = ((vv[u]     - mu) * inv * gw.x + gb.x) * zv.x;
        float o1 = ((vv[u + 1] - mu) * inv * gw.y + gb.y) * zv.y;
        float o2 = ((vv[u + 2] - mu) * inv * gw.z + gb.z) * zv.z;
        float o3 = ((vv[u + 3] - mu) * inv * gw.w + gb.w) * zv.w;
        uint2 hp;
        ((__half2*)&hp)[0] = __halves2half2(__float2half(o0), __float2half(o1));
        ((__half2*)&hp)[1] = __halves2half2(__float2half(o2), __float2half(o3));
        *(uint2*)(g_a_prj1 + row * C_ + cb + u) = hp;
    }
}

// ---------------- launch ----------------
extern "C" void kernel_launch(void* const* d_in, const int* in_sizes, int n_in,
                              void* d_out, int out_size) {
    const float* x       = (const float*)d_in[0];
    const float* w_qkvff = (const float*)d_in[1];
    const float* w_gated = (const float*)d_in[2];
    const float* b_gated = (const float*)d_in[3];
    const float* w_proj  = (const float*)d_in[4];
    const float* b_proj  = (const float*)d_in[5];
    const float* gn_w    = (const float*)d_in[6];
    const float* gn_b    = (const float*)d_in[7];
    const float* w_ff    = (const float*)d_in[8];
    const float* rms_w   = (const float*)d_in[9];
    float* out = (float*)d_out;

    float *p_z, *p_ffout;
    float4* p_rot;
    __half *p_qkv16, *p_a_q1, *p_b_qkv1, *p_a_x1, *p_b_gat1, *p_a_prj1, *p_b_prj1, *p_a_ff1, *p_b_ff1;
    cudaGetSymbolAddress((void**)&p_qkv16, g_qkv16);
    cudaGetSymbolAddress((void**)&p_z,     g_z);
    cudaGetSymbolAddress((void**)&p_ffout, g_ffout);
    cudaGetSymbolAddress((void**)&p_rot,   g_rot);
    cudaGetSymbolAddress((void**)&p_a_q1,  g_a_q1);
    cudaGetSymbolAddress((void**)&p_b_qkv1, g_b_qkv1);
    cudaGetSymbolAddress((void**)&p_a_x1,  g_a_x1);
    cudaGetSymbolAddress((void**)&p_b_gat1, g_b_gat1);
    cudaGetSymbolAddress((void**)&p_a_prj1, g_a_prj1);
    cudaGetSymbolAddress((void**)&p_b_prj1, g_b_prj1);
    cudaGetSymbolAddress((void**)&p_a_ff1, g_a_ff1);
    cudaGetSymbolAddress((void**)&p_b_ff1, g_b_ff1);

    const int SMEM = 1024 + 4 * 49152;               // 197632
    const int ATTN_SMEM = 5 * 64 * 72 * 2 + 256;     // 46336

    static cudaStream_t s1 = nullptr;
    static cudaEvent_t ev0, ev_ax, ev_gate, ev_ff;
    if (s1 == nullptr) {
        cudaStreamCreateWithFlags(&s1, cudaStreamNonBlocking);
        cudaEventCreateWithFlags(&ev0,     cudaEventDisableTiming);
        cudaEventCreateWithFlags(&ev_ax,   cudaEventDisableTiming);
        cudaEventCreateWithFlags(&ev_gate, cudaEventDisableTiming);
        cudaEventCreateWithFlags(&ev_ff,   cudaEventDisableTiming);
        cudaFuncSetAttribute(mma_gemm<1>, cudaFuncAttributeMaxDynamicSharedMemorySize, SMEM);
        cudaFuncSetAttribute(mma_gemm<2>, cudaFuncAttributeMaxDynamicSharedMemorySize, SMEM);
        cudaFuncSetAttribute(mma_gemm<3>, cudaFuncAttributeMaxDynamicSharedMemorySize, SMEM);
        cudaFuncSetAttribute(mma_gemm<4>, cudaFuncAttributeMaxDynamicSharedMemorySize, SMEM);
        cudaFuncSetAttribute(mma_gemm<5>, cudaFuncAttributeMaxDynamicSharedMemorySize, SMEM);
        cudaFuncSetAttribute(k_chunk_attn, cudaFuncAttributeMaxDynamicSharedMemorySize, ATTN_SMEM);
    }

    // ---- fork ----
    cudaEventRecord(ev0, 0);
    cudaStreamWaitEvent(s1, ev0, 0);

    // s1: fp16 weight converts for gate / proj / ff
    k_half1<<<(C_ * C_) / 1024, 256, 0, s1>>>((const float4*)w_gated, p_b_gat1);
    k_half1<<<(C_ * C_) / 1024, 256, 0, s1>>>((const float4*)w_proj,  p_b_prj1);
    k_half1<<<(C_ * 2 * C_) / 1024, 256, 0, s1>>>((const float4*)w_ff, p_b_ff1);

    // main: qkvff weight convert + rotary table + RMSNorm
    k_half1<<<(C5 * C_) / 1024, 256>>>((const float4*)w_qkvff, p_b_qkv1);
    k_rotab<<<(T_ * 512) / 256, 256>>>();
    k_rmsnorm<<<BT, 256>>>(x, rms_w);
    cudaEventRecord(ev_ax, 0);

    // s1: gate GEMM z = silu(x @ w_gated^T + b)
    cudaStreamWaitEvent(s1, ev_ax, 0);
    mma_gemm<1><<<dim3(C_ / 256, BT / 128), 256, SMEM, s1>>>(
        p_a_x1, p_b_gat1, C_, C_, p_z, b_gated, nullptr, nullptr, nullptr);
    cudaEventRecord(ev_gate, s1);

    // s1: ffpart GEMM (B rows 3072..5119) -> gelu fp16 a_ff1
    mma_gemm<4><<<dim3(2 * C_ / 256, BT / 128), 256, SMEM, s1>>>(
        p_a_q1, p_b_qkv1 + (size_t)C3 * C_, C_, 2 * C_,
        nullptr, nullptr, nullptr, nullptr, p_a_ff1);

    // s1: ff GEMM ffout = gelu(ff) @ w_ff^T
    mma_gemm<2><<<dim3(C_ / 256, BT / 128), 256, SMEM, s1>>>(
        p_a_ff1, p_b_ff1, 2 * C_, C_, p_ffout, nullptr, nullptr, nullptr, nullptr);
    cudaEventRecord(ev_ff, s1);

    // main: qkv GEMM with fused xPos rotary -> g_qkv16 fp16
    mma_gemm<5><<<dim3(C3 / 256, BT / 128), 256, SMEM>>>(
        p_a_q1, p_b_qkv1, C_, C3, nullptr, nullptr, (const float*)p_rot, nullptr, p_qkv16);

    // main: tensor-core attention chain
    k_chunk_kv<<<BH * NC, 256>>>();
    k_scan<<<BH * 4, 256>>>();
    cudaStreamWaitEvent(0, ev_gate, 0);
    k_chunk_attn<<<BH * NC, 256, ATTN_SMEM>>>(gn_w, gn_b);

    // join ff, then final proj GEMM: out = y2 @ w_proj^T + b_proj + x + ffout
    cudaStreamWaitEvent(0, ev_ff, 0);
    mma_gemm<3><<<dim3(C_ / 256, BT / 128), 256, SMEM>>>(
        p_a_prj1, p_b_prj1, C_, C_, out, b_proj, x, p_ffout, nullptr);
}